// round 9
// baseline (speedup 1.0000x reference)
#include <cuda_runtime.h>
#include <cuda_bf16.h>
#include <math.h>
#include <stdint.h>

#define B_ 32
#define T_ 64
#define E_ 256
#define H_ 256
#define P_ 63
#define PB_ 2016
#define NPACK_ 64512

#define NCTA_PERS 144
#define NQ_ 18
#define SMEM_A_OFF   196608            // A buffers after 16 chunks * 12288B weights
#define ABUF_STRIDE  8192              // piece-packed: 2 planes * 128 rows * 32B
#define SMEM_TOTAL_PERS (196608 + 3*ABUF_STRIDE)   // 221184

#define DCHUNK 24576                   // dense: A(12288)+B(12288) per buffer
#define SMEM_TOTAL_DENSE (3*DCHUNK)    // 73728

// ------------------------- scratch (device globals) -------------------------
__device__ float g_emb[T_*B_*E_];
__device__ __nv_bfloat16 g_embhi[T_*B_*E_];
__device__ __nv_bfloat16 g_emblo[T_*B_*E_];
__device__ float g_gxa[T_*B_*3*H_];
__device__ float g_gxb[T_*B_*3*H_];
__device__ __nv_bfloat16 g_hhi[2][2][PB_*H_];   // [gru][parity]
__device__ __nv_bfloat16 g_hlo[2][2][PB_*H_];
__device__ __nv_bfloat16 g_whi[2][3*H_*H_];     // w_hh planes
__device__ __nv_bfloat16 g_wlo[2][3*H_*H_];
__device__ __nv_bfloat16 g_wihhi[2][3*H_*E_];   // w_ih planes
__device__ __nv_bfloat16 g_wihlo[2][3*H_*E_];
__device__ __nv_bfloat16 g_bwhi[E_*H_];
__device__ __nv_bfloat16 g_bwlo[E_*H_];
__device__ __nv_bfloat16 g_mthi[E_*E_];
__device__ __nv_bfloat16 g_mtlo[E_*E_];
__device__ float g_prep[(size_t)NPACK_*16];     // pre partials [prow][cb*4+wn]
__device__ __nv_bfloat16 g_fbhi[(size_t)NPACK_*H_];
__device__ __nv_bfloat16 g_fblo[(size_t)NPACK_*H_];
__device__ float g_beta[(size_t)NPACK_*E_];
__device__ __nv_bfloat16 g_betahi[(size_t)NPACK_*E_];
__device__ __nv_bfloat16 g_betalo[(size_t)NPACK_*E_];
__device__ float g_ebeta[(size_t)NPACK_*E_];
__device__ float g_alpha[P_*T_*B_];
__device__ unsigned g_bar2[2];

// ------------------------- helpers ------------------------------------------
__device__ __forceinline__ uint32_t smem_u32(const void* p) {
    uint32_t a;
    asm("{ .reg .u64 t; cvta.to.shared.u64 t, %1; cvt.u32.u64 %0, t; }" : "=r"(a) : "l"(p));
    return a;
}
__device__ __forceinline__ void ldsm4(uint32_t* r, uint32_t addr) {
    asm volatile("ldmatrix.sync.aligned.m8n8.x4.shared.b16 {%0,%1,%2,%3}, [%4];"
        : "=r"(r[0]), "=r"(r[1]), "=r"(r[2]), "=r"(r[3]) : "r"(addr));
}
__device__ __forceinline__ void mma16816(float* d, const uint32_t* a, const uint32_t* b) {
    asm volatile("mma.sync.aligned.m16n8k16.row.col.f32.bf16.bf16.f32 "
        "{%0,%1,%2,%3}, {%4,%5,%6,%7}, {%8,%9}, {%0,%1,%2,%3};"
        : "+f"(d[0]), "+f"(d[1]), "+f"(d[2]), "+f"(d[3])
        : "r"(a[0]), "r"(a[1]), "r"(a[2]), "r"(a[3]), "r"(b[0]), "r"(b[1]));
}
#define CP_ASYNC16(dst, src) \
    asm volatile("cp.async.cg.shared.global [%0], [%1], 16;" :: "r"(dst), "l"(src))
#define CP_COMMIT() asm volatile("cp.async.commit_group;")
#define CP_WAIT1()  asm volatile("cp.async.wait_group 1;")
#define CP_WAIT0()  asm volatile("cp.async.wait_group 0;")

// ------------------------- prep kernels -------------------------------------
__global__ void zero_planes_kernel() {
    int i = blockIdx.x*256 + threadIdx.x;
    uint32_t* a = (uint32_t*)g_hhi;
    uint32_t* b = (uint32_t*)g_hlo;
    if (i < 2*2*PB_*H_/2) { a[i] = 0u; b[i] = 0u; }
    if (i < 2) g_bar2[i] = 0u;
}
__global__ void prep_w_kernel(const float* __restrict__ wa, const float* __restrict__ wb) {
    int idx = blockIdx.x*256 + threadIdx.x;
    int k = idx & 255;
    int r = (idx >> 8) % 768;
    int gru = idx / (768*256);
    float v = (gru ? wb : wa)[r*256 + k];
    __nv_bfloat16 hi = __float2bfloat16(v);
    g_whi[gru][r*256 + k] = hi;
    g_wlo[gru][r*256 + k] = __float2bfloat16(v - __bfloat162float(hi));
}
__global__ void prep_wih_kernel(const float* __restrict__ wa, const float* __restrict__ wb) {
    int idx = blockIdx.x*256 + threadIdx.x;
    int k = idx & 255;
    int r = (idx >> 8) % 768;
    int gru = idx / (768*256);
    float v = (gru ? wb : wa)[r*256 + k];
    __nv_bfloat16 hi = __float2bfloat16(v);
    g_wihhi[gru][r*256 + k] = hi;
    g_wihlo[gru][r*256 + k] = __float2bfloat16(v - __bfloat162float(hi));
}
__global__ void prep_bw_kernel(const float* __restrict__ bw) {
    int idx = blockIdx.x*256 + threadIdx.x;
    float v = bw[idx];
    __nv_bfloat16 hi = __float2bfloat16(v);
    g_bwhi[idx] = hi;
    g_bwlo[idx] = __float2bfloat16(v - __bfloat162float(hi));
}
__global__ void prep_mt_kernel(const float* __restrict__ emb_w, const float* __restrict__ out_w) {
    int idx = blockIdx.x*256 + threadIdx.x;
    int i = idx >> 8, e = idx & 255;
    float v = out_w[e] * emb_w[e*256 + i];
    __nv_bfloat16 hi = __float2bfloat16(v);
    g_mthi[idx] = hi;
    g_mtlo[idx] = __float2bfloat16(v - __bfloat162float(hi));
}

// ------------------------- fp32 SGEMM (emb) ---------------------------------
__global__ void __launch_bounds__(256, 2)
sgemm128(const float* __restrict__ A, const float* __restrict__ Bt,
         const float* __restrict__ bias, float* __restrict__ C,
         int N, int xmode,
         __nv_bfloat16* __restrict__ Phi, __nv_bfloat16* __restrict__ Plo) {
    __shared__ float As[2][8][128];
    __shared__ float Bs[2][8][128];
    const int tid = threadIdx.x;
    const int m0 = blockIdx.x*128, n0 = blockIdx.y*128;
    const int tx = tid & 15, ty = tid >> 4;
    const int lr = tid >> 1;
    const int ks = (tid & 1) * 4;
    const float* pA;
    if (xmode) { int m = m0 + lr; int t = m >> 5, b = m & 31; pA = A + ((size_t)b*T_ + t)*E_ + ks; }
    else pA = A + (size_t)(m0 + lr)*E_ + ks;
    const float* pB = Bt + (size_t)(n0 + lr) * 256 + ks;
    float acc[2][2][4][4] = {};
    float4 va = *(const float4*)pA;
    float4 vb = *(const float4*)pB;
    {
        const float* f = (const float*)&va;
#pragma unroll
        for (int j = 0; j < 4; j++) As[0][ks+j][lr] = f[j];
        f = (const float*)&vb;
#pragma unroll
        for (int j = 0; j < 4; j++) Bs[0][ks+j][lr] = f[j];
    }
    __syncthreads();
    int buf = 0;
#pragma unroll 1
    for (int c = 0; c < 32; c++) {
        if (c < 31) {
            int off = (c+1)*8;
            va = *(const float4*)(pA + off);
            vb = *(const float4*)(pB + off);
        }
#pragma unroll
        for (int kk = 0; kk < 8; kk++) {
            float4 a0 = *(const float4*)&As[buf][kk][ty*4];
            float4 a1 = *(const float4*)&As[buf][kk][ty*4 + 64];
            float4 b0 = *(const float4*)&Bs[buf][kk][tx*4];
            float4 b1 = *(const float4*)&Bs[buf][kk][tx*4 + 64];
            float aa[2][4] = {{a0.x,a0.y,a0.z,a0.w},{a1.x,a1.y,a1.z,a1.w}};
            float bb[2][4] = {{b0.x,b0.y,b0.z,b0.w},{b1.x,b1.y,b1.z,b1.w}};
#pragma unroll
            for (int rh = 0; rh < 2; rh++)
#pragma unroll
            for (int i = 0; i < 4; i++)
#pragma unroll
            for (int ch = 0; ch < 2; ch++)
#pragma unroll
            for (int j = 0; j < 4; j++)
                acc[rh][ch][i][j] = fmaf(aa[rh][i], bb[ch][j], acc[rh][ch][i][j]);
        }
        if (c < 31) {
            int nb = buf ^ 1;
            const float* f = (const float*)&va;
#pragma unroll
            for (int j = 0; j < 4; j++) As[nb][ks+j][lr] = f[j];
            f = (const float*)&vb;
#pragma unroll
            for (int j = 0; j < 4; j++) Bs[nb][ks+j][lr] = f[j];
            __syncthreads();
            buf = nb;
        }
    }
#pragma unroll
    for (int rh = 0; rh < 2; rh++)
#pragma unroll
    for (int i = 0; i < 4; i++) {
        int m = m0 + rh*64 + ty*4 + i;
#pragma unroll
        for (int ch = 0; ch < 2; ch++) {
            int n = n0 + ch*64 + tx*4;
            float4 v;
            v.x = acc[rh][ch][i][0]; v.y = acc[rh][ch][i][1];
            v.z = acc[rh][ch][i][2]; v.w = acc[rh][ch][i][3];
            if (bias) {
                float4 bz = *(const float4*)&bias[n];
                v.x += bz.x; v.y += bz.y; v.z += bz.z; v.w += bz.w;
            }
            *(float4*)&C[(size_t)m*N + n] = v;
            if (Phi) {
                float vv[4] = {v.x, v.y, v.z, v.w};
#pragma unroll
                for (int u = 0; u < 4; u++) {
                    __nv_bfloat16 hi = __float2bfloat16(vv[u]);
                    Phi[(size_t)m*N + n + u] = hi;
                    Plo[(size_t)m*N + n + u] = __float2bfloat16(vv[u] - __bfloat162float(hi));
                }
            }
        }
    }
}

// ------------------------- persistent GRU recurrence ------------------------
// Piece-packed smem: each ldmatrix 8x8 piece = contiguous 128B block.
__global__ void __launch_bounds__(512, 1)
gru_persistent(const float* __restrict__ bhh_a, const float* __restrict__ bhh_b,
               const float* __restrict__ alpha_w) {
    extern __shared__ __align__(16) unsigned char smem[];
    const int tid = threadIdx.x, lane = tid & 31, wid = tid >> 5;
    const int wm = wid & 3, wn = wid >> 2;
    const int gid = blockIdx.x;
    const int gru = gid & 1, cb = (gid >> 1) & 3, q = gid >> 3;
    const uint32_t sbase = smem_u32(smem);

    // ---- one-time weight slice load (piece-packed) ----
    {
        const __nv_bfloat16* Whi = g_whi[gru];
        const __nv_bfloat16* Wlo = g_wlo[gru];
        for (int u = tid; u < 12288; u += 512) {
            int nrow7 = u & 7;
            int kh = (u >> 3) & 1;
            int nh = (u >> 4) & 1;
            int ng16 = (u >> 5) % 12;
            int pc = (u >> 5) / 12;
            int p = pc & 1, c = pc >> 1;
            int Rg = (ng16 >> 2)*256 + cb*64 + (ng16 & 3)*16 + nh*8 + nrow7;
            const __nv_bfloat16* src = (p ? Wlo : Whi) + (size_t)Rg*256 + c*16 + kh*8;
            uint32_t dst = (uint32_t)(c*12288 + p*6144 + ng16*512 + nh*256 + kh*128 + nrow7*16);
            *(uint4*)(smem + dst) = *(const uint4*)src;
        }
    }
    __syncthreads();

    // ---- per-lane ldmatrix offsets (piece-packed, conflict-free) ----
    const uint32_t lpiece = (uint32_t)((lane >> 4)*256 + ((lane >> 3) & 1)*128 + (lane & 7)*16);
    uint32_t abase[3][2][2];   // [buf][plane][i]
#pragma unroll
    for (int bf = 0; bf < 3; bf++)
#pragma unroll
    for (int p = 0; p < 2; p++)
#pragma unroll
    for (int i = 0; i < 2; i++)
        abase[bf][p][i] = sbase + SMEM_A_OFF + bf*ABUF_STRIDE + p*4096u
                        + (uint32_t)((wm*2 + i)*512) + lpiece;
    uint32_t wboff[2][3];
#pragma unroll
    for (int p = 0; p < 2; p++)
#pragma unroll
    for (int g = 0; g < 3; g++)
        wboff[p][g] = (uint32_t)(p*6144 + (g*4 + wn)*512) + lpiece;

    const float* bhh = gru ? bhh_b : bhh_a;
    const float* gx  = gru ? g_gxb : g_gxa;
    const int st_q = tid & 1, st_r = (tid >> 1) & 127, st_p = tid >> 8;
    const uint32_t st_dst0 = sbase + SMEM_A_OFF + st_p*4096u
        + (uint32_t)((st_r >> 4)*512 + st_q*256 + ((st_r & 8) >> 3)*128 + (st_r & 7)*16);

    const int g8 = lane >> 2, t2 = (lane & 3)*2;
    unsigned* mybar = &g_bar2[gru];

#pragma unroll 1
    for (int step = 0; step < 63; step++) {
        const int par = step & 1;
        const int nch = (63 - step)*2;
        const int c0 = (q*nch)/NQ_, c1 = ((q+1)*nch)/NQ_;
        const int R = (c1 - c0)*16;
        if (R > 0) {
            const __nv_bfloat16* Hhi = g_hhi[gru][par];
            const __nv_bfloat16* Hlo = g_hlo[gru][par];
            const int rowbase = step*32 + c0*16;
            const int ng = R >> 4;
            const bool st_on = (st_r < R);
            const __nv_bfloat16* st_src = (st_p ? Hlo : Hhi)
                + (size_t)(rowbase + (st_on ? st_r : 0))*H_ + st_q*8;

            float acc[3][2][2][4] = {};
            if (st_on) CP_ASYNC16(st_dst0, st_src);
            CP_COMMIT();
            if (st_on) CP_ASYNC16(st_dst0 + ABUF_STRIDE, st_src + 16);
            CP_COMMIT();
            int bufi = 0;
#pragma unroll 1
            for (int c = 0; c < 16; c++) {
                if (c < 15) { CP_WAIT1(); } else { CP_WAIT0(); }
                __syncthreads();
                if (c < 14) {
                    int nb = bufi + 2; if (nb >= 3) nb -= 3;
                    if (st_on) CP_ASYNC16(st_dst0 + (uint32_t)(nb*ABUF_STRIDE),
                                          st_src + (c+2)*16);
                    CP_COMMIT();
                }
                if (2*wm < ng) {
                    const bool two = (2*wm + 1 < ng);
                    uint32_t Ah[2][4], Al[2][4];
                    ldsm4(Ah[0], abase[bufi][0][0]);
                    ldsm4(Al[0], abase[bufi][1][0]);
                    if (two) { ldsm4(Ah[1], abase[bufi][0][1]); ldsm4(Al[1], abase[bufi][1][1]); }
                    const uint32_t wbc = sbase + (uint32_t)(c*12288);
#pragma unroll
                    for (int g = 0; g < 3; g++) {
                        uint32_t Bh[4], Bl[4];
                        ldsm4(Bh, wbc + wboff[0][g]);
                        ldsm4(Bl, wbc + wboff[1][g]);
#pragma unroll
                        for (int j = 0; j < 2; j++) {
                            mma16816(acc[g][0][j], Ah[0], &Bh[j*2]);
                            mma16816(acc[g][0][j], Ah[0], &Bl[j*2]);
                            mma16816(acc[g][0][j], Al[0], &Bh[j*2]);
                        }
                        if (two) {
#pragma unroll
                            for (int j = 0; j < 2; j++) {
                                mma16816(acc[g][1][j], Ah[1], &Bh[j*2]);
                                mma16816(acc[g][1][j], Ah[1], &Bl[j*2]);
                                mma16816(acc[g][1][j], Al[1], &Bh[j*2]);
                            }
                        }
                    }
                }
                bufi++; if (bufi == 3) bufi = 0;
            }
            // ---- epilogue ----
            __nv_bfloat16* Hhi_n = g_hhi[gru][par^1];
            __nv_bfloat16* Hlo_n = g_hlo[gru][par^1];
            const size_t offk = (size_t)32*(63*step - (step*(step-1))/2);
#pragma unroll
            for (int i = 0; i < 2; i++) {
                if (2*wm + i >= ng) continue;
#pragma unroll
                for (int half = 0; half < 2; half++) {
                    int grow = rowbase + wm*32 + i*16 + g8 + half*8;
                    int gxrow = grow - step*32;
                    const float* gxr = gx + (size_t)gxrow*(3*H_);
                    size_t prow = offk + gxrow;
                    float row_part = 0.f;
#pragma unroll
                    for (int j = 0; j < 2; j++) {
                        int cc = cb*64 + wn*16 + j*8 + t2;
                        float2 gx_r = *(const float2*)&gxr[cc];
                        float2 gx_z = *(const float2*)&gxr[H_ + cc];
                        float2 gx_n = *(const float2*)&gxr[2*H_ + cc];
                        float2 bh_r = *(const float2*)&bhh[cc];
                        float2 bh_z = *(const float2*)&bhh[H_ + cc];
                        float2 bh_n = *(const float2*)&bhh[2*H_ + cc];
                        __nv_bfloat162 ho_hi = *(const __nv_bfloat162*)&Hhi[(size_t)grow*H_ + cc];
                        __nv_bfloat162 ho_lo = *(const __nv_bfloat162*)&Hlo[(size_t)grow*H_ + cc];
                        float hn2[2];
#pragma unroll
                        for (int u = 0; u < 2; u++) {
                            int ai = half*2 + u;
                            float rp = acc[0][i][j][ai] + (u ? bh_r.y : bh_r.x) + (u ? gx_r.y : gx_r.x);
                            float zp = acc[1][i][j][ai] + (u ? bh_z.y : bh_z.x) + (u ? gx_z.y : gx_z.x);
                            float np = acc[2][i][j][ai] + (u ? bh_n.y : bh_n.x);
                            float r = 1.f/(1.f + expf(-rp));
                            float z = 1.f/(1.f + expf(-zp));
                            float n = tanhf((u ? gx_n.y : gx_n.x) + r*np);
                            float hold = __bfloat162float(u ? ho_hi.y : ho_hi.x)
                                       + __bfloat162float(u ? ho_lo.y : ho_lo.x);
                            hn2[u] = (1.f - z)*n + z*hold;
                        }
                        __nv_bfloat162 hi2, lo2;
                        hi2.x = __float2bfloat16(hn2[0]); hi2.y = __float2bfloat16(hn2[1]);
                        lo2.x = __float2bfloat16(hn2[0] - __bfloat162float(hi2.x));
                        lo2.y = __float2bfloat16(hn2[1] - __bfloat162float(hi2.y));
                        *(__nv_bfloat162*)&Hhi_n[(size_t)grow*H_ + cc] = hi2;
                        *(__nv_bfloat162*)&Hlo_n[(size_t)grow*H_ + cc] = lo2;
                        if (gru == 0) {
                            float2 aw = *(const float2*)&alpha_w[cc];
                            row_part += 0.5f*hn2[0]*aw.x + 0.5f*hn2[1]*aw.y;
                        } else {
                            float f0 = 0.5f*hn2[0], f1 = 0.5f*hn2[1];
                            __nv_bfloat162 fh, fl;
                            fh.x = __float2bfloat16(f0); fh.y = __float2bfloat16(f1);
                            fl.x = __float2bfloat16(f0 - __bfloat162float(fh.x));
                            fl.y = __float2bfloat16(f1 - __bfloat162float(fh.y));
                            *(__nv_bfloat162*)&g_fbhi[prow*H_ + cc] = fh;
                            *(__nv_bfloat162*)&g_fblo[prow*H_ + cc] = fl;
                        }
                    }
                    if (gru == 0) {
                        row_part += __shfl_xor_sync(0xffffffffu, row_part, 1);
                        row_part += __shfl_xor_sync(0xffffffffu, row_part, 2);
                        if ((lane & 3) == 0)
                            g_prep[prow*16 + cb*4 + wn] = row_part;
                    }
                }
            }
        }
        // ---- per-gru grid barrier (72 CTAs each) ----
        __syncthreads();
        if (tid == 0) {
            __threadfence();
            atomicAdd(mybar, 1u);
            const unsigned target = 72u*(unsigned)(step+1);
            unsigned v;
            do {
                asm volatile("ld.acquire.gpu.u32 %0, [%1];" : "=r"(v) : "l"(mybar));
            } while (v < target);
        }
        __syncthreads();
    }
}

// ------------------------- mma dense GEMM (M x ldc, K=256) ------------------
__global__ void __launch_bounds__(512, 1)
dense_mma(const __nv_bfloat16* __restrict__ Ahi, const __nv_bfloat16* __restrict__ Alo,
          const __nv_bfloat16* __restrict__ Bthi, const __nv_bfloat16* __restrict__ Btlo,
          const float* __restrict__ bias, int act, int ldc, float* __restrict__ outf,
          __nv_bfloat16* __restrict__ Phi, __nv_bfloat16* __restrict__ Plo) {
    extern __shared__ __align__(16) unsigned char smem[];
    const int tid = threadIdx.x, lane = tid & 31, wid = tid >> 5;
    const int wm = wid & 3, wn = wid >> 2;
    const int colbase = blockIdx.y * 128;
    const int rowbase = blockIdx.x * 128;
    const uint32_t sbase = smem_u32(smem);

    float acc[2][4][4] = {};

    const int a_r = lane & 15, a_c16 = ((lane >> 4) & 1) * 16;
    const int b_r = (lane & 7) + ((lane >> 4) & 1) * 8, b_c16 = (lane & 8) * 2;
    uint32_t aoff[3][2][2], boff[3][2][2];
#pragma unroll
    for (int bf = 0; bf < 3; bf++)
#pragma unroll
    for (int p = 0; p < 2; p++) {
#pragma unroll
        for (int i = 0; i < 2; i++)
            aoff[bf][p][i] = sbase + bf*DCHUNK + p*6144u
                           + (uint32_t)((wm*32 + i*16 + a_r)*48 + a_c16);
#pragma unroll
        for (int h2 = 0; h2 < 2; h2++)
            boff[bf][p][h2] = sbase + bf*DCHUNK + 12288u + p*6144u
                           + (uint32_t)((wn*32 + h2*16 + b_r)*48 + b_c16);
    }

    const int st_q = tid & 1, st_r = (tid >> 1) & 127, st_p = tid >> 8;
    const uint32_t stA = sbase + st_p*6144u + (uint32_t)(st_r*48 + st_q*16);
    const uint32_t stB = stA + 12288u;
    const __nv_bfloat16* srcA = (st_p ? Alo : Ahi) + (size_t)(rowbase + st_r)*256 + st_q*8;
    const __nv_bfloat16* srcB = (st_p ? Btlo : Bthi) + (size_t)(colbase + st_r)*256 + st_q*8;

    CP_ASYNC16(stA, srcA); CP_ASYNC16(stB, srcB); CP_COMMIT();
    CP_ASYNC16(stA + DCHUNK, srcA + 16); CP_ASYNC16(stB + DCHUNK, srcB + 16); CP_COMMIT();

    int bufi = 0;
#pragma unroll 1
    for (int c = 0; c < 16; c++) {
        if (c < 15) { CP_WAIT1(); } else { CP_WAIT0(); }
        __syncthreads();
        if (c < 14) {
            int nb = bufi + 2; if (nb >= 3) nb -= 3;
            CP_ASYNC16(stA + (uint32_t)(nb*DCHUNK), srcA + (c+2)*16);
            CP_ASYNC16(stB + (uint32_t)(nb*DCHUNK), srcB + (c+2)*16);
            CP_COMMIT();
        }
        uint32_t Ah[2][4], Al[2][4], Bh[8], Bl[8];
        ldsm4(Ah[0], aoff[bufi][0][0]); ldsm4(Ah[1], aoff[bufi][0][1]);
        ldsm4(Al[0], aoff[bufi][1][0]); ldsm4(Al[1], aoff[bufi][1][1]);
        ldsm4(Bh,   boff[bufi][0][0]); ldsm4(Bh+4, boff[bufi][0][1]);
        ldsm4(Bl,   boff[bufi][1][0]); ldsm4(Bl+4, boff[bufi][1][1]);
#pragma unroll
        for (int i = 0; i < 2; i++)
#pragma unroll
        for (int j = 0; j < 4; j++) {
            mma16816(acc[i][j], Ah[i], &Bh[j*2]);
            mma16816(acc[i][j], Ah[i], &Bl[j*2]);
            mma16816(acc[i][j], Al[i], &Bh[j*2]);
        }
        bufi++; if (bufi == 3) bufi = 0;
    }

    const int g8 = lane >> 2, t2 = (lane & 3)*2;
#pragma unroll
    for (int i = 0; i < 2; i++)
#pragma unroll
    for (int half = 0; half < 2; half++) {
        int grow = rowbase + wm*32 + i*16 + g8 + half*8;
#pragma unroll
        for (int j = 0; j < 4; j++) {
            int cc = colbase + wn*32 + j*8 + t2;
            float v0 = acc[i][j][half*2 + 0];
            float v1 = acc[i][j][half*2 + 1];
            if (bias) { v0 += bias[cc]; v1 += bias[cc+1]; }
            if (act == 1) { v0 = tanhf(v0); v1 = tanhf(v1); }
            float2 f2; f2.x = v0; f2.y = v1;
            *(float2*)&outf[(size_t)grow*ldc + cc] = f2;
            if (Phi) {
                __nv_bfloat162 hi2, lo2;
                hi2.x = __float2bfloat16(v0); hi2.y = __float2bfloat16(v1);
                lo2.x = __float2bfloat16(v0 - __bfloat162float(hi2.x));
                lo2.y = __float2bfloat16(v1 - __bfloat162float(hi2.y));
                *(__nv_bfloat162*)&Phi[(size_t)grow*ldc + cc] = hi2;
                *(__nv_bfloat162*)&Plo[(size_t)grow*ldc + cc] = lo2;
            }
        }
    }
}

// ------------------------- alpha (pre-partial sum + softmax) ----------------
__global__ void alpha_kernel(const float* __restrict__ alpha_b) {
    int gw = (blockIdx.x*blockDim.x + threadIdx.x) >> 5;
    int lane = threadIdx.x & 31;
    if (gw >= PB_) return;
    int p = gw >> 5, b = gw & 31;
    float ab = alpha_b[0];
    float v0 = -1e30f, v1 = -1e30f;
    {
        int t = lane;
        if (t <= p) {
            int kk = p - t;
            int offk = 32*(63*kk - (kk*(kk-1))/2);
            size_t prow = (size_t)offk + t*32 + b;
            const float4* qq = (const float4*)&g_prep[prow*16];
            float4 s0 = qq[0], s1 = qq[1], s2 = qq[2], s3 = qq[3];
            v0 = (s0.x+s0.y+s0.z+s0.w) + (s1.x+s1.y+s1.z+s1.w)
               + (s2.x+s2.y+s2.z+s2.w) + (s3.x+s3.y+s3.z+s3.w) + ab;
        }
    }
    {
        int t = lane + 32;
        if (t <= p) {
            int kk = p - t;
            int offk = 32*(63*kk - (kk*(kk-1))/2);
            size_t prow = (size_t)offk + t*32 + b;
            const float4* qq = (const float4*)&g_prep[prow*16];
            float4 s0 = qq[0], s1 = qq[1], s2 = qq[2], s3 = qq[3];
            v1 = (s0.x+s0.y+s0.z+s0.w) + (s1.x+s1.y+s1.z+s1.w)
               + (s2.x+s2.y+s2.z+s2.w) + (s3.x+s3.y+s3.z+s3.w) + ab;
        }
    }
    float m = fmaxf(v0, v1);
#pragma unroll
    for (int o=16;o;o>>=1) m = fmaxf(m, __shfl_xor_sync(0xffffffffu, m, o));
    float e0 = (lane      <= p) ? expf(v0-m) : 0.f;
    float e1 = (lane + 32 <= p) ? expf(v1-m) : 0.f;
    float s = e0 + e1;
#pragma unroll
    for (int o=16;o;o>>=1) s += __shfl_xor_sync(0xffffffffu, s, o);
    float inv = 1.f/s;
    g_alpha[(p*T_+lane   )*B_+b] = e0*inv;
    g_alpha[(p*T_+lane+32)*B_+b] = e1*inv;
}

__global__ void reduce_kernel(const float* __restrict__ x,
                              const float* __restrict__ out_w,
                              const float* __restrict__ out_b,
                              float* __restrict__ out) {
    int pb = blockIdx.x;
    int p = 62 - (pb >> 5);
    int b = pb & 31;
    int e = threadIdx.x;
    float cc = 0.f, gg = 0.f;
    for (int t = 0; t <= p; t++) {
        float a = g_alpha[(p*T_+t)*B_+b];
        int kk = p - t;
        int offk = 32*(63*kk - (kk*(kk-1))/2);
        size_t prow = (size_t)offk + t*32 + b;
        cc += a * g_beta [prow*E_ + e] * g_emb[((size_t)(t*B_+b))*E_ + e];
        gg += a * g_ebeta[prow*E_ + e] * x[((size_t)b*T_ + t)*E_ + e];
    }
    out[B_*P_ + ((size_t)(b*P_+p))*E_ + e] = gg / (float)(p+1);
    __shared__ float red[256];
    red[e] = cc * out_w[e];
    __syncthreads();
    for (int s2=128; s2; s2>>=1) { if (e < s2) red[e] += red[e+s2]; __syncthreads(); }
    if (e == 0) out[b*P_ + p] = red[0] + out_b[0];
}

// ------------------------- launch -------------------------------------------
extern "C" void kernel_launch(void* const* d_in, const int* in_sizes, int n_in,
                              void* d_out, int out_size) {
    (void)in_sizes; (void)n_in; (void)out_size;
    const float* x       = (const float*)d_in[0];
    const float* emb_w   = (const float*)d_in[1];
    const float* emb_b   = (const float*)d_in[2];
    const float* a_wih   = (const float*)d_in[3];
    const float* a_whh   = (const float*)d_in[4];
    const float* a_bih   = (const float*)d_in[5];
    const float* a_bhh   = (const float*)d_in[6];
    const float* b_wih   = (const float*)d_in[7];
    const float* b_whh   = (const float*)d_in[8];
    const float* b_bih   = (const float*)d_in[9];
    const float* b_bhh   = (const float*)d_in[10];
    const float* alpha_w = (const float*)d_in[11];
    const float* alpha_b = (const float*)d_in[12];
    const float* beta_w  = (const float*)d_in[13];
    const float* beta_b  = (const float*)d_in[14];
    const float* out_w   = (const float*)d_in[15];
    const float* out_b   = (const float*)d_in[16];
    float* out = (float*)d_out;

    cudaFuncSetAttribute(gru_persistent, cudaFuncAttributeMaxDynamicSharedMemorySize, SMEM_TOTAL_PERS);
    cudaFuncSetAttribute(dense_mma,      cudaFuncAttributeMaxDynamicSharedMemorySize, SMEM_TOTAL_DENSE);

    float *p_emb=0, *p_gxa=0, *p_gxb=0, *p_beta=0, *p_ebeta=0;
    __nv_bfloat16 *p_embhi=0, *p_emblo=0, *p_fbhi=0, *p_fblo=0;
    __nv_bfloat16 *p_bwhi=0, *p_bwlo=0, *p_mthi=0, *p_mtlo=0, *p_bhi=0, *p_blo=0;
    __nv_bfloat16 *p_wihhi=0, *p_wihlo=0;
    cudaGetSymbolAddress((void**)&p_emb,   g_emb);
    cudaGetSymbolAddress((void**)&p_embhi, g_embhi);
    cudaGetSymbolAddress((void**)&p_emblo, g_emblo);
    cudaGetSymbolAddress((void**)&p_gxa,   g_gxa);
    cudaGetSymbolAddress((void**)&p_gxb,   g_gxb);
    cudaGetSymbolAddress((void**)&p_beta,  g_beta);
    cudaGetSymbolAddress((void**)&p_ebeta, g_ebeta);
    cudaGetSymbolAddress((void**)&p_fbhi,  g_fbhi);
    cudaGetSymbolAddress((void**)&p_fblo,  g_fblo);
    cudaGetSymbolAddress((void**)&p_bwhi,  g_bwhi);
    cudaGetSymbolAddress((void**)&p_bwlo,  g_bwlo);
    cudaGetSymbolAddress((void**)&p_mthi,  g_mthi);
    cudaGetSymbolAddress((void**)&p_mtlo,  g_mtlo);
    cudaGetSymbolAddress((void**)&p_bhi,   g_betahi);
    cudaGetSymbolAddress((void**)&p_blo,   g_betalo);
    cudaGetSymbolAddress((void**)&p_wihhi, g_wihhi);
    cudaGetSymbolAddress((void**)&p_wihlo, g_wihlo);

    zero_planes_kernel<<<(2*2*PB_*H_/2 + 255)/256, 256>>>();
    prep_w_kernel<<<(2*768*256)/256, 256>>>(a_whh, b_whh);
    prep_wih_kernel<<<(2*768*256)/256, 256>>>(a_wih, b_wih);
    prep_bw_kernel<<<256, 256>>>(beta_w);
    prep_mt_kernel<<<256, 256>>>(emb_w, out_w);

    // emb (fp32) + hi/lo planes
    sgemm128<<<dim3((T_*B_)/128, E_/128), 256>>>(x, emb_w, emb_b, p_emb, E_, 1,
                                                 p_embhi, p_emblo);
    // gx via tensor path (3-pass compensated)
    dense_mma<<<dim3((T_*B_)/128, 6), 512, SMEM_TOTAL_DENSE>>>(
        p_embhi, p_emblo, p_wihhi, p_wihlo, a_bih, 0, 3*H_, p_gxa,
        (__nv_bfloat16*)0, (__nv_bfloat16*)0);
    dense_mma<<<dim3((T_*B_)/128, 6), 512, SMEM_TOTAL_DENSE>>>(
        p_embhi, p_emblo, p_wihhi + (size_t)3*H_*E_, p_wihlo + (size_t)3*H_*E_,
        b_bih, 0, 3*H_, p_gxb, (__nv_bfloat16*)0, (__nv_bfloat16*)0);

    gru_persistent<<<NCTA_PERS, 512, SMEM_TOTAL_PERS>>>(a_bhh, b_bhh, alpha_w);

    alpha_kernel<<<(PB_*32 + 255)/256, 256>>>(alpha_b);

    dense_mma<<<dim3(NPACK_/128, 2), 512, SMEM_TOTAL_DENSE>>>(
        p_fbhi, p_fblo, p_bwhi, p_bwlo, beta_b, 1, E_, p_beta, p_bhi, p_blo);
    dense_mma<<<dim3(NPACK_/128, 2), 512, SMEM_TOTAL_DENSE>>>(
        p_bhi, p_blo, p_mthi, p_mtlo, (const float*)0, 0, E_, p_ebeta,
        (__nv_bfloat16*)0, (__nv_bfloat16*)0);

    reduce_kernel<<<PB_, 256>>>(x, out_w, out_b, out);
}

// round 11
// speedup vs baseline: 1.0670x; 1.0670x over previous
#include <cuda_runtime.h>
#include <cuda_bf16.h>
#include <math.h>
#include <stdint.h>

#define B_ 32
#define T_ 64
#define E_ 256
#define H_ 256
#define P_ 63
#define PB_ 2016
#define NPACK_ 64512

#define NCTA_PERS 144
#define NQ_ 18
#define SMEM_A_OFF   196608            // A buffers after 16 chunks * 12288B weights
#define ABUF_STRIDE  16384             // K32 chunk: 2 planes * 2 ksub * 8 rg16 * 512B
#define SMEM_TOTAL_PERS (196608 + 2*ABUF_STRIDE)   // 229376

#define DCHUNK 24576                   // dense: A(12288)+B(12288) per buffer
#define SMEM_TOTAL_DENSE (3*DCHUNK)    // 73728

// ------------------------- scratch (device globals) -------------------------
__device__ float g_emb[T_*B_*E_];
__device__ float g_gxa[T_*B_*3*H_];
__device__ float g_gxb[T_*B_*3*H_];
__device__ __nv_bfloat16 g_hhi[2][2][PB_*H_];   // [gru][parity]
__device__ __nv_bfloat16 g_hlo[2][2][PB_*H_];
__device__ __nv_bfloat16 g_whi[2][3*H_*H_];
__device__ __nv_bfloat16 g_wlo[2][3*H_*H_];
__device__ __nv_bfloat16 g_bwhi[E_*H_];
__device__ __nv_bfloat16 g_bwlo[E_*H_];
__device__ __nv_bfloat16 g_mthi[E_*E_];
__device__ __nv_bfloat16 g_mtlo[E_*E_];
__device__ float g_prep[(size_t)NPACK_*16];     // pre partials [prow][cb*4+wn]
__device__ __nv_bfloat16 g_fbhi[(size_t)NPACK_*H_];
__device__ __nv_bfloat16 g_fblo[(size_t)NPACK_*H_];
__device__ float g_beta[(size_t)NPACK_*E_];
__device__ __nv_bfloat16 g_betahi[(size_t)NPACK_*E_];
__device__ __nv_bfloat16 g_betalo[(size_t)NPACK_*E_];
__device__ float g_ebeta[(size_t)NPACK_*E_];
__device__ float g_alpha[P_*T_*B_];
__device__ unsigned g_bar2[2];

// ------------------------- helpers ------------------------------------------
__device__ __forceinline__ uint32_t smem_u32(const void* p) {
    uint32_t a;
    asm("{ .reg .u64 t; cvta.to.shared.u64 t, %1; cvt.u32.u64 %0, t; }" : "=r"(a) : "l"(p));
    return a;
}
__device__ __forceinline__ void ldsm4(uint32_t* r, uint32_t addr) {
    asm volatile("ldmatrix.sync.aligned.m8n8.x4.shared.b16 {%0,%1,%2,%3}, [%4];"
        : "=r"(r[0]), "=r"(r[1]), "=r"(r[2]), "=r"(r[3]) : "r"(addr));
}
__device__ __forceinline__ void mma16816(float* d, const uint32_t* a, const uint32_t* b) {
    asm volatile("mma.sync.aligned.m16n8k16.row.col.f32.bf16.bf16.f32 "
        "{%0,%1,%2,%3}, {%4,%5,%6,%7}, {%8,%9}, {%0,%1,%2,%3};"
        : "+f"(d[0]), "+f"(d[1]), "+f"(d[2]), "+f"(d[3])
        : "r"(a[0]), "r"(a[1]), "r"(a[2]), "r"(a[3]), "r"(b[0]), "r"(b[1]));
}
#define CP_ASYNC16(dst, src) \
    asm volatile("cp.async.cg.shared.global [%0], [%1], 16;" :: "r"(dst), "l"(src))
#define CP_COMMIT() asm volatile("cp.async.commit_group;")
#define CP_WAIT1()  asm volatile("cp.async.wait_group 1;")
#define CP_WAIT0()  asm volatile("cp.async.wait_group 0;")

// ------------------------- prep kernels -------------------------------------
__global__ void zero_planes_kernel() {
    int i = blockIdx.x*256 + threadIdx.x;
    uint32_t* a = (uint32_t*)g_hhi;
    uint32_t* b = (uint32_t*)g_hlo;
    if (i < 2*2*PB_*H_/2) { a[i] = 0u; b[i] = 0u; }
    if (i < 2) g_bar2[i] = 0u;
}
__global__ void prep_w_kernel(const float* __restrict__ wa, const float* __restrict__ wb) {
    int idx = blockIdx.x*256 + threadIdx.x;
    int k = idx & 255;
    int r = (idx >> 8) % 768;
    int gru = idx / (768*256);
    float v = (gru ? wb : wa)[r*256 + k];
    __nv_bfloat16 hi = __float2bfloat16(v);
    g_whi[gru][r*256 + k] = hi;
    g_wlo[gru][r*256 + k] = __float2bfloat16(v - __bfloat162float(hi));
}
__global__ void prep_bw_kernel(const float* __restrict__ bw) {
    int idx = blockIdx.x*256 + threadIdx.x;
    float v = bw[idx];
    __nv_bfloat16 hi = __float2bfloat16(v);
    g_bwhi[idx] = hi;
    g_bwlo[idx] = __float2bfloat16(v - __bfloat162float(hi));
}
__global__ void prep_mt_kernel(const float* __restrict__ emb_w, const float* __restrict__ out_w) {
    int idx = blockIdx.x*256 + threadIdx.x;
    int i = idx >> 8, e = idx & 255;
    float v = out_w[e] * emb_w[e*256 + i];
    __nv_bfloat16 hi = __float2bfloat16(v);
    g_mthi[idx] = hi;
    g_mtlo[idx] = __float2bfloat16(v - __bfloat162float(hi));
}

// ------------------------- fp32 SGEMM (emb / gx) ----------------------------
__device__ __forceinline__ const float* arow_ptr(const float* A, int m, int xmode) {
    if (xmode) { int t = m >> 5, b = m & 31; return A + ((size_t)b*T_ + t)*E_; }
    return A + (size_t)m*E_;
}
__device__ __forceinline__ void sgemm_body(
        const float* A, const float* Bt, const float* bias, float* C,
        int N, int act, int xmode, int m0, int n0) {
    __shared__ float As[2][8][128];
    __shared__ float Bs[2][8][128];
    const int tid = threadIdx.x;
    const int tx = tid & 15, ty = tid >> 4;
    const int lr = tid >> 1;
    const int ks = (tid & 1) * 4;
    const float* pA = arow_ptr(A, m0 + lr, xmode) + ks;
    const float* pB = Bt + (size_t)(n0 + lr) * 256 + ks;
    float acc[2][2][4][4] = {};
    float4 va = *(const float4*)pA;
    float4 vb = *(const float4*)pB;
    {
        const float* f = (const float*)&va;
#pragma unroll
        for (int j = 0; j < 4; j++) As[0][ks+j][lr] = f[j];
        f = (const float*)&vb;
#pragma unroll
        for (int j = 0; j < 4; j++) Bs[0][ks+j][lr] = f[j];
    }
    __syncthreads();
    int buf = 0;
#pragma unroll 1
    for (int c = 0; c < 32; c++) {
        if (c < 31) {
            int off = (c+1)*8;
            va = *(const float4*)(pA + off);
            vb = *(const float4*)(pB + off);
        }
#pragma unroll
        for (int kk = 0; kk < 8; kk++) {
            float4 a0 = *(const float4*)&As[buf][kk][ty*4];
            float4 a1 = *(const float4*)&As[buf][kk][ty*4 + 64];
            float4 b0 = *(const float4*)&Bs[buf][kk][tx*4];
            float4 b1 = *(const float4*)&Bs[buf][kk][tx*4 + 64];
            float aa[2][4] = {{a0.x,a0.y,a0.z,a0.w},{a1.x,a1.y,a1.z,a1.w}};
            float bb[2][4] = {{b0.x,b0.y,b0.z,b0.w},{b1.x,b1.y,b1.z,b1.w}};
#pragma unroll
            for (int rh = 0; rh < 2; rh++)
#pragma unroll
            for (int i = 0; i < 4; i++)
#pragma unroll
            for (int ch = 0; ch < 2; ch++)
#pragma unroll
            for (int j = 0; j < 4; j++)
                acc[rh][ch][i][j] = fmaf(aa[rh][i], bb[ch][j], acc[rh][ch][i][j]);
        }
        if (c < 31) {
            int nb = buf ^ 1;
            const float* f = (const float*)&va;
#pragma unroll
            for (int j = 0; j < 4; j++) As[nb][ks+j][lr] = f[j];
            f = (const float*)&vb;
#pragma unroll
            for (int j = 0; j < 4; j++) Bs[nb][ks+j][lr] = f[j];
            __syncthreads();
            buf = nb;
        }
    }
#pragma unroll
    for (int rh = 0; rh < 2; rh++)
#pragma unroll
    for (int i = 0; i < 4; i++) {
        int m = m0 + rh*64 + ty*4 + i;
#pragma unroll
        for (int ch = 0; ch < 2; ch++) {
            int n = n0 + ch*64 + tx*4;
            float4 v;
            v.x = acc[rh][ch][i][0]; v.y = acc[rh][ch][i][1];
            v.z = acc[rh][ch][i][2]; v.w = acc[rh][ch][i][3];
            if (bias) {
                float4 bz = *(const float4*)&bias[n];
                v.x += bz.x; v.y += bz.y; v.z += bz.z; v.w += bz.w;
            }
            if (act == 1) { v.x = tanhf(v.x); v.y = tanhf(v.y); v.z = tanhf(v.z); v.w = tanhf(v.w); }
            *(float4*)&C[(size_t)m*N + n] = v;
        }
    }
}
__global__ void __launch_bounds__(256, 2)
sgemm128(const float* __restrict__ A, const float* __restrict__ Bt,
         const float* __restrict__ bias, float* __restrict__ C,
         int N, int act, int xmode) {
    sgemm_body(A, Bt, bias, C, N, act, xmode, blockIdx.x*128, blockIdx.y*128);
}
__global__ void __launch_bounds__(256, 2)
sgemm128_gx(const float* __restrict__ A,
            const float* __restrict__ BtA, const float* __restrict__ biasA, float* __restrict__ CA,
            const float* __restrict__ BtB, const float* __restrict__ biasB, float* __restrict__ CB) {
    int y = blockIdx.y;
    if (y < 6) sgemm_body(A, BtA, biasA, CA, 3*H_, 0, 0, blockIdx.x*128, y*128);
    else       sgemm_body(A, BtB, biasB, CB, 3*H_, 0, 0, blockIdx.x*128, (y-6)*128);
}

// ------------------------- persistent GRU recurrence ------------------------
// Piece-packed smem (conflict-free ldmatrix), K=32 chunks: 8 iters, 8 syncs.
__global__ void __launch_bounds__(512, 1)
gru_persistent(const float* __restrict__ bhh_a, const float* __restrict__ bhh_b,
               const float* __restrict__ alpha_w) {
    extern __shared__ __align__(16) unsigned char smem[];
    const int tid = threadIdx.x, lane = tid & 31, wid = tid >> 5;
    const int wm = wid & 3, wn = wid >> 2;
    const int gid = blockIdx.x;
    const int gru = gid & 1, cb = (gid >> 1) & 3, q = gid >> 3;
    const uint32_t sbase = smem_u32(smem);

    // ---- one-time weight slice load (piece-packed; 16 k16-chunks of 12288B) ----
    {
        const __nv_bfloat16* Whi = g_whi[gru];
        const __nv_bfloat16* Wlo = g_wlo[gru];
        for (int u = tid; u < 12288; u += 512) {
            int nrow7 = u & 7;
            int kh = (u >> 3) & 1;
            int nh = (u >> 4) & 1;
            int ng16 = (u >> 5) % 12;
            int pc = (u >> 5) / 12;
            int p = pc & 1, c = pc >> 1;
            int Rg = (ng16 >> 2)*256 + cb*64 + (ng16 & 3)*16 + nh*8 + nrow7;
            const __nv_bfloat16* src = (p ? Wlo : Whi) + (size_t)Rg*256 + c*16 + kh*8;
            uint32_t dst = (uint32_t)(c*12288 + p*6144 + ng16*512 + nh*256 + kh*128 + nrow7*16);
            *(uint4*)(smem + dst) = *(const uint4*)src;
        }
    }
    __syncthreads();

    // ---- per-lane ldmatrix offsets (piece-packed, conflict-free) ----
    const uint32_t lpiece = (uint32_t)((lane >> 4)*256 + ((lane >> 3) & 1)*128 + (lane & 7)*16);
    uint32_t abase[2][2][2];   // [buf][plane][i]  (+ s*4096 for ksub)
#pragma unroll
    for (int bf = 0; bf < 2; bf++)
#pragma unroll
    for (int p = 0; p < 2; p++)
#pragma unroll
    for (int i = 0; i < 2; i++)
        abase[bf][p][i] = sbase + SMEM_A_OFF + bf*ABUF_STRIDE + p*8192u
                        + (uint32_t)((wm*2 + i)*512) + lpiece;
    uint32_t wboff[2][3];
#pragma unroll
    for (int p = 0; p < 2; p++)
#pragma unroll
    for (int g = 0; g < 3; g++)
        wboff[p][g] = (uint32_t)(p*6144 + (g*4 + wn)*512) + lpiece;

    const float* bhh = gru ? bhh_b : bhh_a;
    const float* gx  = gru ? g_gxb : g_gxa;
    const int st_q = tid & 1, st_r = (tid >> 1) & 127, st_p = tid >> 8;
    const uint32_t st_dst0 = sbase + SMEM_A_OFF + st_p*8192u
        + (uint32_t)((st_r >> 4)*512 + st_q*256 + ((st_r & 8) >> 3)*128 + (st_r & 7)*16);

    const int g8 = lane >> 2, t2 = (lane & 3)*2;
    unsigned* mybar = &g_bar2[gru];

#pragma unroll 1
    for (int step = 0; step < 63; step++) {
        const int par = step & 1;
        const int nch = (63 - step)*2;
        const int c0 = (q*nch)/NQ_, c1 = ((q+1)*nch)/NQ_;
        const int R = (c1 - c0)*16;
        if (R > 0) {
            const __nv_bfloat16* Hhi = g_hhi[gru][par];
            const __nv_bfloat16* Hlo = g_hlo[gru][par];
            const int rowbase = step*32 + c0*16;
            const int ng = R >> 4;
            const bool st_on = (st_r < R);
            const __nv_bfloat16* st_src = (st_p ? Hlo : Hhi)
                + (size_t)(rowbase + (st_on ? st_r : 0))*H_ + st_q*8;

            float acc[3][2][2][4] = {};
            if (st_on) { CP_ASYNC16(st_dst0, st_src); CP_ASYNC16(st_dst0 + 4096u, st_src + 16); }
            CP_COMMIT();
#pragma unroll 1
            for (int cc = 0; cc < 8; cc++) {
                CP_WAIT0();
                __syncthreads();
                if (cc < 7) {
                    uint32_t d = st_dst0 + (uint32_t)(((cc+1)&1)*ABUF_STRIDE);
                    const __nv_bfloat16* s2 = st_src + (cc+1)*32;
                    if (st_on) { CP_ASYNC16(d, s2); CP_ASYNC16(d + 4096u, s2 + 16); }
                    CP_COMMIT();
                }
                const int bufi = cc & 1;
                if (2*wm < ng) {
                    const bool two = (2*wm + 1 < ng);
#pragma unroll
                    for (int s = 0; s < 2; s++) {
                        const uint32_t asub = (uint32_t)(s*4096);
                        uint32_t Ah[2][4], Al[2][4];
                        ldsm4(Ah[0], abase[bufi][0][0] + asub);
                        ldsm4(Al[0], abase[bufi][1][0] + asub);
                        if (two) {
                            ldsm4(Ah[1], abase[bufi][0][1] + asub);
                            ldsm4(Al[1], abase[bufi][1][1] + asub);
                        }
                        const uint32_t wbc = sbase + (uint32_t)((cc*2 + s)*12288);
#pragma unroll
                        for (int g = 0; g < 3; g++) {
                            uint32_t Bh[4], Bl[4];
                            ldsm4(Bh, wbc + wboff[0][g]);
                            ldsm4(Bl, wbc + wboff[1][g]);
#pragma unroll
                            for (int j = 0; j < 2; j++) {
                                mma16816(acc[g][0][j], Ah[0], &Bh[j*2]);
                                mma16816(acc[g][0][j], Ah[0], &Bl[j*2]);
                                mma16816(acc[g][0][j], Al[0], &Bh[j*2]);
                            }
                            if (two) {
#pragma unroll
                                for (int j = 0; j < 2; j++) {
                                    mma16816(acc[g][1][j], Ah[1], &Bh[j*2]);
                                    mma16816(acc[g][1][j], Ah[1], &Bl[j*2]);
                                    mma16816(acc[g][1][j], Al[1], &Bh[j*2]);
                                }
                            }
                        }
                    }
                }
            }
            // ---- epilogue ----
            __nv_bfloat16* Hhi_n = g_hhi[gru][par^1];
            __nv_bfloat16* Hlo_n = g_hlo[gru][par^1];
            const size_t offk = (size_t)32*(63*step - (step*(step-1))/2);
#pragma unroll
            for (int i = 0; i < 2; i++) {
                if (2*wm + i >= ng) continue;
#pragma unroll
                for (int half = 0; half < 2; half++) {
                    int grow = rowbase + wm*32 + i*16 + g8 + half*8;
                    int gxrow = grow - step*32;
                    const float* gxr = gx + (size_t)gxrow*(3*H_);
                    size_t prow = offk + gxrow;
                    float row_part = 0.f;
#pragma unroll
                    for (int j = 0; j < 2; j++) {
                        int cc2 = cb*64 + wn*16 + j*8 + t2;
                        float2 gx_r = *(const float2*)&gxr[cc2];
                        float2 gx_z = *(const float2*)&gxr[H_ + cc2];
                        float2 gx_n = *(const float2*)&gxr[2*H_ + cc2];
                        float2 bh_r = *(const float2*)&bhh[cc2];
                        float2 bh_z = *(const float2*)&bhh[H_ + cc2];
                        float2 bh_n = *(const float2*)&bhh[2*H_ + cc2];
                        __nv_bfloat162 ho_hi = *(const __nv_bfloat162*)&Hhi[(size_t)grow*H_ + cc2];
                        __nv_bfloat162 ho_lo = *(const __nv_bfloat162*)&Hlo[(size_t)grow*H_ + cc2];
                        float hn2[2];
#pragma unroll
                        for (int u = 0; u < 2; u++) {
                            int ai = half*2 + u;
                            float rp = acc[0][i][j][ai] + (u ? bh_r.y : bh_r.x) + (u ? gx_r.y : gx_r.x);
                            float zp = acc[1][i][j][ai] + (u ? bh_z.y : bh_z.x) + (u ? gx_z.y : gx_z.x);
                            float np = acc[2][i][j][ai] + (u ? bh_n.y : bh_n.x);
                            float r = 1.f/(1.f + expf(-rp));
                            float z = 1.f/(1.f + expf(-zp));
                            float n = tanhf((u ? gx_n.y : gx_n.x) + r*np);
                            float hold = __bfloat162float(u ? ho_hi.y : ho_hi.x)
                                       + __bfloat162float(u ? ho_lo.y : ho_lo.x);
                            hn2[u] = (1.f - z)*n + z*hold;
                        }
                        __nv_bfloat162 hi2, lo2;
                        hi2.x = __float2bfloat16(hn2[0]); hi2.y = __float2bfloat16(hn2[1]);
                        lo2.x = __float2bfloat16(hn2[0] - __bfloat162float(hi2.x));
                        lo2.y = __float2bfloat16(hn2[1] - __bfloat162float(hi2.y));
                        *(__nv_bfloat162*)&Hhi_n[(size_t)grow*H_ + cc2] = hi2;
                        *(__nv_bfloat162*)&Hlo_n[(size_t)grow*H_ + cc2] = lo2;
                        if (gru == 0) {
                            float2 aw = *(const float2*)&alpha_w[cc2];
                            row_part += 0.5f*hn2[0]*aw.x + 0.5f*hn2[1]*aw.y;
                        } else {
                            float f0 = 0.5f*hn2[0], f1 = 0.5f*hn2[1];
                            __nv_bfloat162 fh, fl;
                            fh.x = __float2bfloat16(f0); fh.y = __float2bfloat16(f1);
                            fl.x = __float2bfloat16(f0 - __bfloat162float(fh.x));
                            fl.y = __float2bfloat16(f1 - __bfloat162float(fh.y));
                            *(__nv_bfloat162*)&g_fbhi[prow*H_ + cc2] = fh;
                            *(__nv_bfloat162*)&g_fblo[prow*H_ + cc2] = fl;
                        }
                    }
                    if (gru == 0) {
                        row_part += __shfl_xor_sync(0xffffffffu, row_part, 1);
                        row_part += __shfl_xor_sync(0xffffffffu, row_part, 2);
                        if ((lane & 3) == 0)
                            g_prep[prow*16 + cb*4 + wn] = row_part;
                    }
                }
            }
        }
        // ---- per-gru grid barrier (72 CTAs each) ----
        __syncthreads();
        if (tid == 0) {
            __threadfence();
            atomicAdd(mybar, 1u);
            const unsigned target = 72u*(unsigned)(step+1);
            unsigned v;
            do {
                asm volatile("ld.acquire.gpu.u32 %0, [%1];" : "=r"(v) : "l"(mybar));
            } while (v < target);
        }
        __syncthreads();
    }
}

// ------------------------- mma dense GEMM (M x 256, K=256) ------------------
__global__ void __launch_bounds__(512, 1)
dense_mma(const __nv_bfloat16* __restrict__ Ahi, const __nv_bfloat16* __restrict__ Alo,
          const __nv_bfloat16* __restrict__ Bthi, const __nv_bfloat16* __restrict__ Btlo,
          const float* __restrict__ bias, int act, float* __restrict__ outf,
          __nv_bfloat16* __restrict__ Phi, __nv_bfloat16* __restrict__ Plo) {
    extern __shared__ __align__(16) unsigned char smem[];
    const int tid = threadIdx.x, lane = tid & 31, wid = tid >> 5;
    const int wm = wid & 3, wn = wid >> 2;
    const int cb = blockIdx.y;
    const int rowbase = blockIdx.x * 128;
    const uint32_t sbase = smem_u32(smem);

    float acc[2][4][4] = {};

    const int a_r = lane & 15, a_c16 = ((lane >> 4) & 1) * 16;
    const int b_r = (lane & 7) + ((lane >> 4) & 1) * 8, b_c16 = (lane & 8) * 2;
    uint32_t aoff[3][2][2], boff[3][2][2];
#pragma unroll
    for (int bf = 0; bf < 3; bf++)
#pragma unroll
    for (int p = 0; p < 2; p++) {
#pragma unroll
        for (int i = 0; i < 2; i++)
            aoff[bf][p][i] = sbase + bf*DCHUNK + p*6144u
                           + (uint32_t)((wm*32 + i*16 + a_r)*48 + a_c16);
#pragma unroll
        for (int h2 = 0; h2 < 2; h2++)
            boff[bf][p][h2] = sbase + bf*DCHUNK + 12288u + p*6144u
                           + (uint32_t)((wn*32 + h2*16 + b_r)*48 + b_c16);
    }

    const int st_q = tid & 1, st_r = (tid >> 1) & 127, st_p = tid >> 8;
    const uint32_t stA = sbase + st_p*6144u + (uint32_t)(st_r*48 + st_q*16);
    const uint32_t stB = stA + 12288u;
    const __nv_bfloat16* srcA = (st_p ? Alo : Ahi) + (size_t)(rowbase + st_r)*256 + st_q*8;
    const __nv_bfloat16* srcB = (st_p ? Btlo : Bthi) + (size_t)(cb*128 + st_r)*256 + st_q*8;

    CP_ASYNC16(stA, srcA); CP_ASYNC16(stB, srcB); CP_COMMIT();
    CP_ASYNC16(stA + DCHUNK, srcA + 16); CP_ASYNC16(stB + DCHUNK, srcB + 16); CP_COMMIT();

    int bufi = 0;
#pragma unroll 1
    for (int c = 0; c < 16; c++) {
        if (c < 15) { CP_WAIT1(); } else { CP_WAIT0(); }
        __syncthreads();
        if (c < 14) {
            int nb = bufi + 2; if (nb >= 3) nb -= 3;
            CP_ASYNC16(stA + (uint32_t)(nb*DCHUNK), srcA + (c+2)*16);
            CP_ASYNC16(stB + (uint32_t)(nb*DCHUNK), srcB + (c+2)*16);
            CP_COMMIT();
        }
        uint32_t Ah[2][4], Al[2][4], Bh[8], Bl[8];
        ldsm4(Ah[0], aoff[bufi][0][0]); ldsm4(Ah[1], aoff[bufi][0][1]);
        ldsm4(Al[0], aoff[bufi][1][0]); ldsm4(Al[1], aoff[bufi][1][1]);
        ldsm4(Bh,   boff[bufi][0][0]); ldsm4(Bh+4, boff[bufi][0][1]);
        ldsm4(Bl,   boff[bufi][1][0]); ldsm4(Bl+4, boff[bufi][1][1]);
#pragma unroll
        for (int i = 0; i < 2; i++)
#pragma unroll
        for (int j = 0; j < 4; j++) {
            mma16816(acc[i][j], Ah[i], &Bh[j*2]);
            mma16816(acc[i][j], Ah[i], &Bl[j*2]);
            mma16816(acc[i][j], Al[i], &Bh[j*2]);
        }
        bufi++; if (bufi == 3) bufi = 0;
    }

    const int g8 = lane >> 2, t2 = (lane & 3)*2;
#pragma unroll
    for (int i = 0; i < 2; i++)
#pragma unroll
    for (int half = 0; half < 2; half++) {
        int grow = rowbase + wm*32 + i*16 + g8 + half*8;
#pragma unroll
        for (int j = 0; j < 4; j++) {
            int cc = cb*128 + wn*32 + j*8 + t2;
            float v0 = acc[i][j][half*2 + 0];
            float v1 = acc[i][j][half*2 + 1];
            if (bias) { v0 += bias[cc]; v1 += bias[cc+1]; }
            if (act == 1) { v0 = tanhf(v0); v1 = tanhf(v1); }
            float2 f2; f2.x = v0; f2.y = v1;
            *(float2*)&outf[(size_t)grow*E_ + cc] = f2;
            if (Phi) {
                __nv_bfloat162 hi2, lo2;
                hi2.x = __float2bfloat16(v0); hi2.y = __float2bfloat16(v1);
                lo2.x = __float2bfloat16(v0 - __bfloat162float(hi2.x));
                lo2.y = __float2bfloat16(v1 - __bfloat162float(hi2.y));
                *(__nv_bfloat162*)&Phi[(size_t)grow*E_ + cc] = hi2;
                *(__nv_bfloat162*)&Plo[(size_t)grow*E_ + cc] = lo2;
            }
        }
    }
}

// ------------------------- alpha (pre-partial sum + softmax) ----------------
__global__ void alpha_kernel(const float* __restrict__ alpha_b) {
    int gw = (blockIdx.x*blockDim.x + threadIdx.x) >> 5;
    int lane = threadIdx.x & 31;
    if (gw >= PB_) return;
    int p = gw >> 5, b = gw & 31;
    float ab = alpha_b[0];
    float v0 = -1e30f, v1 = -1e30f;
    {
        int t = lane;
        if (t <= p) {
            int kk = p - t;
            int offk = 32*(63*kk - (kk*(kk-1))/2);
            size_t prow = (size_t)offk + t*32 + b;
            const float4* qq = (const float4*)&g_prep[prow*16];
            float4 s0 = qq[0], s1 = qq[1], s2 = qq[2], s3 = qq[3];
            v0 = (s0.x+s0.y+s0.z+s0.w) + (s1.x+s1.y+s1.z+s1.w)
               + (s2.x+s2.y+s2.z+s2.w) + (s3.x+s3.y+s3.z+s3.w) + ab;
        }
    }
    {
        int t = lane + 32;
        if (t <= p) {
            int kk = p - t;
            int offk = 32*(63*kk - (kk*(kk-1))/2);
            size_t prow = (size_t)offk + t*32 + b;
            const float4* qq = (const float4*)&g_prep[prow*16];
            float4 s0 = qq[0], s1 = qq[1], s2 = qq[2], s3 = qq[3];
            v1 = (s0.x+s0.y+s0.z+s0.w) + (s1.x+s1.y+s1.z+s1.w)
               + (s2.x+s2.y+s2.z+s2.w) + (s3.x+s3.y+s3.z+s3.w) + ab;
        }
    }
    float m = fmaxf(v0, v1);
#pragma unroll
    for (int o=16;o;o>>=1) m = fmaxf(m, __shfl_xor_sync(0xffffffffu, m, o));
    float e0 = (lane      <= p) ? expf(v0-m) : 0.f;
    float e1 = (lane + 32 <= p) ? expf(v1-m) : 0.f;
    float s = e0 + e1;
#pragma unroll
    for (int o=16;o;o>>=1) s += __shfl_xor_sync(0xffffffffu, s, o);
    float inv = 1.f/s;
    g_alpha[(p*T_+lane   )*B_+b] = e0*inv;
    g_alpha[(p*T_+lane+32)*B_+b] = e1*inv;
}

__global__ void reduce_kernel(const float* __restrict__ x,
                              const float* __restrict__ out_w,
                              const float* __restrict__ out_b,
                              float* __restrict__ out) {
    int pb = blockIdx.x;
    int p = 62 - (pb >> 5);
    int b = pb & 31;
    int e = threadIdx.x;
    float cc = 0.f, gg = 0.f;
    for (int t = 0; t <= p; t++) {
        float a = g_alpha[(p*T_+t)*B_+b];
        int kk = p - t;
        int offk = 32*(63*kk - (kk*(kk-1))/2);
        size_t prow = (size_t)offk + t*32 + b;
        cc += a * g_beta [prow*E_ + e] * g_emb[((size_t)(t*B_+b))*E_ + e];
        gg += a * g_ebeta[prow*E_ + e] * x[((size_t)b*T_ + t)*E_ + e];
    }
    out[B_*P_ + ((size_t)(b*P_+p))*E_ + e] = gg / (float)(p+1);
    __shared__ float red[256];
    red[e] = cc * out_w[e];
    __syncthreads();
    for (int s2=128; s2; s2>>=1) { if (e < s2) red[e] += red[e+s2]; __syncthreads(); }
    if (e == 0) out[b*P_ + p] = red[0] + out_b[0];
}

// ------------------------- launch -------------------------------------------
extern "C" void kernel_launch(void* const* d_in, const int* in_sizes, int n_in,
                              void* d_out, int out_size) {
    (void)in_sizes; (void)n_in; (void)out_size;
    const float* x       = (const float*)d_in[0];
    const float* emb_w   = (const float*)d_in[1];
    const float* emb_b   = (const float*)d_in[2];
    const float* a_wih   = (const float*)d_in[3];
    const float* a_whh   = (const float*)d_in[4];
    const float* a_bih   = (const float*)d_in[5];
    const float* a_bhh   = (const float*)d_in[6];
    const float* b_wih   = (const float*)d_in[7];
    const float* b_whh   = (const float*)d_in[8];
    const float* b_bih   = (const float*)d_in[9];
    const float* b_bhh   = (const float*)d_in[10];
    const float* alpha_w = (const float*)d_in[11];
    const float* alpha_b = (const float*)d_in[12];
    const float* beta_w  = (const float*)d_in[13];
    const float* beta_b  = (const float*)d_in[14];
    const float* out_w   = (const float*)d_in[15];
    const float* out_b   = (const float*)d_in[16];
    float* out = (float*)d_out;

    cudaFuncSetAttribute(gru_persistent, cudaFuncAttributeMaxDynamicSharedMemorySize, SMEM_TOTAL_PERS);
    cudaFuncSetAttribute(dense_mma,      cudaFuncAttributeMaxDynamicSharedMemorySize, SMEM_TOTAL_DENSE);

    float *p_emb=0, *p_gxa=0, *p_gxb=0, *p_beta=0, *p_ebeta=0;
    __nv_bfloat16 *p_fbhi=0, *p_fblo=0, *p_bwhi=0, *p_bwlo=0;
    __nv_bfloat16 *p_mthi=0, *p_mtlo=0, *p_bhi=0, *p_blo=0;
    cudaGetSymbolAddress((void**)&p_emb,   g_emb);
    cudaGetSymbolAddress((void**)&p_gxa,   g_gxa);
    cudaGetSymbolAddress((void**)&p_gxb,   g_gxb);
    cudaGetSymbolAddress((void**)&p_beta,  g_beta);
    cudaGetSymbolAddress((void**)&p_ebeta, g_ebeta);
    cudaGetSymbolAddress((void**)&p_fbhi,  g_fbhi);
    cudaGetSymbolAddress((void**)&p_fblo,  g_fblo);
    cudaGetSymbolAddress((void**)&p_bwhi,  g_bwhi);
    cudaGetSymbolAddress((void**)&p_bwlo,  g_bwlo);
    cudaGetSymbolAddress((void**)&p_mthi,  g_mthi);
    cudaGetSymbolAddress((void**)&p_mtlo,  g_mtlo);
    cudaGetSymbolAddress((void**)&p_bhi,   g_betahi);
    cudaGetSymbolAddress((void**)&p_blo,   g_betalo);

    zero_planes_kernel<<<(2*2*PB_*H_/2 + 255)/256, 256>>>();
    prep_w_kernel<<<(2*768*256)/256, 256>>>(a_whh, b_whh);
    prep_bw_kernel<<<256, 256>>>(beta_w);
    prep_mt_kernel<<<256, 256>>>(emb_w, out_w);

    sgemm128<<<dim3((T_*B_)/128, E_/128), 256>>>(x, emb_w, emb_b, p_emb, E_, 0, 1);
    sgemm128_gx<<<dim3((T_*B_)/128, 12), 256>>>(p_emb, a_wih, a_bih, p_gxa,
                                                b_wih, b_bih, p_gxb);

    gru_persistent<<<NCTA_PERS, 512, SMEM_TOTAL_PERS>>>(a_bhh, b_bhh, alpha_w);

    alpha_kernel<<<(PB_*32 + 255)/256, 256>>>(alpha_b);

    dense_mma<<<dim3(NPACK_/128, 2), 512, SMEM_TOTAL_DENSE>>>(
        p_fbhi, p_fblo, p_bwhi, p_bwlo, beta_b, 1, p_beta, p_bhi, p_blo);
    dense_mma<<<dim3(NPACK_/128, 2), 512, SMEM_TOTAL_DENSE>>>(
        p_bhi, p_blo, p_mthi, p_mtlo, (const float*)0, 0, p_ebeta,
        (__nv_bfloat16*)0, (__nv_bfloat16*)0);

    reduce_kernel<<<PB_, 256>>>(x, out_w, out_b, out);
}

// round 12
// speedup vs baseline: 1.2786x; 1.1983x over previous
#include <cuda_runtime.h>
#include <cuda_bf16.h>
#include <math.h>
#include <stdint.h>

#define B_ 32
#define T_ 64
#define E_ 256
#define H_ 256
#define P_ 63
#define PB_ 2016
#define NPACK_ 64512

#define NCTA_PERS 144
#define NQ_ 18
#define SMEM_A_OFF   196608            // A buffers after 16 chunks * 12288B weights
#define ABUF_STRIDE  16384             // adaptive chunk: holds R*KC <= 4096 elems * 2 planes * 2B
#define SMEM_TOTAL_PERS (196608 + 2*ABUF_STRIDE)   // 229376

#define DCHUNK 24576                   // dense: A(12288)+B(12288) per buffer
#define SMEM_TOTAL_DENSE (3*DCHUNK)    // 73728

// ------------------------- scratch (device globals) -------------------------
__device__ float g_emb[T_*B_*E_];
__device__ float g_gxa[T_*B_*3*H_];
__device__ float g_gxb[T_*B_*3*H_];
__device__ __nv_bfloat16 g_hhi[2][2][PB_*H_];   // [gru][parity]
__device__ __nv_bfloat16 g_hlo[2][2][PB_*H_];
__device__ __nv_bfloat16 g_whi[2][3*H_*H_];
__device__ __nv_bfloat16 g_wlo[2][3*H_*H_];
__device__ __nv_bfloat16 g_bwhi[E_*H_];
__device__ __nv_bfloat16 g_bwlo[E_*H_];
__device__ __nv_bfloat16 g_mthi[E_*E_];
__device__ __nv_bfloat16 g_mtlo[E_*E_];
__device__ float g_prep[(size_t)NPACK_*16];     // pre partials [prow][cb*4+wn]
__device__ __nv_bfloat16 g_fbhi[(size_t)NPACK_*H_];
__device__ __nv_bfloat16 g_fblo[(size_t)NPACK_*H_];
__device__ float g_beta[(size_t)NPACK_*E_];
__device__ __nv_bfloat16 g_betahi[(size_t)NPACK_*E_];
__device__ __nv_bfloat16 g_betalo[(size_t)NPACK_*E_];
__device__ float g_ebeta[(size_t)NPACK_*E_];
__device__ float g_alpha[P_*T_*B_];
__device__ unsigned g_bar2[2];

// ------------------------- helpers ------------------------------------------
__device__ __forceinline__ uint32_t smem_u32(const void* p) {
    uint32_t a;
    asm("{ .reg .u64 t; cvta.to.shared.u64 t, %1; cvt.u32.u64 %0, t; }" : "=r"(a) : "l"(p));
    return a;
}
__device__ __forceinline__ void ldsm4(uint32_t* r, uint32_t addr) {
    asm volatile("ldmatrix.sync.aligned.m8n8.x4.shared.b16 {%0,%1,%2,%3}, [%4];"
        : "=r"(r[0]), "=r"(r[1]), "=r"(r[2]), "=r"(r[3]) : "r"(addr));
}
__device__ __forceinline__ void mma16816(float* d, const uint32_t* a, const uint32_t* b) {
    asm volatile("mma.sync.aligned.m16n8k16.row.col.f32.bf16.bf16.f32 "
        "{%0,%1,%2,%3}, {%4,%5,%6,%7}, {%8,%9}, {%0,%1,%2,%3};"
        : "+f"(d[0]), "+f"(d[1]), "+f"(d[2]), "+f"(d[3])
        : "r"(a[0]), "r"(a[1]), "r"(a[2]), "r"(a[3]), "r"(b[0]), "r"(b[1]));
}
#define CP_ASYNC16(dst, src) \
    asm volatile("cp.async.cg.shared.global [%0], [%1], 16;" :: "r"(dst), "l"(src))
#define CP_COMMIT() asm volatile("cp.async.commit_group;")
#define CP_WAIT1()  asm volatile("cp.async.wait_group 1;")
#define CP_WAIT0()  asm volatile("cp.async.wait_group 0;")

// ------------------------- prep kernels -------------------------------------
__global__ void zero_planes_kernel() {
    int i = blockIdx.x*256 + threadIdx.x;
    uint32_t* a = (uint32_t*)g_hhi;
    uint32_t* b = (uint32_t*)g_hlo;
    if (i < 2*2*PB_*H_/2) { a[i] = 0u; b[i] = 0u; }
    if (i < 2) g_bar2[i] = 0u;
}
__global__ void prep_w_kernel(const float* __restrict__ wa, const float* __restrict__ wb) {
    int idx = blockIdx.x*256 + threadIdx.x;
    int k = idx & 255;
    int r = (idx >> 8) % 768;
    int gru = idx / (768*256);
    float v = (gru ? wb : wa)[r*256 + k];
    __nv_bfloat16 hi = __float2bfloat16(v);
    g_whi[gru][r*256 + k] = hi;
    g_wlo[gru][r*256 + k] = __float2bfloat16(v - __bfloat162float(hi));
}
__global__ void prep_bw_kernel(const float* __restrict__ bw) {
    int idx = blockIdx.x*256 + threadIdx.x;
    float v = bw[idx];
    __nv_bfloat16 hi = __float2bfloat16(v);
    g_bwhi[idx] = hi;
    g_bwlo[idx] = __float2bfloat16(v - __bfloat162float(hi));
}
__global__ void prep_mt_kernel(const float* __restrict__ emb_w, const float* __restrict__ out_w) {
    int idx = blockIdx.x*256 + threadIdx.x;
    int i = idx >> 8, e = idx & 255;
    float v = out_w[e] * emb_w[e*256 + i];
    __nv_bfloat16 hi = __float2bfloat16(v);
    g_mthi[idx] = hi;
    g_mtlo[idx] = __float2bfloat16(v - __bfloat162float(hi));
}

// ------------------------- fp32 SGEMM (emb / gx) ----------------------------
__device__ __forceinline__ const float* arow_ptr(const float* A, int m, int xmode) {
    if (xmode) { int t = m >> 5, b = m & 31; return A + ((size_t)b*T_ + t)*E_; }
    return A + (size_t)m*E_;
}
__device__ __forceinline__ void sgemm_body(
        const float* A, const float* Bt, const float* bias, float* C,
        int N, int act, int xmode, int m0, int n0) {
    __shared__ float As[2][8][128];
    __shared__ float Bs[2][8][128];
    const int tid = threadIdx.x;
    const int tx = tid & 15, ty = tid >> 4;
    const int lr = tid >> 1;
    const int ks = (tid & 1) * 4;
    const float* pA = arow_ptr(A, m0 + lr, xmode) + ks;
    const float* pB = Bt + (size_t)(n0 + lr) * 256 + ks;
    float acc[2][2][4][4] = {};
    float4 va = *(const float4*)pA;
    float4 vb = *(const float4*)pB;
    {
        const float* f = (const float*)&va;
#pragma unroll
        for (int j = 0; j < 4; j++) As[0][ks+j][lr] = f[j];
        f = (const float*)&vb;
#pragma unroll
        for (int j = 0; j < 4; j++) Bs[0][ks+j][lr] = f[j];
    }
    __syncthreads();
    int buf = 0;
#pragma unroll 1
    for (int c = 0; c < 32; c++) {
        if (c < 31) {
            int off = (c+1)*8;
            va = *(const float4*)(pA + off);
            vb = *(const float4*)(pB + off);
        }
#pragma unroll
        for (int kk = 0; kk < 8; kk++) {
            float4 a0 = *(const float4*)&As[buf][kk][ty*4];
            float4 a1 = *(const float4*)&As[buf][kk][ty*4 + 64];
            float4 b0 = *(const float4*)&Bs[buf][kk][tx*4];
            float4 b1 = *(const float4*)&Bs[buf][kk][tx*4 + 64];
            float aa[2][4] = {{a0.x,a0.y,a0.z,a0.w},{a1.x,a1.y,a1.z,a1.w}};
            float bb[2][4] = {{b0.x,b0.y,b0.z,b0.w},{b1.x,b1.y,b1.z,b1.w}};
#pragma unroll
            for (int rh = 0; rh < 2; rh++)
#pragma unroll
            for (int i = 0; i < 4; i++)
#pragma unroll
            for (int ch = 0; ch < 2; ch++)
#pragma unroll
            for (int j = 0; j < 4; j++)
                acc[rh][ch][i][j] = fmaf(aa[rh][i], bb[ch][j], acc[rh][ch][i][j]);
        }
        if (c < 31) {
            int nb = buf ^ 1;
            const float* f = (const float*)&va;
#pragma unroll
            for (int j = 0; j < 4; j++) As[nb][ks+j][lr] = f[j];
            f = (const float*)&vb;
#pragma unroll
            for (int j = 0; j < 4; j++) Bs[nb][ks+j][lr] = f[j];
            __syncthreads();
            buf = nb;
        }
    }
#pragma unroll
    for (int rh = 0; rh < 2; rh++)
#pragma unroll
    for (int i = 0; i < 4; i++) {
        int m = m0 + rh*64 + ty*4 + i;
#pragma unroll
        for (int ch = 0; ch < 2; ch++) {
            int n = n0 + ch*64 + tx*4;
            float4 v;
            v.x = acc[rh][ch][i][0]; v.y = acc[rh][ch][i][1];
            v.z = acc[rh][ch][i][2]; v.w = acc[rh][ch][i][3];
            if (bias) {
                float4 bz = *(const float4*)&bias[n];
                v.x += bz.x; v.y += bz.y; v.z += bz.z; v.w += bz.w;
            }
            if (act == 1) { v.x = tanhf(v.x); v.y = tanhf(v.y); v.z = tanhf(v.z); v.w = tanhf(v.w); }
            *(float4*)&C[(size_t)m*N + n] = v;
        }
    }
}
__global__ void __launch_bounds__(256, 2)
sgemm128(const float* __restrict__ A, const float* __restrict__ Bt,
         const float* __restrict__ bias, float* __restrict__ C,
         int N, int act, int xmode) {
    sgemm_body(A, Bt, bias, C, N, act, xmode, blockIdx.x*128, blockIdx.y*128);
}
__global__ void __launch_bounds__(256, 2)
sgemm128_gx(const float* __restrict__ A,
            const float* __restrict__ BtA, const float* __restrict__ biasA, float* __restrict__ CA,
            const float* __restrict__ BtB, const float* __restrict__ biasB, float* __restrict__ CB) {
    int y = blockIdx.y;
    if (y < 6) sgemm_body(A, BtA, biasA, CA, 3*H_, 0, 0, blockIdx.x*128, y*128);
    else       sgemm_body(A, BtB, biasB, CB, 3*H_, 0, 0, blockIdx.x*128, (y-6)*128);
}

// ------------------------- persistent GRU recurrence ------------------------
// Piece-packed smem, ADAPTIVE K-chunks (KC grows as R shrinks), warp->SMSP spread.
__global__ void __launch_bounds__(512, 1)
gru_persistent(const float* __restrict__ bhh_a, const float* __restrict__ bhh_b,
               const float* __restrict__ alpha_w) {
    extern __shared__ __align__(16) unsigned char smem[];
    const int tid = threadIdx.x, lane = tid & 31, wid = tid >> 5;
    // wm = rowgroup-pair (spread across SMSPs via wid>>2), wn = column group
    const int wm = wid >> 2, wn = wid & 3;
    const int gid = blockIdx.x;
    const int gru = gid & 1, cb = (gid >> 1) & 3, q = gid >> 3;
    const uint32_t sbase = smem_u32(smem);

    // ---- one-time weight slice load (piece-packed; 16 k16-chunks of 12288B) ----
    {
        const __nv_bfloat16* Whi = g_whi[gru];
        const __nv_bfloat16* Wlo = g_wlo[gru];
        for (int u = tid; u < 12288; u += 512) {
            int nrow7 = u & 7;
            int kh = (u >> 3) & 1;
            int nh = (u >> 4) & 1;
            int ng16 = (u >> 5) % 12;
            int pc = (u >> 5) / 12;
            int p = pc & 1, c = pc >> 1;
            int Rg = (ng16 >> 2)*256 + cb*64 + (ng16 & 3)*16 + nh*8 + nrow7;
            const __nv_bfloat16* src = (p ? Wlo : Whi) + (size_t)Rg*256 + c*16 + kh*8;
            uint32_t dst = (uint32_t)(c*12288 + p*6144 + ng16*512 + nh*256 + kh*128 + nrow7*16);
            *(uint4*)(smem + dst) = *(const uint4*)src;
        }
    }
    __syncthreads();

    const uint32_t lpiece = (uint32_t)((lane >> 4)*256 + ((lane >> 3) & 1)*128 + (lane & 7)*16);
    uint32_t wboff[2][3];
#pragma unroll
    for (int p = 0; p < 2; p++)
#pragma unroll
    for (int g = 0; g < 3; g++)
        wboff[p][g] = (uint32_t)(p*6144 + (g*4 + wn)*512) + lpiece;

    const float* bhh = gru ? bhh_b : bhh_a;
    const float* gx  = gru ? g_gxb : g_gxa;
    const int g8 = lane >> 2, t2 = (lane & 3)*2;
    unsigned* mybar = &g_bar2[gru];
    const uint32_t abuf0 = sbase + SMEM_A_OFF;

#pragma unroll 1
    for (int step = 0; step < 63; step++) {
        const int par = step & 1;
        const int nch = (63 - step)*2;
        const int c0 = (q*nch)/NQ_, c1 = ((q+1)*nch)/NQ_;
        const int R = (c1 - c0)*16;
        if (R > 0) {
            const __nv_bfloat16* Hhi = g_hhi[gru][par];
            const __nv_bfloat16* Hlo = g_hlo[gru][par];
            const int rowbase = step*32 + c0*16;
            const int ng = R >> 4;
            // adaptive chunking: R*kch <= 256 (so 2 planes * R * kch*16 * 2B <= 16384)
            int kch;
            if (R <= 16) kch = 16; else if (R <= 32) kch = 8;
            else if (R <= 64) kch = 4; else kch = 2;
            const int nchunks = 16 / kch;
            const int KC = kch * 16;
            const uint32_t ks_str = (uint32_t)(ng*1024);
            const uint32_t pl_str = (uint32_t)(ng*512);

            // per-thread staging items (16B each): u = ((((s*2+p)*ng+g)*2+k8)*2+r8)*8+r7
            const int Nit = 4*R*kch;
            uint32_t sdst[2]; const __nv_bfloat16* ssrc[2]; bool sval[2];
#pragma unroll
            for (int it = 0; it < 2; it++) {
                int u = tid + it*512;
                sval[it] = (u < Nit);
                int uu = sval[it] ? u : 0;
                int r7 = uu & 7; uu >>= 3;
                int r8 = uu & 1; uu >>= 1;
                int k8 = uu & 1; uu >>= 1;
                int g  = uu % ng; uu /= ng;
                int p  = uu & 1; uu >>= 1;
                int s  = uu;
                sdst[it] = (uint32_t)(s*(int)ks_str + p*(int)pl_str + g*512 + k8*256 + r8*128 + r7*16);
                int row = rowbase + g*16 + r8*8 + r7;
                ssrc[it] = (p ? Hlo : Hhi) + (size_t)row*H_ + s*16 + k8*8;
            }

            float acc[3][2][2][4] = {};
            if (sval[0]) CP_ASYNC16(abuf0 + sdst[0], ssrc[0]);
            if (sval[1]) CP_ASYNC16(abuf0 + sdst[1], ssrc[1]);
            CP_COMMIT();
#pragma unroll 1
            for (int cc = 0; cc < nchunks; cc++) {
                CP_WAIT0();
                __syncthreads();
                if (cc + 1 < nchunks) {
                    uint32_t bb = abuf0 + (uint32_t)(((cc+1)&1)*ABUF_STRIDE);
                    int ko = (cc+1)*KC;
                    if (sval[0]) CP_ASYNC16(bb + sdst[0], ssrc[0] + ko);
                    if (sval[1]) CP_ASYNC16(bb + sdst[1], ssrc[1] + ko);
                    CP_COMMIT();
                }
                if (2*wm < ng) {
                    const bool two = (2*wm + 1 < ng);
                    const uint32_t bufb = abuf0 + (uint32_t)((cc&1)*ABUF_STRIDE);
#pragma unroll 1
                    for (int s = 0; s < kch; s++) {
                        uint32_t a0 = bufb + (uint32_t)s*ks_str + (uint32_t)((wm*2)*512) + lpiece;
                        uint32_t Ah[2][4], Al[2][4];
                        ldsm4(Ah[0], a0);
                        ldsm4(Al[0], a0 + pl_str);
                        if (two) { ldsm4(Ah[1], a0 + 512); ldsm4(Al[1], a0 + 512 + pl_str); }
                        const uint32_t wbc = sbase + (uint32_t)((cc*kch + s)*12288);
#pragma unroll
                        for (int g = 0; g < 3; g++) {
                            uint32_t Bh[4], Bl[4];
                            ldsm4(Bh, wbc + wboff[0][g]);
                            ldsm4(Bl, wbc + wboff[1][g]);
#pragma unroll
                            for (int j = 0; j < 2; j++) {
                                mma16816(acc[g][0][j], Ah[0], &Bh[j*2]);
                                mma16816(acc[g][0][j], Ah[0], &Bl[j*2]);
                                mma16816(acc[g][0][j], Al[0], &Bh[j*2]);
                            }
                            if (two) {
#pragma unroll
                                for (int j = 0; j < 2; j++) {
                                    mma16816(acc[g][1][j], Ah[1], &Bh[j*2]);
                                    mma16816(acc[g][1][j], Ah[1], &Bl[j*2]);
                                    mma16816(acc[g][1][j], Al[1], &Bh[j*2]);
                                }
                            }
                        }
                    }
                }
            }
            // ---- epilogue ----
            __nv_bfloat16* Hhi_n = g_hhi[gru][par^1];
            __nv_bfloat16* Hlo_n = g_hlo[gru][par^1];
            const size_t offk = (size_t)32*(63*step - (step*(step-1))/2);
#pragma unroll
            for (int i = 0; i < 2; i++) {
                if (2*wm + i >= ng) continue;
#pragma unroll
                for (int half = 0; half < 2; half++) {
                    int grow = rowbase + wm*32 + i*16 + g8 + half*8;
                    int gxrow = grow - step*32;
                    const float* gxr = gx + (size_t)gxrow*(3*H_);
                    size_t prow = offk + gxrow;
                    float row_part = 0.f;
#pragma unroll
                    for (int j = 0; j < 2; j++) {
                        int cc2 = cb*64 + wn*16 + j*8 + t2;
                        float2 gx_r = *(const float2*)&gxr[cc2];
                        float2 gx_z = *(const float2*)&gxr[H_ + cc2];
                        float2 gx_n = *(const float2*)&gxr[2*H_ + cc2];
                        float2 bh_r = *(const float2*)&bhh[cc2];
                        float2 bh_z = *(const float2*)&bhh[H_ + cc2];
                        float2 bh_n = *(const float2*)&bhh[2*H_ + cc2];
                        __nv_bfloat162 ho_hi = *(const __nv_bfloat162*)&Hhi[(size_t)grow*H_ + cc2];
                        __nv_bfloat162 ho_lo = *(const __nv_bfloat162*)&Hlo[(size_t)grow*H_ + cc2];
                        float hn2[2];
#pragma unroll
                        for (int u = 0; u < 2; u++) {
                            int ai = half*2 + u;
                            float rp = acc[0][i][j][ai] + (u ? bh_r.y : bh_r.x) + (u ? gx_r.y : gx_r.x);
                            float zp = acc[1][i][j][ai] + (u ? bh_z.y : bh_z.x) + (u ? gx_z.y : gx_z.x);
                            float np = acc[2][i][j][ai] + (u ? bh_n.y : bh_n.x);
                            float r = 1.f/(1.f + expf(-rp));
                            float z = 1.f/(1.f + expf(-zp));
                            float n = tanhf((u ? gx_n.y : gx_n.x) + r*np);
                            float hold = __bfloat162float(u ? ho_hi.y : ho_hi.x)
                                       + __bfloat162float(u ? ho_lo.y : ho_lo.x);
                            hn2[u] = (1.f - z)*n + z*hold;
                        }
                        __nv_bfloat162 hi2, lo2;
                        hi2.x = __float2bfloat16(hn2[0]); hi2.y = __float2bfloat16(hn2[1]);
                        lo2.x = __float2bfloat16(hn2[0] - __bfloat162float(hi2.x));
                        lo2.y = __float2bfloat16(hn2[1] - __bfloat162float(hi2.y));
                        *(__nv_bfloat162*)&Hhi_n[(size_t)grow*H_ + cc2] = hi2;
                        *(__nv_bfloat162*)&Hlo_n[(size_t)grow*H_ + cc2] = lo2;
                        if (gru == 0) {
                            float2 aw = *(const float2*)&alpha_w[cc2];
                            row_part += 0.5f*hn2[0]*aw.x + 0.5f*hn2[1]*aw.y;
                        } else {
                            float f0 = 0.5f*hn2[0], f1 = 0.5f*hn2[1];
                            __nv_bfloat162 fh, fl;
                            fh.x = __float2bfloat16(f0); fh.y = __float2bfloat16(f1);
                            fl.x = __float2bfloat16(f0 - __bfloat162float(fh.x));
                            fl.y = __float2bfloat16(f1 - __bfloat162float(fh.y));
                            *(__nv_bfloat162*)&g_fbhi[prow*H_ + cc2] = fh;
                            *(__nv_bfloat162*)&g_fblo[prow*H_ + cc2] = fl;
                        }
                    }
                    if (gru == 0) {
                        row_part += __shfl_xor_sync(0xffffffffu, row_part, 1);
                        row_part += __shfl_xor_sync(0xffffffffu, row_part, 2);
                        if ((lane & 3) == 0)
                            g_prep[prow*16 + cb*4 + wn] = row_part;
                    }
                }
            }
        }
        // ---- per-gru grid barrier (72 CTAs each) ----
        __syncthreads();
        if (tid == 0) {
            __threadfence();
            atomicAdd(mybar, 1u);
            const unsigned target = 72u*(unsigned)(step+1);
            unsigned v;
            do {
                asm volatile("ld.acquire.gpu.u32 %0, [%1];" : "=r"(v) : "l"(mybar));
            } while (v < target);
        }
        __syncthreads();
    }
}

// ------------------------- mma dense GEMM (M x 256, K=256) ------------------
__global__ void __launch_bounds__(512, 1)
dense_mma(const __nv_bfloat16* __restrict__ Ahi, const __nv_bfloat16* __restrict__ Alo,
          const __nv_bfloat16* __restrict__ Bthi, const __nv_bfloat16* __restrict__ Btlo,
          const float* __restrict__ bias, int act, float* __restrict__ outf,
          __nv_bfloat16* __restrict__ Phi, __nv_bfloat16* __restrict__ Plo) {
    extern __shared__ __align__(16) unsigned char smem[];
    const int tid = threadIdx.x, lane = tid & 31, wid = tid >> 5;
    const int wm = wid & 3, wn = wid >> 2;
    const int cb = blockIdx.y;
    const int rowbase = blockIdx.x * 128;
    const uint32_t sbase = smem_u32(smem);

    float acc[2][4][4] = {};

    const int a_r = lane & 15, a_c16 = ((lane >> 4) & 1) * 16;
    const int b_r = (lane & 7) + ((lane >> 4) & 1) * 8, b_c16 = (lane & 8) * 2;
    uint32_t aoff[3][2][2], boff[3][2][2];
#pragma unroll
    for (int bf = 0; bf < 3; bf++)
#pragma unroll
    for (int p = 0; p < 2; p++) {
#pragma unroll
        for (int i = 0; i < 2; i++)
            aoff[bf][p][i] = sbase + bf*DCHUNK + p*6144u
                           + (uint32_t)((wm*32 + i*16 + a_r)*48 + a_c16);
#pragma unroll
        for (int h2 = 0; h2 < 2; h2++)
            boff[bf][p][h2] = sbase + bf*DCHUNK + 12288u + p*6144u
                           + (uint32_t)((wn*32 + h2*16 + b_r)*48 + b_c16);
    }

    const int st_q = tid & 1, st_r = (tid >> 1) & 127, st_p = tid >> 8;
    const uint32_t stA = sbase + st_p*6144u + (uint32_t)(st_r*48 + st_q*16);
    const uint32_t stB = stA + 12288u;
    const __nv_bfloat16* srcA = (st_p ? Alo : Ahi) + (size_t)(rowbase + st_r)*256 + st_q*8;
    const __nv_bfloat16* srcB = (st_p ? Btlo : Bthi) + (size_t)(cb*128 + st_r)*256 + st_q*8;

    CP_ASYNC16(stA, srcA); CP_ASYNC16(stB, srcB); CP_COMMIT();
    CP_ASYNC16(stA + DCHUNK, srcA + 16); CP_ASYNC16(stB + DCHUNK, srcB + 16); CP_COMMIT();

    int bufi = 0;
#pragma unroll 1
    for (int c = 0; c < 16; c++) {
        if (c < 15) { CP_WAIT1(); } else { CP_WAIT0(); }
        __syncthreads();
        if (c < 14) {
            int nb = bufi + 2; if (nb >= 3) nb -= 3;
            CP_ASYNC16(stA + (uint32_t)(nb*DCHUNK), srcA + (c+2)*16);
            CP_ASYNC16(stB + (uint32_t)(nb*DCHUNK), srcB + (c+2)*16);
            CP_COMMIT();
        }
        uint32_t Ah[2][4], Al[2][4], Bh[8], Bl[8];
        ldsm4(Ah[0], aoff[bufi][0][0]); ldsm4(Ah[1], aoff[bufi][0][1]);
        ldsm4(Al[0], aoff[bufi][1][0]); ldsm4(Al[1], aoff[bufi][1][1]);
        ldsm4(Bh,   boff[bufi][0][0]); ldsm4(Bh+4, boff[bufi][0][1]);
        ldsm4(Bl,   boff[bufi][1][0]); ldsm4(Bl+4, boff[bufi][1][1]);
#pragma unroll
        for (int i = 0; i < 2; i++)
#pragma unroll
        for (int j = 0; j < 4; j++) {
            mma16816(acc[i][j], Ah[i], &Bh[j*2]);
            mma16816(acc[i][j], Ah[i], &Bl[j*2]);
            mma16816(acc[i][j], Al[i], &Bh[j*2]);
        }
        bufi++; if (bufi == 3) bufi = 0;
    }

    const int g8 = lane >> 2, t2 = (lane & 3)*2;
#pragma unroll
    for (int i = 0; i < 2; i++)
#pragma unroll
    for (int half = 0; half < 2; half++) {
        int grow = rowbase + wm*32 + i*16 + g8 + half*8;
#pragma unroll
        for (int j = 0; j < 4; j++) {
            int cc = cb*128 + wn*32 + j*8 + t2;
            float v0 = acc[i][j][half*2 + 0];
            float v1 = acc[i][j][half*2 + 1];
            if (bias) { v0 += bias[cc]; v1 += bias[cc+1]; }
            if (act == 1) { v0 = tanhf(v0); v1 = tanhf(v1); }
            float2 f2; f2.x = v0; f2.y = v1;
            *(float2*)&outf[(size_t)grow*E_ + cc] = f2;
            if (Phi) {
                __nv_bfloat162 hi2, lo2;
                hi2.x = __float2bfloat16(v0); hi2.y = __float2bfloat16(v1);
                lo2.x = __float2bfloat16(v0 - __bfloat162float(hi2.x));
                lo2.y = __float2bfloat16(v1 - __bfloat162float(hi2.y));
                *(__nv_bfloat162*)&Phi[(size_t)grow*E_ + cc] = hi2;
                *(__nv_bfloat162*)&Plo[(size_t)grow*E_ + cc] = lo2;
            }
        }
    }
}

// ------------------------- alpha (pre-partial sum + softmax) ----------------
__global__ void alpha_kernel(const float* __restrict__ alpha_b) {
    int gw = (blockIdx.x*blockDim.x + threadIdx.x) >> 5;
    int lane = threadIdx.x & 31;
    if (gw >= PB_) return;
    int p = gw >> 5, b = gw & 31;
    float ab = alpha_b[0];
    float v0 = -1e30f, v1 = -1e30f;
    {
        int t = lane;
        if (t <= p) {
            int kk = p - t;
            int offk = 32*(63*kk - (kk*(kk-1))/2);
            size_t prow = (size_t)offk + t*32 + b;
            const float4* qq = (const float4*)&g_prep[prow*16];
            float4 s0 = qq[0], s1 = qq[1], s2 = qq[2], s3 = qq[3];
            v0 = (s0.x+s0.y+s0.z+s0.w) + (s1.x+s1.y+s1.z+s1.w)
               + (s2.x+s2.y+s2.z+s2.w) + (s3.x+s3.y+s3.z+s3.w) + ab;
        }
    }
    {
        int t = lane + 32;
        if (t <= p) {
            int kk = p - t;
            int offk = 32*(63*kk - (kk*(kk-1))/2);
            size_t prow = (size_t)offk + t*32 + b;
            const float4* qq = (const float4*)&g_prep[prow*16];
            float4 s0 = qq[0], s1 = qq[1], s2 = qq[2], s3 = qq[3];
            v1 = (s0.x+s0.y+s0.z+s0.w) + (s1.x+s1.y+s1.z+s1.w)
               + (s2.x+s2.y+s2.z+s2.w) + (s3.x+s3.y+s3.z+s3.w) + ab;
        }
    }
    float m = fmaxf(v0, v1);
#pragma unroll
    for (int o=16;o;o>>=1) m = fmaxf(m, __shfl_xor_sync(0xffffffffu, m, o));
    float e0 = (lane      <= p) ? expf(v0-m) : 0.f;
    float e1 = (lane + 32 <= p) ? expf(v1-m) : 0.f;
    float s = e0 + e1;
#pragma unroll
    for (int o=16;o;o>>=1) s += __shfl_xor_sync(0xffffffffu, s, o);
    float inv = 1.f/s;
    g_alpha[(p*T_+lane   )*B_+b] = e0*inv;
    g_alpha[(p*T_+lane+32)*B_+b] = e1*inv;
}

__global__ void reduce_kernel(const float* __restrict__ x,
                              const float* __restrict__ out_w,
                              const float* __restrict__ out_b,
                              float* __restrict__ out) {
    int pb = blockIdx.x;
    int p = 62 - (pb >> 5);
    int b = pb & 31;
    int e = threadIdx.x;
    float cc = 0.f, gg = 0.f;
    for (int t = 0; t <= p; t++) {
        float a = g_alpha[(p*T_+t)*B_+b];
        int kk = p - t;
        int offk = 32*(63*kk - (kk*(kk-1))/2);
        size_t prow = (size_t)offk + t*32 + b;
        cc += a * g_beta [prow*E_ + e] * g_emb[((size_t)(t*B_+b))*E_ + e];
        gg += a * g_ebeta[prow*E_ + e] * x[((size_t)b*T_ + t)*E_ + e];
    }
    out[B_*P_ + ((size_t)(b*P_+p))*E_ + e] = gg / (float)(p+1);
    __shared__ float red[256];
    red[e] = cc * out_w[e];
    __syncthreads();
    for (int s2=128; s2; s2>>=1) { if (e < s2) red[e] += red[e+s2]; __syncthreads(); }
    if (e == 0) out[b*P_ + p] = red[0] + out_b[0];
}

// ------------------------- launch -------------------------------------------
extern "C" void kernel_launch(void* const* d_in, const int* in_sizes, int n_in,
                              void* d_out, int out_size) {
    (void)in_sizes; (void)n_in; (void)out_size;
    const float* x       = (const float*)d_in[0];
    const float* emb_w   = (const float*)d_in[1];
    const float* emb_b   = (const float*)d_in[2];
    const float* a_wih   = (const float*)d_in[3];
    const float* a_whh   = (const float*)d_in[4];
    const float* a_bih   = (const float*)d_in[5];
    const float* a_bhh   = (const float*)d_in[6];
    const float* b_wih   = (const float*)d_in[7];
    const float* b_whh   = (const float*)d_in[8];
    const float* b_bih   = (const float*)d_in[9];
    const float* b_bhh   = (const float*)d_in[10];
    const float* alpha_w = (const float*)d_in[11];
    const float* alpha_b = (const float*)d_in[12];
    const float* beta_w  = (const float*)d_in[13];
    const float* beta_b  = (const float*)d_in[14];
    const float* out_w   = (const float*)d_in[15];
    const float* out_b   = (const float*)d_in[16];
    float* out = (float*)d_out;

    cudaFuncSetAttribute(gru_persistent, cudaFuncAttributeMaxDynamicSharedMemorySize, SMEM_TOTAL_PERS);
    cudaFuncSetAttribute(dense_mma,      cudaFuncAttributeMaxDynamicSharedMemorySize, SMEM_TOTAL_DENSE);

    float *p_emb=0, *p_gxa=0, *p_gxb=0, *p_beta=0, *p_ebeta=0;
    __nv_bfloat16 *p_fbhi=0, *p_fblo=0, *p_bwhi=0, *p_bwlo=0;
    __nv_bfloat16 *p_mthi=0, *p_mtlo=0, *p_bhi=0, *p_blo=0;
    cudaGetSymbolAddress((void**)&p_emb,   g_emb);
    cudaGetSymbolAddress((void**)&p_gxa,   g_gxa);
    cudaGetSymbolAddress((void**)&p_gxb,   g_gxb);
    cudaGetSymbolAddress((void**)&p_beta,  g_beta);
    cudaGetSymbolAddress((void**)&p_ebeta, g_ebeta);
    cudaGetSymbolAddress((void**)&p_fbhi,  g_fbhi);
    cudaGetSymbolAddress((void**)&p_fblo,  g_fblo);
    cudaGetSymbolAddress((void**)&p_bwhi,  g_bwhi);
    cudaGetSymbolAddress((void**)&p_bwlo,  g_bwlo);
    cudaGetSymbolAddress((void**)&p_mthi,  g_mthi);
    cudaGetSymbolAddress((void**)&p_mtlo,  g_mtlo);
    cudaGetSymbolAddress((void**)&p_bhi,   g_betahi);
    cudaGetSymbolAddress((void**)&p_blo,   g_betalo);

    zero_planes_kernel<<<(2*2*PB_*H_/2 + 255)/256, 256>>>();
    prep_w_kernel<<<(2*768*256)/256, 256>>>(a_whh, b_whh);
    prep_bw_kernel<<<256, 256>>>(beta_w);
    prep_mt_kernel<<<256, 256>>>(emb_w, out_w);

    sgemm128<<<dim3((T_*B_)/128, E_/128), 256>>>(x, emb_w, emb_b, p_emb, E_, 0, 1);
    sgemm128_gx<<<dim3((T_*B_)/128, 12), 256>>>(p_emb, a_wih, a_bih, p_gxa,
                                                b_wih, b_bih, p_gxb);

    gru_persistent<<<NCTA_PERS, 512, SMEM_TOTAL_PERS>>>(a_bhh, b_bhh, alpha_w);

    alpha_kernel<<<(PB_*32 + 255)/256, 256>>>(alpha_b);

    dense_mma<<<dim3(NPACK_/128, 2), 512, SMEM_TOTAL_DENSE>>>(
        p_fbhi, p_fblo, p_bwhi, p_bwlo, beta_b, 1, p_beta, p_bhi, p_blo);
    dense_mma<<<dim3(NPACK_/128, 2), 512, SMEM_TOTAL_DENSE>>>(
        p_bhi, p_blo, p_mthi, p_mtlo, (const float*)0, 0, p_ebeta,
        (__nv_bfloat16*)0, (__nv_bfloat16*)0);

    reduce_kernel<<<PB_, 256>>>(x, out_w, out_b, out);
}

// round 13
// speedup vs baseline: 1.2924x; 1.0108x over previous
#include <cuda_runtime.h>
#include <cuda_bf16.h>
#include <math.h>
#include <stdint.h>

#define B_ 32
#define T_ 64
#define E_ 256
#define H_ 256
#define P_ 63
#define PB_ 2016
#define NPACK_ 64512

#define NCTA_PERS 144
#define NQ_ 18
#define SMEM_A_OFF   196608            // A buffers after 16 chunks * 12288B weights
#define ABUF_STRIDE  16384             // adaptive chunk buffer
#define SMEM_TOTAL_PERS (196608 + 2*ABUF_STRIDE)   // 229376

#define DCHUNK 24576                   // dense: A(12288)+B(12288) per buffer
#define SMEM_TOTAL_DENSE (3*DCHUNK)    // 73728

// ------------------------- scratch (device globals) -------------------------
__device__ float g_emb[T_*B_*E_];
__device__ float g_gxa[T_*B_*3*H_];
__device__ float g_gxb[T_*B_*3*H_];
__device__ __nv_bfloat16 g_hhi[2][2][PB_*H_];   // [gru][parity]
__device__ __nv_bfloat16 g_hlo[2][2][PB_*H_];
__device__ __nv_bfloat16 g_whi[2][3*H_*H_];
__device__ __nv_bfloat16 g_wlo[2][3*H_*H_];
__device__ __nv_bfloat16 g_bwhi[E_*H_];
__device__ __nv_bfloat16 g_bwlo[E_*H_];
__device__ __nv_bfloat16 g_mthi[E_*E_];
__device__ __nv_bfloat16 g_mtlo[E_*E_];
__device__ float g_prep[(size_t)NPACK_*16];     // pre partials [prow][cb*4+wn]
__device__ __nv_bfloat16 g_fbhi[(size_t)NPACK_*H_];
__device__ __nv_bfloat16 g_fblo[(size_t)NPACK_*H_];
__device__ float g_beta[(size_t)NPACK_*E_];
__device__ __nv_bfloat16 g_betahi[(size_t)NPACK_*E_];
__device__ __nv_bfloat16 g_betalo[(size_t)NPACK_*E_];
__device__ float g_ebeta[(size_t)NPACK_*E_];
__device__ float g_alpha[P_*T_*B_];
__device__ unsigned g_bars[36*32];              // one counter per (gru,q), 128B apart

// ------------------------- helpers ------------------------------------------
__device__ __forceinline__ uint32_t smem_u32(const void* p) {
    uint32_t a;
    asm("{ .reg .u64 t; cvta.to.shared.u64 t, %1; cvt.u32.u64 %0, t; }" : "=r"(a) : "l"(p));
    return a;
}
__device__ __forceinline__ void ldsm4(uint32_t* r, uint32_t addr) {
    asm volatile("ldmatrix.sync.aligned.m8n8.x4.shared.b16 {%0,%1,%2,%3}, [%4];"
        : "=r"(r[0]), "=r"(r[1]), "=r"(r[2]), "=r"(r[3]) : "r"(addr));
}
__device__ __forceinline__ void mma16816(float* d, const uint32_t* a, const uint32_t* b) {
    asm volatile("mma.sync.aligned.m16n8k16.row.col.f32.bf16.bf16.f32 "
        "{%0,%1,%2,%3}, {%4,%5,%6,%7}, {%8,%9}, {%0,%1,%2,%3};"
        : "+f"(d[0]), "+f"(d[1]), "+f"(d[2]), "+f"(d[3])
        : "r"(a[0]), "r"(a[1]), "r"(a[2]), "r"(a[3]), "r"(b[0]), "r"(b[1]));
}
#define CP_ASYNC16(dst, src) \
    asm volatile("cp.async.cg.shared.global [%0], [%1], 16;" :: "r"(dst), "l"(src))
#define CP_COMMIT() asm volatile("cp.async.commit_group;")
#define CP_WAIT1()  asm volatile("cp.async.wait_group 1;")
#define CP_WAIT0()  asm volatile("cp.async.wait_group 0;")

// ------------------------- prep kernels -------------------------------------
__global__ void zero_planes_kernel() {
    int i = blockIdx.x*256 + threadIdx.x;
    uint32_t* a = (uint32_t*)g_hhi;
    uint32_t* b = (uint32_t*)g_hlo;
    if (i < 2*2*PB_*H_/2) { a[i] = 0u; b[i] = 0u; }
    if (i < 36*32) g_bars[i] = 0u;
}
__global__ void prep_w_kernel(const float* __restrict__ wa, const float* __restrict__ wb) {
    int idx = blockIdx.x*256 + threadIdx.x;
    int k = idx & 255;
    int r = (idx >> 8) % 768;
    int gru = idx / (768*256);
    float v = (gru ? wb : wa)[r*256 + k];
    __nv_bfloat16 hi = __float2bfloat16(v);
    g_whi[gru][r*256 + k] = hi;
    g_wlo[gru][r*256 + k] = __float2bfloat16(v - __bfloat162float(hi));
}
__global__ void prep_bw_kernel(const float* __restrict__ bw) {
    int idx = blockIdx.x*256 + threadIdx.x;
    float v = bw[idx];
    __nv_bfloat16 hi = __float2bfloat16(v);
    g_bwhi[idx] = hi;
    g_bwlo[idx] = __float2bfloat16(v - __bfloat162float(hi));
}
__global__ void prep_mt_kernel(const float* __restrict__ emb_w, const float* __restrict__ out_w) {
    int idx = blockIdx.x*256 + threadIdx.x;
    int i = idx >> 8, e = idx & 255;
    float v = out_w[e] * emb_w[e*256 + i];
    __nv_bfloat16 hi = __float2bfloat16(v);
    g_mthi[idx] = hi;
    g_mtlo[idx] = __float2bfloat16(v - __bfloat162float(hi));
}

// ------------------------- fp32 SGEMM (emb / gx) ----------------------------
__device__ __forceinline__ const float* arow_ptr(const float* A, int m, int xmode) {
    if (xmode) { int t = m >> 5, b = m & 31; return A + ((size_t)b*T_ + t)*E_; }
    return A + (size_t)m*E_;
}
__device__ __forceinline__ void sgemm_body(
        const float* A, const float* Bt, const float* bias, float* C,
        int N, int act, int xmode, int m0, int n0) {
    __shared__ float As[2][8][128];
    __shared__ float Bs[2][8][128];
    const int tid = threadIdx.x;
    const int tx = tid & 15, ty = tid >> 4;
    const int lr = tid >> 1;
    const int ks = (tid & 1) * 4;
    const float* pA = arow_ptr(A, m0 + lr, xmode) + ks;
    const float* pB = Bt + (size_t)(n0 + lr) * 256 + ks;
    float acc[2][2][4][4] = {};
    float4 va = *(const float4*)pA;
    float4 vb = *(const float4*)pB;
    {
        const float* f = (const float*)&va;
#pragma unroll
        for (int j = 0; j < 4; j++) As[0][ks+j][lr] = f[j];
        f = (const float*)&vb;
#pragma unroll
        for (int j = 0; j < 4; j++) Bs[0][ks+j][lr] = f[j];
    }
    __syncthreads();
    int buf = 0;
#pragma unroll 1
    for (int c = 0; c < 32; c++) {
        if (c < 31) {
            int off = (c+1)*8;
            va = *(const float4*)(pA + off);
            vb = *(const float4*)(pB + off);
        }
#pragma unroll
        for (int kk = 0; kk < 8; kk++) {
            float4 a0 = *(const float4*)&As[buf][kk][ty*4];
            float4 a1 = *(const float4*)&As[buf][kk][ty*4 + 64];
            float4 b0 = *(const float4*)&Bs[buf][kk][tx*4];
            float4 b1 = *(const float4*)&Bs[buf][kk][tx*4 + 64];
            float aa[2][4] = {{a0.x,a0.y,a0.z,a0.w},{a1.x,a1.y,a1.z,a1.w}};
            float bb[2][4] = {{b0.x,b0.y,b0.z,b0.w},{b1.x,b1.y,b1.z,b1.w}};
#pragma unroll
            for (int rh = 0; rh < 2; rh++)
#pragma unroll
            for (int i = 0; i < 4; i++)
#pragma unroll
            for (int ch = 0; ch < 2; ch++)
#pragma unroll
            for (int j = 0; j < 4; j++)
                acc[rh][ch][i][j] = fmaf(aa[rh][i], bb[ch][j], acc[rh][ch][i][j]);
        }
        if (c < 31) {
            int nb = buf ^ 1;
            const float* f = (const float*)&va;
#pragma unroll
            for (int j = 0; j < 4; j++) As[nb][ks+j][lr] = f[j];
            f = (const float*)&vb;
#pragma unroll
            for (int j = 0; j < 4; j++) Bs[nb][ks+j][lr] = f[j];
            __syncthreads();
            buf = nb;
        }
    }
#pragma unroll
    for (int rh = 0; rh < 2; rh++)
#pragma unroll
    for (int i = 0; i < 4; i++) {
        int m = m0 + rh*64 + ty*4 + i;
#pragma unroll
        for (int ch = 0; ch < 2; ch++) {
            int n = n0 + ch*64 + tx*4;
            float4 v;
            v.x = acc[rh][ch][i][0]; v.y = acc[rh][ch][i][1];
            v.z = acc[rh][ch][i][2]; v.w = acc[rh][ch][i][3];
            if (bias) {
                float4 bz = *(const float4*)&bias[n];
                v.x += bz.x; v.y += bz.y; v.z += bz.z; v.w += bz.w;
            }
            if (act == 1) { v.x = tanhf(v.x); v.y = tanhf(v.y); v.z = tanhf(v.z); v.w = tanhf(v.w); }
            *(float4*)&C[(size_t)m*N + n] = v;
        }
    }
}
__global__ void __launch_bounds__(256, 2)
sgemm128(const float* __restrict__ A, const float* __restrict__ Bt,
         const float* __restrict__ bias, float* __restrict__ C,
         int N, int act, int xmode) {
    sgemm_body(A, Bt, bias, C, N, act, xmode, blockIdx.x*128, blockIdx.y*128);
}
__global__ void __launch_bounds__(256, 2)
sgemm128_gx(const float* __restrict__ A,
            const float* __restrict__ BtA, const float* __restrict__ biasA, float* __restrict__ CA,
            const float* __restrict__ BtB, const float* __restrict__ biasB, float* __restrict__ CB) {
    int y = blockIdx.y;
    if (y < 6) sgemm_body(A, BtA, biasA, CA, 3*H_, 0, 0, blockIdx.x*128, y*128);
    else       sgemm_body(A, BtB, biasB, CB, 3*H_, 0, 0, blockIdx.x*128, (y-6)*128);
}

// ------------------------- persistent GRU recurrence ------------------------
// Identity-stable chunk ownership (chunk c -> q = c mod 18) => only the 4
// column-block CTAs of a (gru,q) group depend on each other per step.
// Per-group 4-CTA barrier; groups drift independently; CTAs retire early.
__global__ void __launch_bounds__(512, 1)
gru_persistent(const float* __restrict__ bhh_a, const float* __restrict__ bhh_b,
               const float* __restrict__ alpha_w) {
    extern __shared__ __align__(16) unsigned char smem[];
    const int tid = threadIdx.x, lane = tid & 31, wid = tid >> 5;
    const int wm = wid >> 2, wn = wid & 3;   // wm spread across SMSPs
    const int gid = blockIdx.x;
    const int gru = gid & 1, cb = (gid >> 1) & 3, q = gid >> 3;
    const uint32_t sbase = smem_u32(smem);

    // ---- one-time weight slice load (piece-packed; 16 k16-chunks of 12288B) ----
    {
        const __nv_bfloat16* Whi = g_whi[gru];
        const __nv_bfloat16* Wlo = g_wlo[gru];
        for (int u = tid; u < 12288; u += 512) {
            int nrow7 = u & 7;
            int kh = (u >> 3) & 1;
            int nh = (u >> 4) & 1;
            int ng16 = (u >> 5) % 12;
            int pc = (u >> 5) / 12;
            int p = pc & 1, c = pc >> 1;
            int Rg = (ng16 >> 2)*256 + cb*64 + (ng16 & 3)*16 + nh*8 + nrow7;
            const __nv_bfloat16* src = (p ? Wlo : Whi) + (size_t)Rg*256 + c*16 + kh*8;
            uint32_t dst = (uint32_t)(c*12288 + p*6144 + ng16*512 + nh*256 + kh*128 + nrow7*16);
            *(uint4*)(smem + dst) = *(const uint4*)src;
        }
    }
    __syncthreads();

    const uint32_t lpiece = (uint32_t)((lane >> 4)*256 + ((lane >> 3) & 1)*128 + (lane & 7)*16);
    uint32_t wboff[2][3];
#pragma unroll
    for (int p = 0; p < 2; p++)
#pragma unroll
    for (int g = 0; g < 3; g++)
        wboff[p][g] = (uint32_t)(p*6144 + (g*4 + wn)*512) + lpiece;

    const float* bhh = gru ? bhh_b : bhh_a;
    const float* gx  = gru ? g_gxb : g_gxa;
    const int g8 = lane >> 2, t2 = (lane & 3)*2;
    unsigned* mybar = &g_bars[(gru*18 + q)*32];
    const uint32_t abuf0 = sbase + SMEM_A_OFF;

#pragma unroll 1
    for (int step = 0; step < 63; step++) {
        const int par = step & 1;
        const int a2 = 2*step;                 // first active chunk id
        int d = q - (a2 % 18); if (d < 0) d += 18;
        const int cfirst = a2 + d;
        if (cfirst >= 126) break;              // this group is done forever
        const int ng = 1 + (126 - cfirst - 1)/18;
        const int R = ng*16;
        {
            const __nv_bfloat16* Hhi = g_hhi[gru][par];
            const __nv_bfloat16* Hlo = g_hlo[gru][par];
            // adaptive chunking: R*kch <= 256
            int kch;
            if (R <= 16) kch = 16; else if (R <= 32) kch = 8;
            else if (R <= 64) kch = 4; else kch = 2;
            const int nchunks = 16 / kch;
            const int KC = kch * 16;
            const uint32_t ks_str = (uint32_t)(ng*1024);
            const uint32_t pl_str = (uint32_t)(ng*512);

            const int Nit = 4*R*kch;
            uint32_t sdst[2]; const __nv_bfloat16* ssrc[2]; bool sval[2];
#pragma unroll
            for (int it = 0; it < 2; it++) {
                int u = tid + it*512;
                sval[it] = (u < Nit);
                int uu = sval[it] ? u : 0;
                int r7 = uu & 7; uu >>= 3;
                int r8 = uu & 1; uu >>= 1;
                int k8 = uu & 1; uu >>= 1;
                int g  = uu % ng; uu /= ng;
                int p  = uu & 1; uu >>= 1;
                int s  = uu;
                sdst[it] = (uint32_t)(s*(int)ks_str + p*(int)pl_str + g*512 + k8*256 + r8*128 + r7*16);
                int row = (cfirst + g*18)*16 + r8*8 + r7;
                ssrc[it] = (p ? Hlo : Hhi) + (size_t)row*H_ + s*16 + k8*8;
            }

            float acc[3][2][2][4] = {};
            if (sval[0]) CP_ASYNC16(abuf0 + sdst[0], ssrc[0]);
            if (sval[1]) CP_ASYNC16(abuf0 + sdst[1], ssrc[1]);
            CP_COMMIT();
#pragma unroll 1
            for (int cc = 0; cc < nchunks; cc++) {
                CP_WAIT0();
                __syncthreads();
                if (cc + 1 < nchunks) {
                    uint32_t bb = abuf0 + (uint32_t)(((cc+1)&1)*ABUF_STRIDE);
                    int ko = (cc+1)*KC;
                    if (sval[0]) CP_ASYNC16(bb + sdst[0], ssrc[0] + ko);
                    if (sval[1]) CP_ASYNC16(bb + sdst[1], ssrc[1] + ko);
                    CP_COMMIT();
                }
                if (2*wm < ng) {
                    const bool two = (2*wm + 1 < ng);
                    const uint32_t bufb = abuf0 + (uint32_t)((cc&1)*ABUF_STRIDE);
#pragma unroll 1
                    for (int s = 0; s < kch; s++) {
                        uint32_t a0 = bufb + (uint32_t)s*ks_str + (uint32_t)((wm*2)*512) + lpiece;
                        uint32_t Ah[2][4], Al[2][4];
                        ldsm4(Ah[0], a0);
                        ldsm4(Al[0], a0 + pl_str);
                        if (two) { ldsm4(Ah[1], a0 + 512); ldsm4(Al[1], a0 + 512 + pl_str); }
                        const uint32_t wbc = sbase + (uint32_t)((cc*kch + s)*12288);
#pragma unroll
                        for (int g = 0; g < 3; g++) {
                            uint32_t Bh[4], Bl[4];
                            ldsm4(Bh, wbc + wboff[0][g]);
                            ldsm4(Bl, wbc + wboff[1][g]);
#pragma unroll
                            for (int j = 0; j < 2; j++) {
                                mma16816(acc[g][0][j], Ah[0], &Bh[j*2]);
                                mma16816(acc[g][0][j], Ah[0], &Bl[j*2]);
                                mma16816(acc[g][0][j], Al[0], &Bh[j*2]);
                            }
                            if (two) {
#pragma unroll
                                for (int j = 0; j < 2; j++) {
                                    mma16816(acc[g][1][j], Ah[1], &Bh[j*2]);
                                    mma16816(acc[g][1][j], Ah[1], &Bl[j*2]);
                                    mma16816(acc[g][1][j], Al[1], &Bh[j*2]);
                                }
                            }
                        }
                    }
                }
            }
            // ---- epilogue ----
            __nv_bfloat16* Hhi_n = g_hhi[gru][par^1];
            __nv_bfloat16* Hlo_n = g_hlo[gru][par^1];
            const size_t offk = (size_t)32*(63*step - (step*(step-1))/2);
#pragma unroll
            for (int i = 0; i < 2; i++) {
                if (2*wm + i >= ng) continue;
#pragma unroll
                for (int half = 0; half < 2; half++) {
                    int grow = (cfirst + (2*wm + i)*18)*16 + g8 + half*8;
                    int gxrow = grow - step*32;
                    const float* gxr = gx + (size_t)gxrow*(3*H_);
                    size_t prow = offk + gxrow;
                    float row_part = 0.f;
#pragma unroll
                    for (int j = 0; j < 2; j++) {
                        int cc2 = cb*64 + wn*16 + j*8 + t2;
                        float2 gx_r = *(const float2*)&gxr[cc2];
                        float2 gx_z = *(const float2*)&gxr[H_ + cc2];
                        float2 gx_n = *(const float2*)&gxr[2*H_ + cc2];
                        float2 bh_r = *(const float2*)&bhh[cc2];
                        float2 bh_z = *(const float2*)&bhh[H_ + cc2];
                        float2 bh_n = *(const float2*)&bhh[2*H_ + cc2];
                        __nv_bfloat162 ho_hi = *(const __nv_bfloat162*)&Hhi[(size_t)grow*H_ + cc2];
                        __nv_bfloat162 ho_lo = *(const __nv_bfloat162*)&Hlo[(size_t)grow*H_ + cc2];
                        float hn2[2];
#pragma unroll
                        for (int u = 0; u < 2; u++) {
                            int ai = half*2 + u;
                            float rp = acc[0][i][j][ai] + (u ? bh_r.y : bh_r.x) + (u ? gx_r.y : gx_r.x);
                            float zp = acc[1][i][j][ai] + (u ? bh_z.y : bh_z.x) + (u ? gx_z.y : gx_z.x);
                            float np = acc[2][i][j][ai] + (u ? bh_n.y : bh_n.x);
                            float r = 1.f/(1.f + expf(-rp));
                            float z = 1.f/(1.f + expf(-zp));
                            float n = tanhf((u ? gx_n.y : gx_n.x) + r*np);
                            float hold = __bfloat162float(u ? ho_hi.y : ho_hi.x)
                                       + __bfloat162float(u ? ho_lo.y : ho_lo.x);
                            hn2[u] = (1.f - z)*n + z*hold;
                        }
                        __nv_bfloat162 hi2, lo2;
                        hi2.x = __float2bfloat16(hn2[0]); hi2.y = __float2bfloat16(hn2[1]);
                        lo2.x = __float2bfloat16(hn2[0] - __bfloat162float(hi2.x));
                        lo2.y = __float2bfloat16(hn2[1] - __bfloat162float(hi2.y));
                        *(__nv_bfloat162*)&Hhi_n[(size_t)grow*H_ + cc2] = hi2;
                        *(__nv_bfloat162*)&Hlo_n[(size_t)grow*H_ + cc2] = lo2;
                        if (gru == 0) {
                            float2 aw = *(const float2*)&alpha_w[cc2];
                            row_part += 0.5f*hn2[0]*aw.x + 0.5f*hn2[1]*aw.y;
                        } else {
                            float f0 = 0.5f*hn2[0], f1 = 0.5f*hn2[1];
                            __nv_bfloat162 fh, fl;
                            fh.x = __float2bfloat16(f0); fh.y = __float2bfloat16(f1);
                            fl.x = __float2bfloat16(f0 - __bfloat162float(fh.x));
                            fl.y = __float2bfloat16(f1 - __bfloat162float(fh.y));
                            *(__nv_bfloat162*)&g_fbhi[prow*H_ + cc2] = fh;
                            *(__nv_bfloat162*)&g_fblo[prow*H_ + cc2] = fl;
                        }
                    }
                    if (gru == 0) {
                        row_part += __shfl_xor_sync(0xffffffffu, row_part, 1);
                        row_part += __shfl_xor_sync(0xffffffffu, row_part, 2);
                        if ((lane & 3) == 0)
                            g_prep[prow*16 + cb*4 + wn] = row_part;
                    }
                }
            }
        }
        // ---- 4-CTA group barrier (gru, q) ----
        __syncthreads();
        if (tid == 0) {
            __threadfence();
            atomicAdd(mybar, 1u);
            const unsigned target = 4u*(unsigned)(step+1);
            unsigned v;
            do {
                asm volatile("ld.acquire.gpu.u32 %0, [%1];" : "=r"(v) : "l"(mybar));
            } while (v < target);
        }
        __syncthreads();
    }
}

// ------------------------- mma dense GEMM (M x 256, K=256) ------------------
__global__ void __launch_bounds__(512, 1)
dense_mma(const __nv_bfloat16* __restrict__ Ahi, const __nv_bfloat16* __restrict__ Alo,
          const __nv_bfloat16* __restrict__ Bthi, const __nv_bfloat16* __restrict__ Btlo,
          const float* __restrict__ bias, int act, float* __restrict__ outf,
          __nv_bfloat16* __restrict__ Phi, __nv_bfloat16* __restrict__ Plo) {
    extern __shared__ __align__(16) unsigned char smem[];
    const int tid = threadIdx.x, lane = tid & 31, wid = tid >> 5;
    const int wm = wid & 3, wn = wid >> 2;
    const int cb = blockIdx.y;
    const int rowbase = blockIdx.x * 128;
    const uint32_t sbase = smem_u32(smem);

    float acc[2][4][4] = {};

    const int a_r = lane & 15, a_c16 = ((lane >> 4) & 1) * 16;
    const int b_r = (lane & 7) + ((lane >> 4) & 1) * 8, b_c16 = (lane & 8) * 2;
    uint32_t aoff[3][2][2], boff[3][2][2];
#pragma unroll
    for (int bf = 0; bf < 3; bf++)
#pragma unroll
    for (int p = 0; p < 2; p++) {
#pragma unroll
        for (int i = 0; i < 2; i++)
            aoff[bf][p][i] = sbase + bf*DCHUNK + p*6144u
                           + (uint32_t)((wm*32 + i*16 + a_r)*48 + a_c16);
#pragma unroll
        for (int h2 = 0; h2 < 2; h2++)
            boff[bf][p][h2] = sbase + bf*DCHUNK + 12288u + p*6144u
                           + (uint32_t)((wn*32 + h2*16 + b_r)*48 + b_c16);
    }

    const int st_q = tid & 1, st_r = (tid >> 1) & 127, st_p = tid >> 8;
    const uint32_t stA = sbase + st_p*6144u + (uint32_t)(st_r*48 + st_q*16);
    const uint32_t stB = stA + 12288u;
    const __nv_bfloat16* srcA = (st_p ? Alo : Ahi) + (size_t)(rowbase + st_r)*256 + st_q*8;
    const __nv_bfloat16* srcB = (st_p ? Btlo : Bthi) + (size_t)(cb*128 + st_r)*256 + st_q*8;

    CP_ASYNC16(stA, srcA); CP_ASYNC16(stB, srcB); CP_COMMIT();
    CP_ASYNC16(stA + DCHUNK, srcA + 16); CP_ASYNC16(stB + DCHUNK, srcB + 16); CP_COMMIT();

    int bufi = 0;
#pragma unroll 1
    for (int c = 0; c < 16; c++) {
        if (c < 15) { CP_WAIT1(); } else { CP_WAIT0(); }
        __syncthreads();
        if (c < 14) {
            int nb = bufi + 2; if (nb >= 3) nb -= 3;
            CP_ASYNC16(stA + (uint32_t)(nb*DCHUNK), srcA + (c+2)*16);
            CP_ASYNC16(stB + (uint32_t)(nb*DCHUNK), srcB + (c+2)*16);
            CP_COMMIT();
        }
        uint32_t Ah[2][4], Al[2][4], Bh[8], Bl[8];
        ldsm4(Ah[0], aoff[bufi][0][0]); ldsm4(Ah[1], aoff[bufi][0][1]);
        ldsm4(Al[0], aoff[bufi][1][0]); ldsm4(Al[1], aoff[bufi][1][1]);
        ldsm4(Bh,   boff[bufi][0][0]); ldsm4(Bh+4, boff[bufi][0][1]);
        ldsm4(Bl,   boff[bufi][1][0]); ldsm4(Bl+4, boff[bufi][1][1]);
#pragma unroll
        for (int i = 0; i < 2; i++)
#pragma unroll
        for (int j = 0; j < 4; j++) {
            mma16816(acc[i][j], Ah[i], &Bh[j*2]);
            mma16816(acc[i][j], Ah[i], &Bl[j*2]);
            mma16816(acc[i][j], Al[i], &Bh[j*2]);
        }
        bufi++; if (bufi == 3) bufi = 0;
    }

    const int g8 = lane >> 2, t2 = (lane & 3)*2;
#pragma unroll
    for (int i = 0; i < 2; i++)
#pragma unroll
    for (int half = 0; half < 2; half++) {
        int grow = rowbase + wm*32 + i*16 + g8 + half*8;
#pragma unroll
        for (int j = 0; j < 4; j++) {
            int cc = cb*128 + wn*32 + j*8 + t2;
            float v0 = acc[i][j][half*2 + 0];
            float v1 = acc[i][j][half*2 + 1];
            if (bias) { v0 += bias[cc]; v1 += bias[cc+1]; }
            if (act == 1) { v0 = tanhf(v0); v1 = tanhf(v1); }
            float2 f2; f2.x = v0; f2.y = v1;
            *(float2*)&outf[(size_t)grow*E_ + cc] = f2;
            if (Phi) {
                __nv_bfloat162 hi2, lo2;
                hi2.x = __float2bfloat16(v0); hi2.y = __float2bfloat16(v1);
                lo2.x = __float2bfloat16(v0 - __bfloat162float(hi2.x));
                lo2.y = __float2bfloat16(v1 - __bfloat162float(hi2.y));
                *(__nv_bfloat162*)&Phi[(size_t)grow*E_ + cc] = hi2;
                *(__nv_bfloat162*)&Plo[(size_t)grow*E_ + cc] = lo2;
            }
        }
    }
}

// ------------------------- alpha (pre-partial sum + softmax) ----------------
__global__ void alpha_kernel(const float* __restrict__ alpha_b) {
    int gw = (blockIdx.x*blockDim.x + threadIdx.x) >> 5;
    int lane = threadIdx.x & 31;
    if (gw >= PB_) return;
    int p = gw >> 5, b = gw & 31;
    float ab = alpha_b[0];
    float v0 = -1e30f, v1 = -1e30f;
    {
        int t = lane;
        if (t <= p) {
            int kk = p - t;
            int offk = 32*(63*kk - (kk*(kk-1))/2);
            size_t prow = (size_t)offk + t*32 + b;
            const float4* qq = (const float4*)&g_prep[prow*16];
            float4 s0 = qq[0], s1 = qq[1], s2 = qq[2], s3 = qq[3];
            v0 = (s0.x+s0.y+s0.z+s0.w) + (s1.x+s1.y+s1.z+s1.w)
               + (s2.x+s2.y+s2.z+s2.w) + (s3.x+s3.y+s3.z+s3.w) + ab;
        }
    }
    {
        int t = lane + 32;
        if (t <= p) {
            int kk = p - t;
            int offk = 32*(63*kk - (kk*(kk-1))/2);
            size_t prow = (size_t)offk + t*32 + b;
            const float4* qq = (const float4*)&g_prep[prow*16];
            float4 s0 = qq[0], s1 = qq[1], s2 = qq[2], s3 = qq[3];
            v1 = (s0.x+s0.y+s0.z+s0.w) + (s1.x+s1.y+s1.z+s1.w)
               + (s2.x+s2.y+s2.z+s2.w) + (s3.x+s3.y+s3.z+s3.w) + ab;
        }
    }
    float m = fmaxf(v0, v1);
#pragma unroll
    for (int o=16;o;o>>=1) m = fmaxf(m, __shfl_xor_sync(0xffffffffu, m, o));
    float e0 = (lane      <= p) ? expf(v0-m) : 0.f;
    float e1 = (lane + 32 <= p) ? expf(v1-m) : 0.f;
    float s = e0 + e1;
#pragma unroll
    for (int o=16;o;o>>=1) s += __shfl_xor_sync(0xffffffffu, s, o);
    float inv = 1.f/s;
    g_alpha[(p*T_+lane   )*B_+b] = e0*inv;
    g_alpha[(p*T_+lane+32)*B_+b] = e1*inv;
}

__global__ void reduce_kernel(const float* __restrict__ x,
                              const float* __restrict__ out_w,
                              const float* __restrict__ out_b,
                              float* __restrict__ out) {
    int pb = blockIdx.x;
    int p = 62 - (pb >> 5);
    int b = pb & 31;
    int e = threadIdx.x;
    float cc = 0.f, gg = 0.f;
    for (int t = 0; t <= p; t++) {
        float a = g_alpha[(p*T_+t)*B_+b];
        int kk = p - t;
        int offk = 32*(63*kk - (kk*(kk-1))/2);
        size_t prow = (size_t)offk + t*32 + b;
        cc += a * g_beta [prow*E_ + e] * g_emb[((size_t)(t*B_+b))*E_ + e];
        gg += a * g_ebeta[prow*E_ + e] * x[((size_t)b*T_ + t)*E_ + e];
    }
    out[B_*P_ + ((size_t)(b*P_+p))*E_ + e] = gg / (float)(p+1);
    __shared__ float red[256];
    red[e] = cc * out_w[e];
    __syncthreads();
    for (int s2=128; s2; s2>>=1) { if (e < s2) red[e] += red[e+s2]; __syncthreads(); }
    if (e == 0) out[b*P_ + p] = red[0] + out_b[0];
}

// ------------------------- launch -------------------------------------------
extern "C" void kernel_launch(void* const* d_in, const int* in_sizes, int n_in,
                              void* d_out, int out_size) {
    (void)in_sizes; (void)n_in; (void)out_size;
    const float* x       = (const float*)d_in[0];
    const float* emb_w   = (const float*)d_in[1];
    const float* emb_b   = (const float*)d_in[2];
    const float* a_wih   = (const float*)d_in[3];
    const float* a_whh   = (const float*)d_in[4];
    const float* a_bih   = (const float*)d_in[5];
    const float* a_bhh   = (const float*)d_in[6];
    const float* b_wih   = (const float*)d_in[7];
    const float* b_whh   = (const float*)d_in[8];
    const float* b_bih   = (const float*)d_in[9];
    const float* b_bhh   = (const float*)d_in[10];
    const float* alpha_w = (const float*)d_in[11];
    const float* alpha_b = (const float*)d_in[12];
    const float* beta_w  = (const float*)d_in[13];
    const float* beta_b  = (const float*)d_in[14];
    const float* out_w   = (const float*)d_in[15];
    const float* out_b   = (const float*)d_in[16];
    float* out = (float*)d_out;

    cudaFuncSetAttribute(gru_persistent, cudaFuncAttributeMaxDynamicSharedMemorySize, SMEM_TOTAL_PERS);
    cudaFuncSetAttribute(dense_mma,      cudaFuncAttributeMaxDynamicSharedMemorySize, SMEM_TOTAL_DENSE);

    float *p_emb=0, *p_gxa=0, *p_gxb=0, *p_beta=0, *p_ebeta=0;
    __nv_bfloat16 *p_fbhi=0, *p_fblo=0, *p_bwhi=0, *p_bwlo=0;
    __nv_bfloat16 *p_mthi=0, *p_mtlo=0, *p_bhi=0, *p_blo=0;
    cudaGetSymbolAddress((void**)&p_emb,   g_emb);
    cudaGetSymbolAddress((void**)&p_gxa,   g_gxa);
    cudaGetSymbolAddress((void**)&p_gxb,   g_gxb);
    cudaGetSymbolAddress((void**)&p_beta,  g_beta);
    cudaGetSymbolAddress((void**)&p_ebeta, g_ebeta);
    cudaGetSymbolAddress((void**)&p_fbhi,  g_fbhi);
    cudaGetSymbolAddress((void**)&p_fblo,  g_fblo);
    cudaGetSymbolAddress((void**)&p_bwhi,  g_bwhi);
    cudaGetSymbolAddress((void**)&p_bwlo,  g_bwlo);
    cudaGetSymbolAddress((void**)&p_mthi,  g_mthi);
    cudaGetSymbolAddress((void**)&p_mtlo,  g_mtlo);
    cudaGetSymbolAddress((void**)&p_bhi,   g_betahi);
    cudaGetSymbolAddress((void**)&p_blo,   g_betalo);

    zero_planes_kernel<<<(2*2*PB_*H_/2 + 255)/256, 256>>>();
    prep_w_kernel<<<(2*768*256)/256, 256>>>(a_whh, b_whh);
    prep_bw_kernel<<<256, 256>>>(beta_w);
    prep_mt_kernel<<<256, 256>>>(emb_w, out_w);

    sgemm128<<<dim3((T_*B_)/128, E_/128), 256>>>(x, emb_w, emb_b, p_emb, E_, 0, 1);
    sgemm128_gx<<<dim3((T_*B_)/128, 12), 256>>>(p_emb, a_wih, a_bih, p_gxa,
                                                b_wih, b_bih, p_gxb);

    gru_persistent<<<NCTA_PERS, 512, SMEM_TOTAL_PERS>>>(a_bhh, b_bhh, alpha_w);

    alpha_kernel<<<(PB_*32 + 255)/256, 256>>>(alpha_b);

    dense_mma<<<dim3(NPACK_/128, 2), 512, SMEM_TOTAL_DENSE>>>(
        p_fbhi, p_fblo, p_bwhi, p_bwlo, beta_b, 1, p_beta, p_bhi, p_blo);
    dense_mma<<<dim3(NPACK_/128, 2), 512, SMEM_TOTAL_DENSE>>>(
        p_bhi, p_blo, p_mthi, p_mtlo, (const float*)0, 0, p_ebeta,
        (__nv_bfloat16*)0, (__nv_bfloat16*)0);

    reduce_kernel<<<PB_, 256>>>(x, out_w, out_b, out);
}

// round 14
// speedup vs baseline: 1.3507x; 1.0451x over previous
#include <cuda_runtime.h>
#include <cuda_bf16.h>
#include <math.h>
#include <stdint.h>

#define B_ 32
#define T_ 64
#define E_ 256
#define H_ 256
#define P_ 63
#define PB_ 2016
#define NPACK_ 64512

#define NCTA_PERS 144
#define NQ_ 18
#define SMEM_A_OFF   196608            // A buffers after 16 chunks * 12288B weights
#define ABUF_STRIDE  16384             // adaptive chunk buffer
#define SMEM_TOTAL_PERS (196608 + 2*ABUF_STRIDE)   // 229376

#define DCH2 49152                     // dense K32 chunk: A(2x12288)+B(2x12288)
#define SMEM_TOTAL_DENSE (2*DCH2)      // 98304

// ------------------------- scratch (device globals) -------------------------
__device__ float g_emb[T_*B_*E_];
__device__ float g_gxa[T_*B_*3*H_];
__device__ float g_gxb[T_*B_*3*H_];
__device__ __nv_bfloat16 g_hhi[2][2][PB_*H_];   // [gru][parity]
__device__ __nv_bfloat16 g_hlo[2][2][PB_*H_];
__device__ __nv_bfloat16 g_whi[2][3*H_*H_];
__device__ __nv_bfloat16 g_wlo[2][3*H_*H_];
__device__ __nv_bfloat16 g_bwhi[E_*H_];
__device__ __nv_bfloat16 g_bwlo[E_*H_];
__device__ __nv_bfloat16 g_mthi[E_*E_];
__device__ __nv_bfloat16 g_mtlo[E_*E_];
__device__ float g_prep[(size_t)NPACK_*16];     // pre partials [prow][cb*4+wn]
__device__ __nv_bfloat16 g_fbhi[(size_t)NPACK_*H_];
__device__ __nv_bfloat16 g_fblo[(size_t)NPACK_*H_];
__device__ float g_beta[(size_t)NPACK_*E_];
__device__ __nv_bfloat16 g_betahi[(size_t)NPACK_*E_];
__device__ __nv_bfloat16 g_betalo[(size_t)NPACK_*E_];
__device__ float g_ebeta[(size_t)NPACK_*E_];
__device__ unsigned g_bars[36*32];              // one counter per (gru,q), 128B apart

// ------------------------- helpers ------------------------------------------
__device__ __forceinline__ uint32_t smem_u32(const void* p) {
    uint32_t a;
    asm("{ .reg .u64 t; cvta.to.shared.u64 t, %1; cvt.u32.u64 %0, t; }" : "=r"(a) : "l"(p));
    return a;
}
__device__ __forceinline__ void ldsm4(uint32_t* r, uint32_t addr) {
    asm volatile("ldmatrix.sync.aligned.m8n8.x4.shared.b16 {%0,%1,%2,%3}, [%4];"
        : "=r"(r[0]), "=r"(r[1]), "=r"(r[2]), "=r"(r[3]) : "r"(addr));
}
__device__ __forceinline__ void mma16816(float* d, const uint32_t* a, const uint32_t* b) {
    asm volatile("mma.sync.aligned.m16n8k16.row.col.f32.bf16.bf16.f32 "
        "{%0,%1,%2,%3}, {%4,%5,%6,%7}, {%8,%9}, {%0,%1,%2,%3};"
        : "+f"(d[0]), "+f"(d[1]), "+f"(d[2]), "+f"(d[3])
        : "r"(a[0]), "r"(a[1]), "r"(a[2]), "r"(a[3]), "r"(b[0]), "r"(b[1]));
}
#define CP_ASYNC16(dst, src) \
    asm volatile("cp.async.cg.shared.global [%0], [%1], 16;" :: "r"(dst), "l"(src))
#define CP_COMMIT() asm volatile("cp.async.commit_group;")
#define CP_WAIT0()  asm volatile("cp.async.wait_group 0;")

// ------------------------- prep kernels -------------------------------------
__global__ void zero_planes_kernel() {
    int i = blockIdx.x*256 + threadIdx.x;
    uint32_t* a = (uint32_t*)g_hhi;
    uint32_t* b = (uint32_t*)g_hlo;
    if (i < 2*2*PB_*H_/2) { a[i] = 0u; b[i] = 0u; }
    if (i < 36*32) g_bars[i] = 0u;
}
__global__ void prep_w_kernel(const float* __restrict__ wa, const float* __restrict__ wb) {
    int idx = blockIdx.x*256 + threadIdx.x;
    int k = idx & 255;
    int r = (idx >> 8) % 768;
    int gru = idx / (768*256);
    float v = (gru ? wb : wa)[r*256 + k];
    __nv_bfloat16 hi = __float2bfloat16(v);
    g_whi[gru][r*256 + k] = hi;
    g_wlo[gru][r*256 + k] = __float2bfloat16(v - __bfloat162float(hi));
}
__global__ void prep_bw_kernel(const float* __restrict__ bw) {
    int idx = blockIdx.x*256 + threadIdx.x;
    float v = bw[idx];
    __nv_bfloat16 hi = __float2bfloat16(v);
    g_bwhi[idx] = hi;
    g_bwlo[idx] = __float2bfloat16(v - __bfloat162float(hi));
}
__global__ void prep_mt_kernel(const float* __restrict__ emb_w, const float* __restrict__ out_w) {
    int idx = blockIdx.x*256 + threadIdx.x;
    int i = idx >> 8, e = idx & 255;
    float v = out_w[e] * emb_w[e*256 + i];
    __nv_bfloat16 hi = __float2bfloat16(v);
    g_mthi[idx] = hi;
    g_mtlo[idx] = __float2bfloat16(v - __bfloat162float(hi));
}

// ------------------------- fp32 SGEMM (emb / gx) ----------------------------
__device__ __forceinline__ const float* arow_ptr(const float* A, int m, int xmode) {
    if (xmode) { int t = m >> 5, b = m & 31; return A + ((size_t)b*T_ + t)*E_; }
    return A + (size_t)m*E_;
}
__device__ __forceinline__ void sgemm_body(
        const float* A, const float* Bt, const float* bias, float* C,
        int N, int act, int xmode, int m0, int n0) {
    __shared__ float As[2][8][128];
    __shared__ float Bs[2][8][128];
    const int tid = threadIdx.x;
    const int tx = tid & 15, ty = tid >> 4;
    const int lr = tid >> 1;
    const int ks = (tid & 1) * 4;
    const float* pA = arow_ptr(A, m0 + lr, xmode) + ks;
    const float* pB = Bt + (size_t)(n0 + lr) * 256 + ks;
    float acc[2][2][4][4] = {};
    float4 va = *(const float4*)pA;
    float4 vb = *(const float4*)pB;
    {
        const float* f = (const float*)&va;
#pragma unroll
        for (int j = 0; j < 4; j++) As[0][ks+j][lr] = f[j];
        f = (const float*)&vb;
#pragma unroll
        for (int j = 0; j < 4; j++) Bs[0][ks+j][lr] = f[j];
    }
    __syncthreads();
    int buf = 0;
#pragma unroll 1
    for (int c = 0; c < 32; c++) {
        if (c < 31) {
            int off = (c+1)*8;
            va = *(const float4*)(pA + off);
            vb = *(const float4*)(pB + off);
        }
#pragma unroll
        for (int kk = 0; kk < 8; kk++) {
            float4 a0 = *(const float4*)&As[buf][kk][ty*4];
            float4 a1 = *(const float4*)&As[buf][kk][ty*4 + 64];
            float4 b0 = *(const float4*)&Bs[buf][kk][tx*4];
            float4 b1 = *(const float4*)&Bs[buf][kk][tx*4 + 64];
            float aa[2][4] = {{a0.x,a0.y,a0.z,a0.w},{a1.x,a1.y,a1.z,a1.w}};
            float bb[2][4] = {{b0.x,b0.y,b0.z,b0.w},{b1.x,b1.y,b1.z,b1.w}};
#pragma unroll
            for (int rh = 0; rh < 2; rh++)
#pragma unroll
            for (int i = 0; i < 4; i++)
#pragma unroll
            for (int ch = 0; ch < 2; ch++)
#pragma unroll
            for (int j = 0; j < 4; j++)
                acc[rh][ch][i][j] = fmaf(aa[rh][i], bb[ch][j], acc[rh][ch][i][j]);
        }
        if (c < 31) {
            int nb = buf ^ 1;
            const float* f = (const float*)&va;
#pragma unroll
            for (int j = 0; j < 4; j++) As[nb][ks+j][lr] = f[j];
            f = (const float*)&vb;
#pragma unroll
            for (int j = 0; j < 4; j++) Bs[nb][ks+j][lr] = f[j];
            __syncthreads();
            buf = nb;
        }
    }
#pragma unroll
    for (int rh = 0; rh < 2; rh++)
#pragma unroll
    for (int i = 0; i < 4; i++) {
        int m = m0 + rh*64 + ty*4 + i;
#pragma unroll
        for (int ch = 0; ch < 2; ch++) {
            int n = n0 + ch*64 + tx*4;
            float4 v;
            v.x = acc[rh][ch][i][0]; v.y = acc[rh][ch][i][1];
            v.z = acc[rh][ch][i][2]; v.w = acc[rh][ch][i][3];
            if (bias) {
                float4 bz = *(const float4*)&bias[n];
                v.x += bz.x; v.y += bz.y; v.z += bz.z; v.w += bz.w;
            }
            if (act == 1) { v.x = tanhf(v.x); v.y = tanhf(v.y); v.z = tanhf(v.z); v.w = tanhf(v.w); }
            *(float4*)&C[(size_t)m*N + n] = v;
        }
    }
}
__global__ void __launch_bounds__(256, 2)
sgemm128(const float* __restrict__ A, const float* __restrict__ Bt,
         const float* __restrict__ bias, float* __restrict__ C,
         int N, int act, int xmode) {
    sgemm_body(A, Bt, bias, C, N, act, xmode, blockIdx.x*128, blockIdx.y*128);
}
__global__ void __launch_bounds__(256, 2)
sgemm128_gx(const float* __restrict__ A,
            const float* __restrict__ BtA, const float* __restrict__ biasA, float* __restrict__ CA,
            const float* __restrict__ BtB, const float* __restrict__ biasB, float* __restrict__ CB) {
    int y = blockIdx.y;
    if (y < 6) sgemm_body(A, BtA, biasA, CA, 3*H_, 0, 0, blockIdx.x*128, y*128);
    else       sgemm_body(A, BtB, biasB, CB, 3*H_, 0, 0, blockIdx.x*128, (y-6)*128);
}

// ------------------------- persistent GRU recurrence ------------------------
// Identity-stable chunk ownership (chunk c -> q = c mod 18); per-group 4-CTA
// barrier; groups drift independently. (Unchanged from R13.)
__global__ void __launch_bounds__(512, 1)
gru_persistent(const float* __restrict__ bhh_a, const float* __restrict__ bhh_b,
               const float* __restrict__ alpha_w) {
    extern __shared__ __align__(16) unsigned char smem[];
    const int tid = threadIdx.x, lane = tid & 31, wid = tid >> 5;
    const int wm = wid >> 2, wn = wid & 3;   // wm spread across SMSPs
    const int gid = blockIdx.x;
    const int gru = gid & 1, cb = (gid >> 1) & 3, q = gid >> 3;
    const uint32_t sbase = smem_u32(smem);

    {
        const __nv_bfloat16* Whi = g_whi[gru];
        const __nv_bfloat16* Wlo = g_wlo[gru];
        for (int u = tid; u < 12288; u += 512) {
            int nrow7 = u & 7;
            int kh = (u >> 3) & 1;
            int nh = (u >> 4) & 1;
            int ng16 = (u >> 5) % 12;
            int pc = (u >> 5) / 12;
            int p = pc & 1, c = pc >> 1;
            int Rg = (ng16 >> 2)*256 + cb*64 + (ng16 & 3)*16 + nh*8 + nrow7;
            const __nv_bfloat16* src = (p ? Wlo : Whi) + (size_t)Rg*256 + c*16 + kh*8;
            uint32_t dst = (uint32_t)(c*12288 + p*6144 + ng16*512 + nh*256 + kh*128 + nrow7*16);
            *(uint4*)(smem + dst) = *(const uint4*)src;
        }
    }
    __syncthreads();

    const uint32_t lpiece = (uint32_t)((lane >> 4)*256 + ((lane >> 3) & 1)*128 + (lane & 7)*16);
    uint32_t wboff[2][3];
#pragma unroll
    for (int p = 0; p < 2; p++)
#pragma unroll
    for (int g = 0; g < 3; g++)
        wboff[p][g] = (uint32_t)(p*6144 + (g*4 + wn)*512) + lpiece;

    const float* bhh = gru ? bhh_b : bhh_a;
    const float* gx  = gru ? g_gxb : g_gxa;
    const int g8 = lane >> 2, t2 = (lane & 3)*2;
    unsigned* mybar = &g_bars[(gru*18 + q)*32];
    const uint32_t abuf0 = sbase + SMEM_A_OFF;

#pragma unroll 1
    for (int step = 0; step < 63; step++) {
        const int par = step & 1;
        const int a2 = 2*step;
        int d = q - (a2 % 18); if (d < 0) d += 18;
        const int cfirst = a2 + d;
        if (cfirst >= 126) break;
        const int ng = 1 + (126 - cfirst - 1)/18;
        const int R = ng*16;
        {
            const __nv_bfloat16* Hhi = g_hhi[gru][par];
            const __nv_bfloat16* Hlo = g_hlo[gru][par];
            int kch;
            if (R <= 16) kch = 16; else if (R <= 32) kch = 8;
            else if (R <= 64) kch = 4; else kch = 2;
            const int nchunks = 16 / kch;
            const int KC = kch * 16;
            const uint32_t ks_str = (uint32_t)(ng*1024);
            const uint32_t pl_str = (uint32_t)(ng*512);

            const int Nit = 4*R*kch;
            uint32_t sdst[2]; const __nv_bfloat16* ssrc[2]; bool sval[2];
#pragma unroll
            for (int it = 0; it < 2; it++) {
                int u = tid + it*512;
                sval[it] = (u < Nit);
                int uu = sval[it] ? u : 0;
                int r7 = uu & 7; uu >>= 3;
                int r8 = uu & 1; uu >>= 1;
                int k8 = uu & 1; uu >>= 1;
                int g  = uu % ng; uu /= ng;
                int p  = uu & 1; uu >>= 1;
                int s  = uu;
                sdst[it] = (uint32_t)(s*(int)ks_str + p*(int)pl_str + g*512 + k8*256 + r8*128 + r7*16);
                int row = (cfirst + g*18)*16 + r8*8 + r7;
                ssrc[it] = (p ? Hlo : Hhi) + (size_t)row*H_ + s*16 + k8*8;
            }

            float acc[3][2][2][4] = {};
            if (sval[0]) CP_ASYNC16(abuf0 + sdst[0], ssrc[0]);
            if (sval[1]) CP_ASYNC16(abuf0 + sdst[1], ssrc[1]);
            CP_COMMIT();
#pragma unroll 1
            for (int cc = 0; cc < nchunks; cc++) {
                CP_WAIT0();
                __syncthreads();
                if (cc + 1 < nchunks) {
                    uint32_t bb = abuf0 + (uint32_t)(((cc+1)&1)*ABUF_STRIDE);
                    int ko = (cc+1)*KC;
                    if (sval[0]) CP_ASYNC16(bb + sdst[0], ssrc[0] + ko);
                    if (sval[1]) CP_ASYNC16(bb + sdst[1], ssrc[1] + ko);
                    CP_COMMIT();
                }
                if (2*wm < ng) {
                    const bool two = (2*wm + 1 < ng);
                    const uint32_t bufb = abuf0 + (uint32_t)((cc&1)*ABUF_STRIDE);
#pragma unroll 1
                    for (int s = 0; s < kch; s++) {
                        uint32_t a0 = bufb + (uint32_t)s*ks_str + (uint32_t)((wm*2)*512) + lpiece;
                        uint32_t Ah[2][4], Al[2][4];
                        ldsm4(Ah[0], a0);
                        ldsm4(Al[0], a0 + pl_str);
                        if (two) { ldsm4(Ah[1], a0 + 512); ldsm4(Al[1], a0 + 512 + pl_str); }
                        const uint32_t wbc = sbase + (uint32_t)((cc*kch + s)*12288);
#pragma unroll
                        for (int g = 0; g < 3; g++) {
                            uint32_t Bh[4], Bl[4];
                            ldsm4(Bh, wbc + wboff[0][g]);
                            ldsm4(Bl, wbc + wboff[1][g]);
#pragma unroll
                            for (int j = 0; j < 2; j++) {
                                mma16816(acc[g][0][j], Ah[0], &Bh[j*2]);
                                mma16816(acc[g][0][j], Ah[0], &Bl[j*2]);
                                mma16816(acc[g][0][j], Al[0], &Bh[j*2]);
                            }
                            if (two) {
#pragma unroll
                                for (int j = 0; j < 2; j++) {
                                    mma16816(acc[g][1][j], Ah[1], &Bh[j*2]);
                                    mma16816(acc[g][1][j], Ah[1], &Bl[j*2]);
                                    mma16816(acc[g][1][j], Al[1], &Bh[j*2]);
                                }
                            }
                        }
                    }
                }
            }
            // ---- epilogue ----
            __nv_bfloat16* Hhi_n = g_hhi[gru][par^1];
            __nv_bfloat16* Hlo_n = g_hlo[gru][par^1];
            const size_t offk = (size_t)32*(63*step - (step*(step-1))/2);
#pragma unroll
            for (int i = 0; i < 2; i++) {
                if (2*wm + i >= ng) continue;
#pragma unroll
                for (int half = 0; half < 2; half++) {
                    int grow = (cfirst + (2*wm + i)*18)*16 + g8 + half*8;
                    int gxrow = grow - step*32;
                    const float* gxr = gx + (size_t)gxrow*(3*H_);
                    size_t prow = offk + gxrow;
                    float row_part = 0.f;
#pragma unroll
                    for (int j = 0; j < 2; j++) {
                        int cc2 = cb*64 + wn*16 + j*8 + t2;
                        float2 gx_r = *(const float2*)&gxr[cc2];
                        float2 gx_z = *(const float2*)&gxr[H_ + cc2];
                        float2 gx_n = *(const float2*)&gxr[2*H_ + cc2];
                        float2 bh_r = *(const float2*)&bhh[cc2];
                        float2 bh_z = *(const float2*)&bhh[H_ + cc2];
                        float2 bh_n = *(const float2*)&bhh[2*H_ + cc2];
                        __nv_bfloat162 ho_hi = *(const __nv_bfloat162*)&Hhi[(size_t)grow*H_ + cc2];
                        __nv_bfloat162 ho_lo = *(const __nv_bfloat162*)&Hlo[(size_t)grow*H_ + cc2];
                        float hn2[2];
#pragma unroll
                        for (int u = 0; u < 2; u++) {
                            int ai = half*2 + u;
                            float rp = acc[0][i][j][ai] + (u ? bh_r.y : bh_r.x) + (u ? gx_r.y : gx_r.x);
                            float zp = acc[1][i][j][ai] + (u ? bh_z.y : bh_z.x) + (u ? gx_z.y : gx_z.x);
                            float np = acc[2][i][j][ai] + (u ? bh_n.y : bh_n.x);
                            float r = 1.f/(1.f + expf(-rp));
                            float z = 1.f/(1.f + expf(-zp));
                            float n = tanhf((u ? gx_n.y : gx_n.x) + r*np);
                            float hold = __bfloat162float(u ? ho_hi.y : ho_hi.x)
                                       + __bfloat162float(u ? ho_lo.y : ho_lo.x);
                            hn2[u] = (1.f - z)*n + z*hold;
                        }
                        __nv_bfloat162 hi2, lo2;
                        hi2.x = __float2bfloat16(hn2[0]); hi2.y = __float2bfloat16(hn2[1]);
                        lo2.x = __float2bfloat16(hn2[0] - __bfloat162float(hi2.x));
                        lo2.y = __float2bfloat16(hn2[1] - __bfloat162float(hi2.y));
                        *(__nv_bfloat162*)&Hhi_n[(size_t)grow*H_ + cc2] = hi2;
                        *(__nv_bfloat162*)&Hlo_n[(size_t)grow*H_ + cc2] = lo2;
                        if (gru == 0) {
                            float2 aw = *(const float2*)&alpha_w[cc2];
                            row_part += 0.5f*hn2[0]*aw.x + 0.5f*hn2[1]*aw.y;
                        } else {
                            float f0 = 0.5f*hn2[0], f1 = 0.5f*hn2[1];
                            __nv_bfloat162 fh, fl;
                            fh.x = __float2bfloat16(f0); fh.y = __float2bfloat16(f1);
                            fl.x = __float2bfloat16(f0 - __bfloat162float(fh.x));
                            fl.y = __float2bfloat16(f1 - __bfloat162float(fh.y));
                            *(__nv_bfloat162*)&g_fbhi[prow*H_ + cc2] = fh;
                            *(__nv_bfloat162*)&g_fblo[prow*H_ + cc2] = fl;
                        }
                    }
                    if (gru == 0) {
                        row_part += __shfl_xor_sync(0xffffffffu, row_part, 1);
                        row_part += __shfl_xor_sync(0xffffffffu, row_part, 2);
                        if ((lane & 3) == 0)
                            g_prep[prow*16 + cb*4 + wn] = row_part;
                    }
                }
            }
        }
        // ---- 4-CTA group barrier (gru, q) ----
        __syncthreads();
        if (tid == 0) {
            __threadfence();
            atomicAdd(mybar, 1u);
            const unsigned target = 4u*(unsigned)(step+1);
            unsigned v;
            do {
                asm volatile("ld.acquire.gpu.u32 %0, [%1];" : "=r"(v) : "l"(mybar));
            } while (v < target);
        }
        __syncthreads();
    }
}

// ------------------------- mma dense GEMM (M x 256, K=256) ------------------
// K=32 chunks, 2 buffers, ONE sync per chunk (8 chunks).
__global__ void __launch_bounds__(512, 1)
dense_mma(const __nv_bfloat16* __restrict__ Ahi, const __nv_bfloat16* __restrict__ Alo,
          const __nv_bfloat16* __restrict__ Bthi, const __nv_bfloat16* __restrict__ Btlo,
          const float* __restrict__ bias, int act, float* __restrict__ outf,
          __nv_bfloat16* __restrict__ Phi, __nv_bfloat16* __restrict__ Plo) {
    extern __shared__ __align__(16) unsigned char smem[];
    const int tid = threadIdx.x, lane = tid & 31, wid = tid >> 5;
    const int wm = wid & 3, wn = wid >> 2;
    const int cb = blockIdx.y;
    const int rowbase = blockIdx.x * 128;
    const uint32_t sbase = smem_u32(smem);

    float acc[2][4][4] = {};

    const int a_r = lane & 15, a_c16 = ((lane >> 4) & 1) * 16;
    const int b_r = (lane & 7) + ((lane >> 4) & 1) * 8, b_c16 = (lane & 8) * 2;
    // relative offsets within one 12288B sub-block
    uint32_t aob[2][2], bob[2][2];
#pragma unroll
    for (int p = 0; p < 2; p++) {
#pragma unroll
        for (int i = 0; i < 2; i++)
            aob[p][i] = (uint32_t)(p*6144 + (wm*32 + i*16 + a_r)*48 + a_c16);
#pragma unroll
        for (int h2 = 0; h2 < 2; h2++)
            bob[p][h2] = (uint32_t)(p*6144 + (wn*32 + h2*16 + b_r)*48 + b_c16);
    }

    const int st_q = tid & 1, st_r = (tid >> 1) & 127, st_p = tid >> 8;
    const uint32_t stoff = (uint32_t)(st_p*6144 + st_r*48 + st_q*16);
    const __nv_bfloat16* srcA = (st_p ? Alo : Ahi) + (size_t)(rowbase + st_r)*256 + st_q*8;
    const __nv_bfloat16* srcB = (st_p ? Btlo : Bthi) + (size_t)(cb*128 + st_r)*256 + st_q*8;

    // stage chunk 0 (k16 sub-chunks 0,1)
#pragma unroll
    for (int sub = 0; sub < 2; sub++) {
        CP_ASYNC16(sbase + sub*12288u + stoff, srcA + sub*16);
        CP_ASYNC16(sbase + 24576u + sub*12288u + stoff, srcB + sub*16);
    }
    CP_COMMIT();

#pragma unroll 1
    for (int c = 0; c < 8; c++) {
        CP_WAIT0();
        __syncthreads();
        if (c < 7) {
            uint32_t bb = sbase + (uint32_t)(((c+1)&1)*DCH2);
            int ko = (c+1)*32;
#pragma unroll
            for (int sub = 0; sub < 2; sub++) {
                CP_ASYNC16(bb + sub*12288u + stoff, srcA + ko + sub*16);
                CP_ASYNC16(bb + 24576u + sub*12288u + stoff, srcB + ko + sub*16);
            }
            CP_COMMIT();
        }
        const uint32_t bufb = sbase + (uint32_t)((c&1)*DCH2);
#pragma unroll
        for (int sub = 0; sub < 2; sub++) {
            const uint32_t ab = bufb + sub*12288u;
            const uint32_t bbB = bufb + 24576u + sub*12288u;
            uint32_t Ah[2][4], Al[2][4], Bh[8], Bl[8];
            ldsm4(Ah[0], ab + aob[0][0]); ldsm4(Ah[1], ab + aob[0][1]);
            ldsm4(Al[0], ab + aob[1][0]); ldsm4(Al[1], ab + aob[1][1]);
            ldsm4(Bh,   bbB + bob[0][0]); ldsm4(Bh+4, bbB + bob[0][1]);
            ldsm4(Bl,   bbB + bob[1][0]); ldsm4(Bl+4, bbB + bob[1][1]);
#pragma unroll
            for (int i = 0; i < 2; i++)
#pragma unroll
            for (int j = 0; j < 4; j++) {
                mma16816(acc[i][j], Ah[i], &Bh[j*2]);
                mma16816(acc[i][j], Ah[i], &Bl[j*2]);
                mma16816(acc[i][j], Al[i], &Bh[j*2]);
            }
        }
    }

    const int g8 = lane >> 2, t2 = (lane & 3)*2;
#pragma unroll
    for (int i = 0; i < 2; i++)
#pragma unroll
    for (int half = 0; half < 2; half++) {
        int grow = rowbase + wm*32 + i*16 + g8 + half*8;
#pragma unroll
        for (int j = 0; j < 4; j++) {
            int cc = cb*128 + wn*32 + j*8 + t2;
            float v0 = acc[i][j][half*2 + 0];
            float v1 = acc[i][j][half*2 + 1];
            if (bias) { v0 += bias[cc]; v1 += bias[cc+1]; }
            if (act == 1) { v0 = tanhf(v0); v1 = tanhf(v1); }
            float2 f2; f2.x = v0; f2.y = v1;
            *(float2*)&outf[(size_t)grow*E_ + cc] = f2;
            if (Phi) {
                __nv_bfloat162 hi2, lo2;
                hi2.x = __float2bfloat16(v0); hi2.y = __float2bfloat16(v1);
                lo2.x = __float2bfloat16(v0 - __bfloat162float(hi2.x));
                lo2.y = __float2bfloat16(v1 - __bfloat162float(hi2.y));
                *(__nv_bfloat162*)&Phi[(size_t)grow*E_ + cc] = hi2;
                *(__nv_bfloat162*)&Plo[(size_t)grow*E_ + cc] = lo2;
            }
        }
    }
}

// ------------------------- reduce (alpha fused) -----------------------------
__global__ void reduce_kernel(const float* __restrict__ x,
                              const float* __restrict__ out_w,
                              const float* __restrict__ out_b,
                              const float* __restrict__ alpha_b,
                              float* __restrict__ out) {
    int pb = blockIdx.x;
    int p = 62 - (pb >> 5);
    int b = pb & 31;
    int e = threadIdx.x;
    __shared__ float s_alpha[T_];
    if (e < 32) {
        int lane = e;
        float ab = alpha_b[0];
        float v0 = -1e30f, v1 = -1e30f;
        {
            int t = lane;
            if (t <= p) {
                int kk = p - t;
                int offk = 32*(63*kk - (kk*(kk-1))/2);
                size_t prow = (size_t)offk + t*32 + b;
                const float4* qq = (const float4*)&g_prep[prow*16];
                float4 s0 = qq[0], s1 = qq[1], s2 = qq[2], s3 = qq[3];
                v0 = (s0.x+s0.y+s0.z+s0.w) + (s1.x+s1.y+s1.z+s1.w)
                   + (s2.x+s2.y+s2.z+s2.w) + (s3.x+s3.y+s3.z+s3.w) + ab;
            }
        }
        {
            int t = lane + 32;
            if (t <= p) {
                int kk = p - t;
                int offk = 32*(63*kk - (kk*(kk-1))/2);
                size_t prow = (size_t)offk + t*32 + b;
                const float4* qq = (const float4*)&g_prep[prow*16];
                float4 s0 = qq[0], s1 = qq[1], s2 = qq[2], s3 = qq[3];
                v1 = (s0.x+s0.y+s0.z+s0.w) + (s1.x+s1.y+s1.z+s1.w)
                   + (s2.x+s2.y+s2.z+s2.w) + (s3.x+s3.y+s3.z+s3.w) + ab;
            }
        }
        float m = fmaxf(v0, v1);
#pragma unroll
        for (int o=16;o;o>>=1) m = fmaxf(m, __shfl_xor_sync(0xffffffffu, m, o));
        float e0 = (lane      <= p) ? expf(v0-m) : 0.f;
        float e1 = (lane + 32 <= p) ? expf(v1-m) : 0.f;
        float s = e0 + e1;
#pragma unroll
        for (int o=16;o;o>>=1) s += __shfl_xor_sync(0xffffffffu, s, o);
        float inv = 1.f/s;
        s_alpha[lane]      = e0*inv;
        s_alpha[lane + 32] = e1*inv;
    }
    __syncthreads();
    float cc = 0.f, gg = 0.f;
    for (int t = 0; t <= p; t++) {
        float a = s_alpha[t];
        int kk = p - t;
        int offk = 32*(63*kk - (kk*(kk-1))/2);
        size_t prow = (size_t)offk + t*32 + b;
        cc += a * g_beta [prow*E_ + e] * g_emb[((size_t)(t*B_+b))*E_ + e];
        gg += a * g_ebeta[prow*E_ + e] * x[((size_t)b*T_ + t)*E_ + e];
    }
    out[B_*P_ + ((size_t)(b*P_+p))*E_ + e] = gg / (float)(p+1);
    __shared__ float red[256];
    red[e] = cc * out_w[e];
    __syncthreads();
    for (int s2=128; s2; s2>>=1) { if (e < s2) red[e] += red[e+s2]; __syncthreads(); }
    if (e == 0) out[b*P_ + p] = red[0] + out_b[0];
}

// ------------------------- launch -------------------------------------------
extern "C" void kernel_launch(void* const* d_in, const int* in_sizes, int n_in,
                              void* d_out, int out_size) {
    (void)in_sizes; (void)n_in; (void)out_size;
    const float* x       = (const float*)d_in[0];
    const float* emb_w   = (const float*)d_in[1];
    const float* emb_b   = (const float*)d_in[2];
    const float* a_wih   = (const float*)d_in[3];
    const float* a_whh   = (const float*)d_in[4];
    const float* a_bih   = (const float*)d_in[5];
    const float* a_bhh   = (const float*)d_in[6];
    const float* b_wih   = (const float*)d_in[7];
    const float* b_whh   = (const float*)d_in[8];
    const float* b_bih   = (const float*)d_in[9];
    const float* b_bhh   = (const float*)d_in[10];
    const float* alpha_w = (const float*)d_in[11];
    const float* alpha_b = (const float*)d_in[12];
    const float* beta_w  = (const float*)d_in[13];
    const float* beta_b  = (const float*)d_in[14];
    const float* out_w   = (const float*)d_in[15];
    const float* out_b   = (const float*)d_in[16];
    float* out = (float*)d_out;

    cudaFuncSetAttribute(gru_persistent, cudaFuncAttributeMaxDynamicSharedMemorySize, SMEM_TOTAL_PERS);
    cudaFuncSetAttribute(dense_mma,      cudaFuncAttributeMaxDynamicSharedMemorySize, SMEM_TOTAL_DENSE);

    float *p_emb=0, *p_gxa=0, *p_gxb=0, *p_beta=0, *p_ebeta=0;
    __nv_bfloat16 *p_fbhi=0, *p_fblo=0, *p_bwhi=0, *p_bwlo=0;
    __nv_bfloat16 *p_mthi=0, *p_mtlo=0, *p_bhi=0, *p_blo=0;
    cudaGetSymbolAddress((void**)&p_emb,   g_emb);
    cudaGetSymbolAddress((void**)&p_gxa,   g_gxa);
    cudaGetSymbolAddress((void**)&p_gxb,   g_gxb);
    cudaGetSymbolAddress((void**)&p_beta,  g_beta);
    cudaGetSymbolAddress((void**)&p_ebeta, g_ebeta);
    cudaGetSymbolAddress((void**)&p_fbhi,  g_fbhi);
    cudaGetSymbolAddress((void**)&p_fblo,  g_fblo);
    cudaGetSymbolAddress((void**)&p_bwhi,  g_bwhi);
    cudaGetSymbolAddress((void**)&p_bwlo,  g_bwlo);
    cudaGetSymbolAddress((void**)&p_mthi,  g_mthi);
    cudaGetSymbolAddress((void**)&p_mtlo,  g_mtlo);
    cudaGetSymbolAddress((void**)&p_bhi,   g_betahi);
    cudaGetSymbolAddress((void**)&p_blo,   g_betalo);

    zero_planes_kernel<<<(2*2*PB_*H_/2 + 255)/256, 256>>>();
    prep_w_kernel<<<(2*768*256)/256, 256>>>(a_whh, b_whh);
    prep_bw_kernel<<<256, 256>>>(beta_w);
    prep_mt_kernel<<<256, 256>>>(emb_w, out_w);

    sgemm128<<<dim3((T_*B_)/128, E_/128), 256>>>(x, emb_w, emb_b, p_emb, E_, 0, 1);
    sgemm128_gx<<<dim3((T_*B_)/128, 12), 256>>>(p_emb, a_wih, a_bih, p_gxa,
                                                b_wih, b_bih, p_gxb);

    gru_persistent<<<NCTA_PERS, 512, SMEM_TOTAL_PERS>>>(a_bhh, b_bhh, alpha_w);

    dense_mma<<<dim3(NPACK_/128, 2), 512, SMEM_TOTAL_DENSE>>>(
        p_fbhi, p_fblo, p_bwhi, p_bwlo, beta_b, 1, p_beta, p_bhi, p_blo);
    dense_mma<<<dim3(NPACK_/128, 2), 512, SMEM_TOTAL_DENSE>>>(
        p_bhi, p_blo, p_mthi, p_mtlo, (const float*)0, 0, p_ebeta,
        (__nv_bfloat16*)0, (__nv_bfloat16*)0);

    reduce_kernel<<<PB_, 256>>>(x, out_w, out_b, alpha_b, out);
}

// round 15
// speedup vs baseline: 1.3556x; 1.0036x over previous
#include <cuda_runtime.h>
#include <cuda_bf16.h>
#include <math.h>
#include <stdint.h>

#define B_ 32
#define T_ 64
#define E_ 256
#define H_ 256
#define P_ 63
#define PB_ 2016
#define NPACK_ 64512

#define NCTA_PERS 144
#define NQ_ 18
#define SMEM_A_OFF   196608            // A buffers after 16 chunks * 12288B weights
#define ABUF_STRIDE  16384             // adaptive chunk buffer
#define SMEM_TOTAL_PERS (196608 + 2*ABUF_STRIDE)   // 229376

#define DCH2 49152                     // dense K32 chunk: A(2x12288)+B(2x12288)
#define SMEM_TOTAL_DENSE (2*DCH2)      // 98304

// ------------------------- scratch (device globals) -------------------------
__device__ float g_emb[T_*B_*E_];
__device__ __nv_bfloat16 g_embhi[T_*B_*E_];
__device__ __nv_bfloat16 g_emblo[T_*B_*E_];
__device__ float g_gxa[T_*B_*3*H_];
__device__ float g_gxb[T_*B_*3*H_];
__device__ __nv_bfloat16 g_hhi[2][2][PB_*H_];   // [gru][parity]
__device__ __nv_bfloat16 g_hlo[2][2][PB_*H_];
__device__ __nv_bfloat16 g_whi[2][3*H_*H_];
__device__ __nv_bfloat16 g_wlo[2][3*H_*H_];
__device__ __nv_bfloat16 g_wihhi[2][3*H_*E_];
__device__ __nv_bfloat16 g_wihlo[2][3*H_*E_];
__device__ __nv_bfloat16 g_bwhi[E_*H_];
__device__ __nv_bfloat16 g_bwlo[E_*H_];
__device__ __nv_bfloat16 g_mthi[E_*E_];
__device__ __nv_bfloat16 g_mtlo[E_*E_];
__device__ float g_prep[(size_t)NPACK_*16];     // pre partials [prow][cb*4+wn]
__device__ __nv_bfloat16 g_fbhi[(size_t)NPACK_*H_];
__device__ __nv_bfloat16 g_fblo[(size_t)NPACK_*H_];
__device__ float g_beta[(size_t)NPACK_*E_];
__device__ __nv_bfloat16 g_betahi[(size_t)NPACK_*E_];
__device__ __nv_bfloat16 g_betalo[(size_t)NPACK_*E_];
__device__ float g_ebeta[(size_t)NPACK_*E_];
__device__ unsigned g_bars[36*32];              // one counter per (gru,q), 128B apart

// ------------------------- helpers ------------------------------------------
__device__ __forceinline__ uint32_t smem_u32(const void* p) {
    uint32_t a;
    asm("{ .reg .u64 t; cvta.to.shared.u64 t, %1; cvt.u32.u64 %0, t; }" : "=r"(a) : "l"(p));
    return a;
}
__device__ __forceinline__ void ldsm4(uint32_t* r, uint32_t addr) {
    asm volatile("ldmatrix.sync.aligned.m8n8.x4.shared.b16 {%0,%1,%2,%3}, [%4];"
        : "=r"(r[0]), "=r"(r[1]), "=r"(r[2]), "=r"(r[3]) : "r"(addr));
}
__device__ __forceinline__ void mma16816(float* d, const uint32_t* a, const uint32_t* b) {
    asm volatile("mma.sync.aligned.m16n8k16.row.col.f32.bf16.bf16.f32 "
        "{%0,%1,%2,%3}, {%4,%5,%6,%7}, {%8,%9}, {%0,%1,%2,%3};"
        : "+f"(d[0]), "+f"(d[1]), "+f"(d[2]), "+f"(d[3])
        : "r"(a[0]), "r"(a[1]), "r"(a[2]), "r"(a[3]), "r"(b[0]), "r"(b[1]));
}
#define CP_ASYNC16(dst, src) \
    asm volatile("cp.async.cg.shared.global [%0], [%1], 16;" :: "r"(dst), "l"(src))
#define CP_COMMIT() asm volatile("cp.async.commit_group;")
#define CP_WAIT0()  asm volatile("cp.async.wait_group 0;")

// ------------------------- merged prep kernel --------------------------------
__global__ void prep_all(const float* __restrict__ wa, const float* __restrict__ wb,
                         const float* __restrict__ wia, const float* __restrict__ wib,
                         const float* __restrict__ bw,
                         const float* __restrict__ emb_w, const float* __restrict__ out_w) {
    long idx = (long)blockIdx.x*256 + threadIdx.x;
    const long Z = 2L*PB_*H_;                    // u32 zero items (parity-0 planes)
    if (idx < Z) {
        int gru = idx >= (long)PB_*H_;
        long r = idx - (long)gru*((long)PB_*H_);
        int arr = r >= (long)PB_*H_/2;
        long o = r - (long)arr*((long)PB_*H_/2);
        uint32_t* base = arr ? (uint32_t*)g_hlo[gru][0] : (uint32_t*)g_hhi[gru][0];
        base[o] = 0u;
        return;
    }
    idx -= Z;
    if (idx < 36*32) { g_bars[idx] = 0u; return; }
    idx -= 36*32;
    if (idx < 2L*768*256) {
        int k = (int)(idx & 255); int r = (int)((idx >> 8) % 768); int gru = (int)(idx/(768*256));
        float v = (gru ? wb : wa)[r*256 + k];
        __nv_bfloat16 hi = __float2bfloat16(v);
        g_whi[gru][r*256 + k] = hi;
        g_wlo[gru][r*256 + k] = __float2bfloat16(v - __bfloat162float(hi));
        return;
    }
    idx -= 2L*768*256;
    if (idx < 2L*768*256) {
        int k = (int)(idx & 255); int r = (int)((idx >> 8) % 768); int gru = (int)(idx/(768*256));
        float v = (gru ? wib : wia)[r*256 + k];
        __nv_bfloat16 hi = __float2bfloat16(v);
        g_wihhi[gru][r*256 + k] = hi;
        g_wihlo[gru][r*256 + k] = __float2bfloat16(v - __bfloat162float(hi));
        return;
    }
    idx -= 2L*768*256;
    if (idx < 65536) {
        float v = bw[idx];
        __nv_bfloat16 hi = __float2bfloat16(v);
        g_bwhi[idx] = hi;
        g_bwlo[idx] = __float2bfloat16(v - __bfloat162float(hi));
        return;
    }
    idx -= 65536;
    if (idx < 65536) {
        int i = (int)(idx >> 8), e = (int)(idx & 255);
        float v = out_w[e] * emb_w[e*256 + i];
        __nv_bfloat16 hi = __float2bfloat16(v);
        g_mthi[idx] = hi;
        g_mtlo[idx] = __float2bfloat16(v - __bfloat162float(hi));
    }
}
#define PREP_TOTAL (2L*PB_*H_ + 36*32 + 2L*768*256 + 2L*768*256 + 65536 + 65536)

// ------------------------- fp32 SGEMM (emb, emits planes) -------------------
__global__ void __launch_bounds__(256, 2)
sgemm128(const float* __restrict__ A, const float* __restrict__ Bt,
         const float* __restrict__ bias, float* __restrict__ C, int N,
         __nv_bfloat16* __restrict__ Phi, __nv_bfloat16* __restrict__ Plo) {
    __shared__ float As[2][8][128];
    __shared__ float Bs[2][8][128];
    const int tid = threadIdx.x;
    const int m0 = blockIdx.x*128, n0 = blockIdx.y*128;
    const int tx = tid & 15, ty = tid >> 4;
    const int lr = tid >> 1;
    const int ks = (tid & 1) * 4;
    const float* pA;
    { int m = m0 + lr; int t = m >> 5, b = m & 31; pA = A + ((size_t)b*T_ + t)*E_ + ks; }
    const float* pB = Bt + (size_t)(n0 + lr) * 256 + ks;
    float acc[2][2][4][4] = {};
    float4 va = *(const float4*)pA;
    float4 vb = *(const float4*)pB;
    {
        const float* f = (const float*)&va;
#pragma unroll
        for (int j = 0; j < 4; j++) As[0][ks+j][lr] = f[j];
        f = (const float*)&vb;
#pragma unroll
        for (int j = 0; j < 4; j++) Bs[0][ks+j][lr] = f[j];
    }
    __syncthreads();
    int buf = 0;
#pragma unroll 1
    for (int c = 0; c < 32; c++) {
        if (c < 31) {
            int off = (c+1)*8;
            va = *(const float4*)(pA + off);
            vb = *(const float4*)(pB + off);
        }
#pragma unroll
        for (int kk = 0; kk < 8; kk++) {
            float4 a0 = *(const float4*)&As[buf][kk][ty*4];
            float4 a1 = *(const float4*)&As[buf][kk][ty*4 + 64];
            float4 b0 = *(const float4*)&Bs[buf][kk][tx*4];
            float4 b1 = *(const float4*)&Bs[buf][kk][tx*4 + 64];
            float aa[2][4] = {{a0.x,a0.y,a0.z,a0.w},{a1.x,a1.y,a1.z,a1.w}};
            float bb[2][4] = {{b0.x,b0.y,b0.z,b0.w},{b1.x,b1.y,b1.z,b1.w}};
#pragma unroll
            for (int rh = 0; rh < 2; rh++)
#pragma unroll
            for (int i = 0; i < 4; i++)
#pragma unroll
            for (int ch = 0; ch < 2; ch++)
#pragma unroll
            for (int j = 0; j < 4; j++)
                acc[rh][ch][i][j] = fmaf(aa[rh][i], bb[ch][j], acc[rh][ch][i][j]);
        }
        if (c < 31) {
            int nb = buf ^ 1;
            const float* f = (const float*)&va;
#pragma unroll
            for (int j = 0; j < 4; j++) As[nb][ks+j][lr] = f[j];
            f = (const float*)&vb;
#pragma unroll
            for (int j = 0; j < 4; j++) Bs[nb][ks+j][lr] = f[j];
            __syncthreads();
            buf = nb;
        }
    }
#pragma unroll
    for (int rh = 0; rh < 2; rh++)
#pragma unroll
    for (int i = 0; i < 4; i++) {
        int m = m0 + rh*64 + ty*4 + i;
#pragma unroll
        for (int ch = 0; ch < 2; ch++) {
            int n = n0 + ch*64 + tx*4;
            float4 v;
            v.x = acc[rh][ch][i][0]; v.y = acc[rh][ch][i][1];
            v.z = acc[rh][ch][i][2]; v.w = acc[rh][ch][i][3];
            float4 bz = *(const float4*)&bias[n];
            v.x += bz.x; v.y += bz.y; v.z += bz.z; v.w += bz.w;
            *(float4*)&C[(size_t)m*N + n] = v;
            __nv_bfloat162 h0, h1, l0, l1;
            h0.x = __float2bfloat16(v.x); h0.y = __float2bfloat16(v.y);
            h1.x = __float2bfloat16(v.z); h1.y = __float2bfloat16(v.w);
            l0.x = __float2bfloat16(v.x - __bfloat162float(h0.x));
            l0.y = __float2bfloat16(v.y - __bfloat162float(h0.y));
            l1.x = __float2bfloat16(v.z - __bfloat162float(h1.x));
            l1.y = __float2bfloat16(v.w - __bfloat162float(h1.y));
            *(__nv_bfloat162*)&Phi[(size_t)m*N + n]     = h0;
            *(__nv_bfloat162*)&Phi[(size_t)m*N + n + 2] = h1;
            *(__nv_bfloat162*)&Plo[(size_t)m*N + n]     = l0;
            *(__nv_bfloat162*)&Plo[(size_t)m*N + n + 2] = l1;
        }
    }
}

// ------------------------- persistent GRU recurrence (R13/R14, unchanged) ---
__global__ void __launch_bounds__(512, 1)
gru_persistent(const float* __restrict__ bhh_a, const float* __restrict__ bhh_b,
               const float* __restrict__ alpha_w) {
    extern __shared__ __align__(16) unsigned char smem[];
    const int tid = threadIdx.x, lane = tid & 31, wid = tid >> 5;
    const int wm = wid >> 2, wn = wid & 3;
    const int gid = blockIdx.x;
    const int gru = gid & 1, cb = (gid >> 1) & 3, q = gid >> 3;
    const uint32_t sbase = smem_u32(smem);

    {
        const __nv_bfloat16* Whi = g_whi[gru];
        const __nv_bfloat16* Wlo = g_wlo[gru];
        for (int u = tid; u < 12288; u += 512) {
            int nrow7 = u & 7;
            int kh = (u >> 3) & 1;
            int nh = (u >> 4) & 1;
            int ng16 = (u >> 5) % 12;
            int pc = (u >> 5) / 12;
            int p = pc & 1, c = pc >> 1;
            int Rg = (ng16 >> 2)*256 + cb*64 + (ng16 & 3)*16 + nh*8 + nrow7;
            const __nv_bfloat16* src = (p ? Wlo : Whi) + (size_t)Rg*256 + c*16 + kh*8;
            uint32_t dst = (uint32_t)(c*12288 + p*6144 + ng16*512 + nh*256 + kh*128 + nrow7*16);
            *(uint4*)(smem + dst) = *(const uint4*)src;
        }
    }
    __syncthreads();

    const uint32_t lpiece = (uint32_t)((lane >> 4)*256 + ((lane >> 3) & 1)*128 + (lane & 7)*16);
    uint32_t wboff[2][3];
#pragma unroll
    for (int p = 0; p < 2; p++)
#pragma unroll
    for (int g = 0; g < 3; g++)
        wboff[p][g] = (uint32_t)(p*6144 + (g*4 + wn)*512) + lpiece;

    const float* bhh = gru ? bhh_b : bhh_a;
    const float* gx  = gru ? g_gxb : g_gxa;
    const int g8 = lane >> 2, t2 = (lane & 3)*2;
    unsigned* mybar = &g_bars[(gru*18 + q)*32];
    const uint32_t abuf0 = sbase + SMEM_A_OFF;

#pragma unroll 1
    for (int step = 0; step < 63; step++) {
        const int par = step & 1;
        const int a2 = 2*step;
        int d = q - (a2 % 18); if (d < 0) d += 18;
        const int cfirst = a2 + d;
        if (cfirst >= 126) break;
        const int ng = 1 + (126 - cfirst - 1)/18;
        const int R = ng*16;
        {
            const __nv_bfloat16* Hhi = g_hhi[gru][par];
            const __nv_bfloat16* Hlo = g_hlo[gru][par];
            int kch;
            if (R <= 16) kch = 16; else if (R <= 32) kch = 8;
            else if (R <= 64) kch = 4; else kch = 2;
            const int nchunks = 16 / kch;
            const int KC = kch * 16;
            const uint32_t ks_str = (uint32_t)(ng*1024);
            const uint32_t pl_str = (uint32_t)(ng*512);

            const int Nit = 4*R*kch;
            uint32_t sdst[2]; const __nv_bfloat16* ssrc[2]; bool sval[2];
#pragma unroll
            for (int it = 0; it < 2; it++) {
                int u = tid + it*512;
                sval[it] = (u < Nit);
                int uu = sval[it] ? u : 0;
                int r7 = uu & 7; uu >>= 3;
                int r8 = uu & 1; uu >>= 1;
                int k8 = uu & 1; uu >>= 1;
                int g  = uu % ng; uu /= ng;
                int p  = uu & 1; uu >>= 1;
                int s  = uu;
                sdst[it] = (uint32_t)(s*(int)ks_str + p*(int)pl_str + g*512 + k8*256 + r8*128 + r7*16);
                int row = (cfirst + g*18)*16 + r8*8 + r7;
                ssrc[it] = (p ? Hlo : Hhi) + (size_t)row*H_ + s*16 + k8*8;
            }

            float acc[3][2][2][4] = {};
            if (sval[0]) CP_ASYNC16(abuf0 + sdst[0], ssrc[0]);
            if (sval[1]) CP_ASYNC16(abuf0 + sdst[1], ssrc[1]);
            CP_COMMIT();
#pragma unroll 1
            for (int cc = 0; cc < nchunks; cc++) {
                CP_WAIT0();
                __syncthreads();
                if (cc + 1 < nchunks) {
                    uint32_t bb = abuf0 + (uint32_t)(((cc+1)&1)*ABUF_STRIDE);
                    int ko = (cc+1)*KC;
                    if (sval[0]) CP_ASYNC16(bb + sdst[0], ssrc[0] + ko);
                    if (sval[1]) CP_ASYNC16(bb + sdst[1], ssrc[1] + ko);
                    CP_COMMIT();
                }
                if (2*wm < ng) {
                    const bool two = (2*wm + 1 < ng);
                    const uint32_t bufb = abuf0 + (uint32_t)((cc&1)*ABUF_STRIDE);
#pragma unroll 1
                    for (int s = 0; s < kch; s++) {
                        uint32_t a0 = bufb + (uint32_t)s*ks_str + (uint32_t)((wm*2)*512) + lpiece;
                        uint32_t Ah[2][4], Al[2][4];
                        ldsm4(Ah[0], a0);
                        ldsm4(Al[0], a0 + pl_str);
                        if (two) { ldsm4(Ah[1], a0 + 512); ldsm4(Al[1], a0 + 512 + pl_str); }
                        const uint32_t wbc = sbase + (uint32_t)((cc*kch + s)*12288);
#pragma unroll
                        for (int g = 0; g < 3; g++) {
                            uint32_t Bh[4], Bl[4];
                            ldsm4(Bh, wbc + wboff[0][g]);
                            ldsm4(Bl, wbc + wboff[1][g]);
#pragma unroll
                            for (int j = 0; j < 2; j++) {
                                mma16816(acc[g][0][j], Ah[0], &Bh[j*2]);
                                mma16816(acc[g][0][j], Ah[0], &Bl[j*2]);
                                mma16816(acc[g][0][j], Al[0], &Bh[j*2]);
                            }
                            if (two) {
#pragma unroll
                                for (int j = 0; j < 2; j++) {
                                    mma16816(acc[g][1][j], Ah[1], &Bh[j*2]);
                                    mma16816(acc[g][1][j], Ah[1], &Bl[j*2]);
                                    mma16816(acc[g][1][j], Al[1], &Bh[j*2]);
                                }
                            }
                        }
                    }
                }
            }
            // ---- epilogue ----
            __nv_bfloat16* Hhi_n = g_hhi[gru][par^1];
            __nv_bfloat16* Hlo_n = g_hlo[gru][par^1];
            const size_t offk = (size_t)32*(63*step - (step*(step-1))/2);
#pragma unroll
            for (int i = 0; i < 2; i++) {
                if (2*wm + i >= ng) continue;
#pragma unroll
                for (int half = 0; half < 2; half++) {
                    int grow = (cfirst + (2*wm + i)*18)*16 + g8 + half*8;
                    int gxrow = grow - step*32;
                    const float* gxr = gx + (size_t)gxrow*(3*H_);
                    size_t prow = offk + gxrow;
                    float row_part = 0.f;
#pragma unroll
                    for (int j = 0; j < 2; j++) {
                        int cc2 = cb*64 + wn*16 + j*8 + t2;
                        float2 gx_r = *(const float2*)&gxr[cc2];
                        float2 gx_z = *(const float2*)&gxr[H_ + cc2];
                        float2 gx_n = *(const float2*)&gxr[2*H_ + cc2];
                        float2 bh_r = *(const float2*)&bhh[cc2];
                        float2 bh_z = *(const float2*)&bhh[H_ + cc2];
                        float2 bh_n = *(const float2*)&bhh[2*H_ + cc2];
                        __nv_bfloat162 ho_hi = *(const __nv_bfloat162*)&Hhi[(size_t)grow*H_ + cc2];
                        __nv_bfloat162 ho_lo = *(const __nv_bfloat162*)&Hlo[(size_t)grow*H_ + cc2];
                        float hn2[2];
#pragma unroll
                        for (int u = 0; u < 2; u++) {
                            int ai = half*2 + u;
                            float rp = acc[0][i][j][ai] + (u ? bh_r.y : bh_r.x) + (u ? gx_r.y : gx_r.x);
                            float zp = acc[1][i][j][ai] + (u ? bh_z.y : bh_z.x) + (u ? gx_z.y : gx_z.x);
                            float np = acc[2][i][j][ai] + (u ? bh_n.y : bh_n.x);
                            float r = 1.f/(1.f + expf(-rp));
                            float z = 1.f/(1.f + expf(-zp));
                            float n = tanhf((u ? gx_n.y : gx_n.x) + r*np);
                            float hold = __bfloat162float(u ? ho_hi.y : ho_hi.x)
                                       + __bfloat162float(u ? ho_lo.y : ho_lo.x);
                            hn2[u] = (1.f - z)*n + z*hold;
                        }
                        __nv_bfloat162 hi2, lo2;
                        hi2.x = __float2bfloat16(hn2[0]); hi2.y = __float2bfloat16(hn2[1]);
                        lo2.x = __float2bfloat16(hn2[0] - __bfloat162float(hi2.x));
                        lo2.y = __float2bfloat16(hn2[1] - __bfloat162float(hi2.y));
                        *(__nv_bfloat162*)&Hhi_n[(size_t)grow*H_ + cc2] = hi2;
                        *(__nv_bfloat162*)&Hlo_n[(size_t)grow*H_ + cc2] = lo2;
                        if (gru == 0) {
                            float2 aw = *(const float2*)&alpha_w[cc2];
                            row_part += 0.5f*hn2[0]*aw.x + 0.5f*hn2[1]*aw.y;
                        } else {
                            float f0 = 0.5f*hn2[0], f1 = 0.5f*hn2[1];
                            __nv_bfloat162 fh, fl;
                            fh.x = __float2bfloat16(f0); fh.y = __float2bfloat16(f1);
                            fl.x = __float2bfloat16(f0 - __bfloat162float(fh.x));
                            fl.y = __float2bfloat16(f1 - __bfloat162float(fh.y));
                            *(__nv_bfloat162*)&g_fbhi[prow*H_ + cc2] = fh;
                            *(__nv_bfloat162*)&g_fblo[prow*H_ + cc2] = fl;
                        }
                    }
                    if (gru == 0) {
                        row_part += __shfl_xor_sync(0xffffffffu, row_part, 1);
                        row_part += __shfl_xor_sync(0xffffffffu, row_part, 2);
                        if ((lane & 3) == 0)
                            g_prep[prow*16 + cb*4 + wn] = row_part;
                    }
                }
            }
        }
        __syncthreads();
        if (tid == 0) {
            __threadfence();
            atomicAdd(mybar, 1u);
            const unsigned target = 4u*(unsigned)(step+1);
            unsigned v;
            do {
                asm volatile("ld.acquire.gpu.u32 %0, [%1];" : "=r"(v) : "l"(mybar));
            } while (v < target);
        }
        __syncthreads();
    }
}

// ------------------------- mma dense GEMM (M x ldc, K=256) ------------------
__global__ void __launch_bounds__(512, 1)
dense_mma(const __nv_bfloat16* __restrict__ Ahi, const __nv_bfloat16* __restrict__ Alo,
          const __nv_bfloat16* __restrict__ Bthi, const __nv_bfloat16* __restrict__ Btlo,
          const float* __restrict__ bias, int act, int ldc, float* __restrict__ outf,
          __nv_bfloat16* __restrict__ Phi, __nv_bfloat16* __restrict__ Plo) {
    extern __shared__ __align__(16) unsigned char smem[];
    const int tid = threadIdx.x, lane = tid & 31, wid = tid >> 5;
    const int wm = wid & 3, wn = wid >> 2;
    const int colbase = blockIdx.y * 128;
    const int rowbase = blockIdx.x * 128;
    const uint32_t sbase = smem_u32(smem);

    float acc[2][4][4] = {};

    const int a_r = lane & 15, a_c16 = ((lane >> 4) & 1) * 16;
    const int b_r = (lane & 7) + ((lane >> 4) & 1) * 8, b_c16 = (lane & 8) * 2;
    uint32_t aob[2][2], bob[2][2];
#pragma unroll
    for (int p = 0; p < 2; p++) {
#pragma unroll
        for (int i = 0; i < 2; i++)
            aob[p][i] = (uint32_t)(p*6144 + (wm*32 + i*16 + a_r)*48 + a_c16);
#pragma unroll
        for (int h2 = 0; h2 < 2; h2++)
            bob[p][h2] = (uint32_t)(p*6144 + (wn*32 + h2*16 + b_r)*48 + b_c16);
    }

    const int st_q = tid & 1, st_r = (tid >> 1) & 127, st_p = tid >> 8;
    const uint32_t stoff = (uint32_t)(st_p*6144 + st_r*48 + st_q*16);
    const __nv_bfloat16* srcA = (st_p ? Alo : Ahi) + (size_t)(rowbase + st_r)*256 + st_q*8;
    const __nv_bfloat16* srcB = (st_p ? Btlo : Bthi) + (size_t)(colbase + st_r)*256 + st_q*8;

#pragma unroll
    for (int sub = 0; sub < 2; sub++) {
        CP_ASYNC16(sbase + sub*12288u + stoff, srcA + sub*16);
        CP_ASYNC16(sbase + 24576u + sub*12288u + stoff, srcB + sub*16);
    }
    CP_COMMIT();

#pragma unroll 1
    for (int c = 0; c < 8; c++) {
        CP_WAIT0();
        __syncthreads();
        if (c < 7) {
            uint32_t bb = sbase + (uint32_t)(((c+1)&1)*DCH2);
            int ko = (c+1)*32;
#pragma unroll
            for (int sub = 0; sub < 2; sub++) {
                CP_ASYNC16(bb + sub*12288u + stoff, srcA + ko + sub*16);
                CP_ASYNC16(bb + 24576u + sub*12288u + stoff, srcB + ko + sub*16);
            }
            CP_COMMIT();
        }
        const uint32_t bufb = sbase + (uint32_t)((c&1)*DCH2);
#pragma unroll
        for (int sub = 0; sub < 2; sub++) {
            const uint32_t ab = bufb + sub*12288u;
            const uint32_t bbB = bufb + 24576u + sub*12288u;
            uint32_t Ah[2][4], Al[2][4], Bh[8], Bl[8];
            ldsm4(Ah[0], ab + aob[0][0]); ldsm4(Ah[1], ab + aob[0][1]);
            ldsm4(Al[0], ab + aob[1][0]); ldsm4(Al[1], ab + aob[1][1]);
            ldsm4(Bh,   bbB + bob[0][0]); ldsm4(Bh+4, bbB + bob[0][1]);
            ldsm4(Bl,   bbB + bob[1][0]); ldsm4(Bl+4, bbB + bob[1][1]);
#pragma unroll
            for (int i = 0; i < 2; i++)
#pragma unroll
            for (int j = 0; j < 4; j++) {
                mma16816(acc[i][j], Ah[i], &Bh[j*2]);
                mma16816(acc[i][j], Ah[i], &Bl[j*2]);
                mma16816(acc[i][j], Al[i], &Bh[j*2]);
            }
        }
    }

    const int g8 = lane >> 2, t2 = (lane & 3)*2;
#pragma unroll
    for (int i = 0; i < 2; i++)
#pragma unroll
    for (int half = 0; half < 2; half++) {
        int grow = rowbase + wm*32 + i*16 + g8 + half*8;
#pragma unroll
        for (int j = 0; j < 4; j++) {
            int cc = colbase + wn*32 + j*8 + t2;
            float v0 = acc[i][j][half*2 + 0];
            float v1 = acc[i][j][half*2 + 1];
            if (bias) { v0 += bias[cc]; v1 += bias[cc+1]; }
            if (act == 1) { v0 = tanhf(v0); v1 = tanhf(v1); }
            float2 f2; f2.x = v0; f2.y = v1;
            *(float2*)&outf[(size_t)grow*ldc + cc] = f2;
            if (Phi) {
                __nv_bfloat162 hi2, lo2;
                hi2.x = __float2bfloat16(v0); hi2.y = __float2bfloat16(v1);
                lo2.x = __float2bfloat16(v0 - __bfloat162float(hi2.x));
                lo2.y = __float2bfloat16(v1 - __bfloat162float(hi2.y));
                *(__nv_bfloat162*)&Phi[(size_t)grow*ldc + cc] = hi2;
                *(__nv_bfloat162*)&Plo[(size_t)grow*ldc + cc] = lo2;
            }
        }
    }
}

// ------------------------- reduce (alpha fused) -----------------------------
__global__ void reduce_kernel(const float* __restrict__ x,
                              const float* __restrict__ out_w,
                              const float* __restrict__ out_b,
                              const float* __restrict__ alpha_b,
                              float* __restrict__ out) {
    int pb = blockIdx.x;
    int p = 62 - (pb >> 5);
    int b = pb & 31;
    int e = threadIdx.x;
    __shared__ float s_alpha[T_];
    if (e < 32) {
        int lane = e;
        float ab = alpha_b[0];
        float v0 = -1e30f, v1 = -1e30f;
        {
            int t = lane;
            if (t <= p) {
                int kk = p - t;
                int offk = 32*(63*kk - (kk*(kk-1))/2);
                size_t prow = (size_t)offk + t*32 + b;
                const float4* qq = (const float4*)&g_prep[prow*16];
                float4 s0 = qq[0], s1 = qq[1], s2 = qq[2], s3 = qq[3];
                v0 = (s0.x+s0.y+s0.z+s0.w) + (s1.x+s1.y+s1.z+s1.w)
                   + (s2.x+s2.y+s2.z+s2.w) + (s3.x+s3.y+s3.z+s3.w) + ab;
            }
        }
        {
            int t = lane + 32;
            if (t <= p) {
                int kk = p - t;
                int offk = 32*(63*kk - (kk*(kk-1))/2);
                size_t prow = (size_t)offk + t*32 + b;
                const float4* qq = (const float4*)&g_prep[prow*16];
                float4 s0 = qq[0], s1 = qq[1], s2 = qq[2], s3 = qq[3];
                v1 = (s0.x+s0.y+s0.z+s0.w) + (s1.x+s1.y+s1.z+s1.w)
                   + (s2.x+s2.y+s2.z+s2.w) + (s3.x+s3.y+s3.z+s3.w) + ab;
            }
        }
        float m = fmaxf(v0, v1);
#pragma unroll
        for (int o=16;o;o>>=1) m = fmaxf(m, __shfl_xor_sync(0xffffffffu, m, o));
        float e0 = (lane      <= p) ? expf(v0-m) : 0.f;
        float e1 = (lane + 32 <= p) ? expf(v1-m) : 0.f;
        float s = e0 + e1;
#pragma unroll
        for (int o=16;o;o>>=1) s += __shfl_xor_sync(0xffffffffu, s, o);
        float inv = 1.f/s;
        s_alpha[lane]      = e0*inv;
        s_alpha[lane + 32] = e1*inv;
    }
    __syncthreads();
    float cc = 0.f, gg = 0.f;
    for (int t = 0; t <= p; t++) {
        float a = s_alpha[t];
        int kk = p - t;
        int offk = 32*(63*kk - (kk*(kk-1))/2);
        size_t prow = (size_t)offk + t*32 + b;
        cc += a * g_beta [prow*E_ + e] * g_emb[((size_t)(t*B_+b))*E_ + e];
        gg += a * g_ebeta[prow*E_ + e] * x[((size_t)b*T_ + t)*E_ + e];
    }
    out[B_*P_ + ((size_t)(b*P_+p))*E_ + e] = gg / (float)(p+1);
    __shared__ float red[256];
    red[e] = cc * out_w[e];
    __syncthreads();
    for (int s2=128; s2; s2>>=1) { if (e < s2) red[e] += red[e+s2]; __syncthreads(); }
    if (e == 0) out[b*P_ + p] = red[0] + out_b[0];
}

// ------------------------- launch -------------------------------------------
extern "C" void kernel_launch(void* const* d_in, const int* in_sizes, int n_in,
                              void* d_out, int out_size) {
    (void)in_sizes; (void)n_in; (void)out_size;
    const float* x       = (const float*)d_in[0];
    const float* emb_w   = (const float*)d_in[1];
    const float* emb_b   = (const float*)d_in[2];
    const float* a_wih   = (const float*)d_in[3];
    const float* a_whh   = (const float*)d_in[4];
    const float* a_bih   = (const float*)d_in[5];
    const float* a_bhh   = (const float*)d_in[6];
    const float* b_wih   = (const float*)d_in[7];
    const float* b_whh   = (const float*)d_in[8];
    const float* b_bih   = (const float*)d_in[9];
    const float* b_bhh   = (const float*)d_in[10];
    const float* alpha_w = (const float*)d_in[11];
    const float* alpha_b = (const float*)d_in[12];
    const float* beta_w  = (const float*)d_in[13];
    const float* beta_b  = (const float*)d_in[14];
    const float* out_w   = (const float*)d_in[15];
    const float* out_b   = (const float*)d_in[16];
    float* out = (float*)d_out;

    cudaFuncSetAttribute(gru_persistent, cudaFuncAttributeMaxDynamicSharedMemorySize, SMEM_TOTAL_PERS);
    cudaFuncSetAttribute(dense_mma,      cudaFuncAttributeMaxDynamicSharedMemorySize, SMEM_TOTAL_DENSE);

    float *p_emb=0, *p_gxa=0, *p_gxb=0, *p_beta=0, *p_ebeta=0;
    __nv_bfloat16 *p_embhi=0, *p_emblo=0, *p_fbhi=0, *p_fblo=0;
    __nv_bfloat16 *p_bwhi=0, *p_bwlo=0, *p_mthi=0, *p_mtlo=0, *p_bhi=0, *p_blo=0;
    __nv_bfloat16 *p_wihhi=0, *p_wihlo=0;
    cudaGetSymbolAddress((void**)&p_emb,   g_emb);
    cudaGetSymbolAddress((void**)&p_embhi, g_embhi);
    cudaGetSymbolAddress((void**)&p_emblo, g_emblo);
    cudaGetSymbolAddress((void**)&p_gxa,   g_gxa);
    cudaGetSymbolAddress((void**)&p_gxb,   g_gxb);
    cudaGetSymbolAddress((void**)&p_beta,  g_beta);
    cudaGetSymbolAddress((void**)&p_ebeta, g_ebeta);
    cudaGetSymbolAddress((void**)&p_fbhi,  g_fbhi);
    cudaGetSymbolAddress((void**)&p_fblo,  g_fblo);
    cudaGetSymbolAddress((void**)&p_bwhi,  g_bwhi);
    cudaGetSymbolAddress((void**)&p_bwlo,  g_bwlo);
    cudaGetSymbolAddress((void**)&p_mthi,  g_mthi);
    cudaGetSymbolAddress((void**)&p_mtlo,  g_mtlo);
    cudaGetSymbolAddress((void**)&p_bhi,   g_betahi);
    cudaGetSymbolAddress((void**)&p_blo,   g_betalo);
    cudaGetSymbolAddress((void**)&p_wihhi, g_wihhi);
    cudaGetSymbolAddress((void**)&p_wihlo, g_wihlo);

    prep_all<<<(int)((PREP_TOTAL + 255)/256), 256>>>(a_whh, b_whh, a_wih, b_wih,
                                                     beta_w, emb_w, out_w);

    sgemm128<<<dim3((T_*B_)/128, E_/128), 256>>>(x, emb_w, emb_b, p_emb, E_,
                                                 p_embhi, p_emblo);

    dense_mma<<<dim3((T_*B_)/128, 6), 512, SMEM_TOTAL_DENSE>>>(
        p_embhi, p_emblo, p_wihhi, p_wihlo, a_bih, 0, 3*H_, p_gxa,
        (__nv_bfloat16*)0, (__nv_bfloat16*)0);
    dense_mma<<<dim3((T_*B_)/128, 6), 512, SMEM_TOTAL_DENSE>>>(
        p_embhi, p_emblo, p_wihhi + (size_t)3*H_*E_, p_wihlo + (size_t)3*H_*E_,
        b_bih, 0, 3*H_, p_gxb, (__nv_bfloat16*)0, (__nv_bfloat16*)0);

    gru_persistent<<<NCTA_PERS, 512, SMEM_TOTAL_PERS>>>(a_bhh, b_bhh, alpha_w);

    dense_mma<<<dim3(NPACK_/128, 2), 512, SMEM_TOTAL_DENSE>>>(
        p_fbhi, p_fblo, p_bwhi, p_bwlo, beta_b, 1, E_, p_beta, p_bhi, p_blo);
    dense_mma<<<dim3(NPACK_/128, 2), 512, SMEM_TOTAL_DENSE>>>(
        p_bhi, p_blo, p_mthi, p_mtlo, (const float*)0, 0, E_, p_ebeta,
        (__nv_bfloat16*)0, (__nv_bfloat16*)0);

    reduce_kernel<<<PB_, 256>>>(x, out_w, out_b, alpha_b, out);
}

// round 16
// speedup vs baseline: 1.3702x; 1.0107x over previous
#include <cuda_runtime.h>
#include <cuda_bf16.h>
#include <math.h>
#include <stdint.h>

#define B_ 32
#define T_ 64
#define E_ 256
#define H_ 256
#define P_ 63
#define PB_ 2016
#define NPACK_ 64512

#define NCTA_PERS 144
#define NQ_ 18
#define SMEM_A_OFF   196608
#define ABUF_STRIDE  16384
#define SMEM_TOTAL_PERS (196608 + 2*ABUF_STRIDE)   // 229376

#define DCH2 49152
#define SMEM_TOTAL_DENSE (2*DCH2)      // 98304

// ------------------------- scratch (device globals) -------------------------
__device__ float g_emb[T_*B_*E_];
__device__ __nv_bfloat16 g_embhi[T_*B_*E_];
__device__ __nv_bfloat16 g_emblo[T_*B_*E_];
__device__ float g_gxa[T_*B_*3*H_];
__device__ float g_gxb[T_*B_*3*H_];
__device__ __nv_bfloat16 g_hhi[2][2][PB_*H_];
__device__ __nv_bfloat16 g_hlo[2][2][PB_*H_];
__device__ __nv_bfloat16 g_whi[2][3*H_*H_];
__device__ __nv_bfloat16 g_wlo[2][3*H_*H_];
__device__ __nv_bfloat16 g_wihhi[2][3*H_*E_];
__device__ __nv_bfloat16 g_wihlo[2][3*H_*E_];
__device__ __nv_bfloat16 g_bwhi[E_*H_];
__device__ __nv_bfloat16 g_bwlo[E_*H_];
__device__ __nv_bfloat16 g_mthi[E_*E_];
__device__ __nv_bfloat16 g_mtlo[E_*E_];
__device__ float g_prep[(size_t)NPACK_*16];
__device__ __nv_bfloat16 g_fbhi[(size_t)NPACK_*H_];
__device__ __nv_bfloat16 g_fblo[(size_t)NPACK_*H_];
__device__ __nv_bfloat16 g_betahi[(size_t)NPACK_*E_];
__device__ __nv_bfloat16 g_betalo[(size_t)NPACK_*E_];
__device__ float g_ebeta[(size_t)NPACK_*E_];
__device__ unsigned g_bars[36*32];

// ------------------------- helpers ------------------------------------------
__device__ __forceinline__ uint32_t smem_u32(const void* p) {
    uint32_t a;
    asm("{ .reg .u64 t; cvta.to.shared.u64 t, %1; cvt.u32.u64 %0, t; }" : "=r"(a) : "l"(p));
    return a;
}
__device__ __forceinline__ void ldsm4(uint32_t* r, uint32_t addr) {
    asm volatile("ldmatrix.sync.aligned.m8n8.x4.shared.b16 {%0,%1,%2,%3}, [%4];"
        : "=r"(r[0]), "=r"(r[1]), "=r"(r[2]), "=r"(r[3]) : "r"(addr));
}
__device__ __forceinline__ void mma16816(float* d, const uint32_t* a, const uint32_t* b) {
    asm volatile("mma.sync.aligned.m16n8k16.row.col.f32.bf16.bf16.f32 "
        "{%0,%1,%2,%3}, {%4,%5,%6,%7}, {%8,%9}, {%0,%1,%2,%3};"
        : "+f"(d[0]), "+f"(d[1]), "+f"(d[2]), "+f"(d[3])
        : "r"(a[0]), "r"(a[1]), "r"(a[2]), "r"(a[3]), "r"(b[0]), "r"(b[1]));
}
#define CP_ASYNC16(dst, src) \
    asm volatile("cp.async.cg.shared.global [%0], [%1], 16;" :: "r"(dst), "l"(src))
#define CP_COMMIT() asm volatile("cp.async.commit_group;")
#define CP_WAIT0()  asm volatile("cp.async.wait_group 0;")

// ------------------------- merged prep kernel --------------------------------
__global__ void prep_all(const float* __restrict__ wa, const float* __restrict__ wb,
                         const float* __restrict__ wia, const float* __restrict__ wib,
                         const float* __restrict__ bw,
                         const float* __restrict__ emb_w, const float* __restrict__ out_w) {
    long idx = (long)blockIdx.x*256 + threadIdx.x;
    const long Z = 2L*PB_*H_;
    if (idx < Z) {
        int gru = idx >= (long)PB_*H_;
        long r = idx - (long)gru*((long)PB_*H_);
        int arr = r >= (long)PB_*H_/2;
        long o = r - (long)arr*((long)PB_*H_/2);
        uint32_t* base = arr ? (uint32_t*)g_hlo[gru][0] : (uint32_t*)g_hhi[gru][0];
        base[o] = 0u;
        return;
    }
    idx -= Z;
    if (idx < 36*32) { g_bars[idx] = 0u; return; }
    idx -= 36*32;
    if (idx < 2L*768*256) {
        int k = (int)(idx & 255); int r = (int)((idx >> 8) % 768); int gru = (int)(idx/(768*256));
        float v = (gru ? wb : wa)[r*256 + k];
        __nv_bfloat16 hi = __float2bfloat16(v);
        g_whi[gru][r*256 + k] = hi;
        g_wlo[gru][r*256 + k] = __float2bfloat16(v - __bfloat162float(hi));
        return;
    }
    idx -= 2L*768*256;
    if (idx < 2L*768*256) {
        int k = (int)(idx & 255); int r = (int)((idx >> 8) % 768); int gru = (int)(idx/(768*256));
        float v = (gru ? wib : wia)[r*256 + k];
        __nv_bfloat16 hi = __float2bfloat16(v);
        g_wihhi[gru][r*256 + k] = hi;
        g_wihlo[gru][r*256 + k] = __float2bfloat16(v - __bfloat162float(hi));
        return;
    }
    idx -= 2L*768*256;
    if (idx < 65536) {
        float v = bw[idx];
        __nv_bfloat16 hi = __float2bfloat16(v);
        g_bwhi[idx] = hi;
        g_bwlo[idx] = __float2bfloat16(v - __bfloat162float(hi));
        return;
    }
    idx -= 65536;
    if (idx < 65536) {
        int i = (int)(idx >> 8), e = (int)(idx & 255);
        float v = out_w[e] * emb_w[e*256 + i];
        __nv_bfloat16 hi = __float2bfloat16(v);
        g_mthi[idx] = hi;
        g_mtlo[idx] = __float2bfloat16(v - __bfloat162float(hi));
    }
}
#define PREP_TOTAL (2L*PB_*H_ + 36*32 + 2L*768*256 + 2L*768*256 + 65536 + 65536)

// ------------------------- fp32 SGEMM (emb, emits planes) -------------------
__global__ void __launch_bounds__(256, 2)
sgemm128(const float* __restrict__ A, const float* __restrict__ Bt,
         const float* __restrict__ bias, float* __restrict__ C, int N,
         __nv_bfloat16* __restrict__ Phi, __nv_bfloat16* __restrict__ Plo) {
    __shared__ float As[2][8][128];
    __shared__ float Bs[2][8][128];
    const int tid = threadIdx.x;
    const int m0 = blockIdx.x*128, n0 = blockIdx.y*128;
    const int tx = tid & 15, ty = tid >> 4;
    const int lr = tid >> 1;
    const int ks = (tid & 1) * 4;
    const float* pA;
    { int m = m0 + lr; int t = m >> 5, b = m & 31; pA = A + ((size_t)b*T_ + t)*E_ + ks; }
    const float* pB = Bt + (size_t)(n0 + lr) * 256 + ks;
    float acc[2][2][4][4] = {};
    float4 va = *(const float4*)pA;
    float4 vb = *(const float4*)pB;
    {
        const float* f = (const float*)&va;
#pragma unroll
        for (int j = 0; j < 4; j++) As[0][ks+j][lr] = f[j];
        f = (const float*)&vb;
#pragma unroll
        for (int j = 0; j < 4; j++) Bs[0][ks+j][lr] = f[j];
    }
    __syncthreads();
    int buf = 0;
#pragma unroll 1
    for (int c = 0; c < 32; c++) {
        if (c < 31) {
            int off = (c+1)*8;
            va = *(const float4*)(pA + off);
            vb = *(const float4*)(pB + off);
        }
#pragma unroll
        for (int kk = 0; kk < 8; kk++) {
            float4 a0 = *(const float4*)&As[buf][kk][ty*4];
            float4 a1 = *(const float4*)&As[buf][kk][ty*4 + 64];
            float4 b0 = *(const float4*)&Bs[buf][kk][tx*4];
            float4 b1 = *(const float4*)&Bs[buf][kk][tx*4 + 64];
            float aa[2][4] = {{a0.x,a0.y,a0.z,a0.w},{a1.x,a1.y,a1.z,a1.w}};
            float bb[2][4] = {{b0.x,b0.y,b0.z,b0.w},{b1.x,b1.y,b1.z,b1.w}};
#pragma unroll
            for (int rh = 0; rh < 2; rh++)
#pragma unroll
            for (int i = 0; i < 4; i++)
#pragma unroll
            for (int ch = 0; ch < 2; ch++)
#pragma unroll
            for (int j = 0; j < 4; j++)
                acc[rh][ch][i][j] = fmaf(aa[rh][i], bb[ch][j], acc[rh][ch][i][j]);
        }
        if (c < 31) {
            int nb = buf ^ 1;
            const float* f = (const float*)&va;
#pragma unroll
            for (int j = 0; j < 4; j++) As[nb][ks+j][lr] = f[j];
            f = (const float*)&vb;
#pragma unroll
            for (int j = 0; j < 4; j++) Bs[nb][ks+j][lr] = f[j];
            __syncthreads();
            buf = nb;
        }
    }
#pragma unroll
    for (int rh = 0; rh < 2; rh++)
#pragma unroll
    for (int i = 0; i < 4; i++) {
        int m = m0 + rh*64 + ty*4 + i;
#pragma unroll
        for (int ch = 0; ch < 2; ch++) {
            int n = n0 + ch*64 + tx*4;
            float4 v;
            v.x = acc[rh][ch][i][0]; v.y = acc[rh][ch][i][1];
            v.z = acc[rh][ch][i][2]; v.w = acc[rh][ch][i][3];
            float4 bz = *(const float4*)&bias[n];
            v.x += bz.x; v.y += bz.y; v.z += bz.z; v.w += bz.w;
            *(float4*)&C[(size_t)m*N + n] = v;
            __nv_bfloat162 h0, h1, l0, l1;
            h0.x = __float2bfloat16(v.x); h0.y = __float2bfloat16(v.y);
            h1.x = __float2bfloat16(v.z); h1.y = __float2bfloat16(v.w);
            l0.x = __float2bfloat16(v.x - __bfloat162float(h0.x));
            l0.y = __float2bfloat16(v.y - __bfloat162float(h0.y));
            l1.x = __float2bfloat16(v.z - __bfloat162float(h1.x));
            l1.y = __float2bfloat16(v.w - __bfloat162float(h1.y));
            *(__nv_bfloat162*)&Phi[(size_t)m*N + n]     = h0;
            *(__nv_bfloat162*)&Phi[(size_t)m*N + n + 2] = h1;
            *(__nv_bfloat162*)&Plo[(size_t)m*N + n]     = l0;
            *(__nv_bfloat162*)&Plo[(size_t)m*N + n + 2] = l1;
        }
    }
}

// ------------------------- persistent GRU recurrence (unchanged) ------------
__global__ void __launch_bounds__(512, 1)
gru_persistent(const float* __restrict__ bhh_a, const float* __restrict__ bhh_b,
               const float* __restrict__ alpha_w) {
    extern __shared__ __align__(16) unsigned char smem[];
    const int tid = threadIdx.x, lane = tid & 31, wid = tid >> 5;
    const int wm = wid >> 2, wn = wid & 3;
    const int gid = blockIdx.x;
    const int gru = gid & 1, cb = (gid >> 1) & 3, q = gid >> 3;
    const uint32_t sbase = smem_u32(smem);

    {
        const __nv_bfloat16* Whi = g_whi[gru];
        const __nv_bfloat16* Wlo = g_wlo[gru];
        for (int u = tid; u < 12288; u += 512) {
            int nrow7 = u & 7;
            int kh = (u >> 3) & 1;
            int nh = (u >> 4) & 1;
            int ng16 = (u >> 5) % 12;
            int pc = (u >> 5) / 12;
            int p = pc & 1, c = pc >> 1;
            int Rg = (ng16 >> 2)*256 + cb*64 + (ng16 & 3)*16 + nh*8 + nrow7;
            const __nv_bfloat16* src = (p ? Wlo : Whi) + (size_t)Rg*256 + c*16 + kh*8;
            uint32_t dst = (uint32_t)(c*12288 + p*6144 + ng16*512 + nh*256 + kh*128 + nrow7*16);
            *(uint4*)(smem + dst) = *(const uint4*)src;
        }
    }
    __syncthreads();

    const uint32_t lpiece = (uint32_t)((lane >> 4)*256 + ((lane >> 3) & 1)*128 + (lane & 7)*16);
    uint32_t wboff[2][3];
#pragma unroll
    for (int p = 0; p < 2; p++)
#pragma unroll
    for (int g = 0; g < 3; g++)
        wboff[p][g] = (uint32_t)(p*6144 + (g*4 + wn)*512) + lpiece;

    const float* bhh = gru ? bhh_b : bhh_a;
    const float* gx  = gru ? g_gxb : g_gxa;
    const int g8 = lane >> 2, t2 = (lane & 3)*2;
    unsigned* mybar = &g_bars[(gru*18 + q)*32];
    const uint32_t abuf0 = sbase + SMEM_A_OFF;

#pragma unroll 1
    for (int step = 0; step < 63; step++) {
        const int par = step & 1;
        const int a2 = 2*step;
        int d = q - (a2 % 18); if (d < 0) d += 18;
        const int cfirst = a2 + d;
        if (cfirst >= 126) break;
        const int ng = 1 + (126 - cfirst - 1)/18;
        const int R = ng*16;
        {
            const __nv_bfloat16* Hhi = g_hhi[gru][par];
            const __nv_bfloat16* Hlo = g_hlo[gru][par];
            int kch;
            if (R <= 16) kch = 16; else if (R <= 32) kch = 8;
            else if (R <= 64) kch = 4; else kch = 2;
            const int nchunks = 16 / kch;
            const int KC = kch * 16;
            const uint32_t ks_str = (uint32_t)(ng*1024);
            const uint32_t pl_str = (uint32_t)(ng*512);

            const int Nit = 4*R*kch;
            uint32_t sdst[2]; const __nv_bfloat16* ssrc[2]; bool sval[2];
#pragma unroll
            for (int it = 0; it < 2; it++) {
                int u = tid + it*512;
                sval[it] = (u < Nit);
                int uu = sval[it] ? u : 0;
                int r7 = uu & 7; uu >>= 3;
                int r8 = uu & 1; uu >>= 1;
                int k8 = uu & 1; uu >>= 1;
                int g  = uu % ng; uu /= ng;
                int p  = uu & 1; uu >>= 1;
                int s  = uu;
                sdst[it] = (uint32_t)(s*(int)ks_str + p*(int)pl_str + g*512 + k8*256 + r8*128 + r7*16);
                int row = (cfirst + g*18)*16 + r8*8 + r7;
                ssrc[it] = (p ? Hlo : Hhi) + (size_t)row*H_ + s*16 + k8*8;
            }

            float acc[3][2][2][4] = {};
            if (sval[0]) CP_ASYNC16(abuf0 + sdst[0], ssrc[0]);
            if (sval[1]) CP_ASYNC16(abuf0 + sdst[1], ssrc[1]);
            CP_COMMIT();
#pragma unroll 1
            for (int cc = 0; cc < nchunks; cc++) {
                CP_WAIT0();
                __syncthreads();
                if (cc + 1 < nchunks) {
                    uint32_t bb = abuf0 + (uint32_t)(((cc+1)&1)*ABUF_STRIDE);
                    int ko = (cc+1)*KC;
                    if (sval[0]) CP_ASYNC16(bb + sdst[0], ssrc[0] + ko);
                    if (sval[1]) CP_ASYNC16(bb + sdst[1], ssrc[1] + ko);
                    CP_COMMIT();
                }
                if (2*wm < ng) {
                    const bool two = (2*wm + 1 < ng);
                    const uint32_t bufb = abuf0 + (uint32_t)((cc&1)*ABUF_STRIDE);
#pragma unroll 1
                    for (int s = 0; s < kch; s++) {
                        uint32_t a0 = bufb + (uint32_t)s*ks_str + (uint32_t)((wm*2)*512) + lpiece;
                        uint32_t Ah[2][4], Al[2][4];
                        ldsm4(Ah[0], a0);
                        ldsm4(Al[0], a0 + pl_str);
                        if (two) { ldsm4(Ah[1], a0 + 512); ldsm4(Al[1], a0 + 512 + pl_str); }
                        const uint32_t wbc = sbase + (uint32_t)((cc*kch + s)*12288);
#pragma unroll
                        for (int g = 0; g < 3; g++) {
                            uint32_t Bh[4], Bl[4];
                            ldsm4(Bh, wbc + wboff[0][g]);
                            ldsm4(Bl, wbc + wboff[1][g]);
#pragma unroll
                            for (int j = 0; j < 2; j++) {
                                mma16816(acc[g][0][j], Ah[0], &Bh[j*2]);
                                mma16816(acc[g][0][j], Ah[0], &Bl[j*2]);
                                mma16816(acc[g][0][j], Al[0], &Bh[j*2]);
                            }
                            if (two) {
#pragma unroll
                                for (int j = 0; j < 2; j++) {
                                    mma16816(acc[g][1][j], Ah[1], &Bh[j*2]);
                                    mma16816(acc[g][1][j], Ah[1], &Bl[j*2]);
                                    mma16816(acc[g][1][j], Al[1], &Bh[j*2]);
                                }
                            }
                        }
                    }
                }
            }
            // ---- epilogue ----
            __nv_bfloat16* Hhi_n = g_hhi[gru][par^1];
            __nv_bfloat16* Hlo_n = g_hlo[gru][par^1];
            const size_t offk = (size_t)32*(63*step - (step*(step-1))/2);
#pragma unroll
            for (int i = 0; i < 2; i++) {
                if (2*wm + i >= ng) continue;
#pragma unroll
                for (int half = 0; half < 2; half++) {
                    int grow = (cfirst + (2*wm + i)*18)*16 + g8 + half*8;
                    int gxrow = grow - step*32;
                    const float* gxr = gx + (size_t)gxrow*(3*H_);
                    size_t prow = offk + gxrow;
                    float row_part = 0.f;
#pragma unroll
                    for (int j = 0; j < 2; j++) {
                        int cc2 = cb*64 + wn*16 + j*8 + t2;
                        float2 gx_r = *(const float2*)&gxr[cc2];
                        float2 gx_z = *(const float2*)&gxr[H_ + cc2];
                        float2 gx_n = *(const float2*)&gxr[2*H_ + cc2];
                        float2 bh_r = *(const float2*)&bhh[cc2];
                        float2 bh_z = *(const float2*)&bhh[H_ + cc2];
                        float2 bh_n = *(const float2*)&bhh[2*H_ + cc2];
                        __nv_bfloat162 ho_hi = *(const __nv_bfloat162*)&Hhi[(size_t)grow*H_ + cc2];
                        __nv_bfloat162 ho_lo = *(const __nv_bfloat162*)&Hlo[(size_t)grow*H_ + cc2];
                        float hn2[2];
#pragma unroll
                        for (int u = 0; u < 2; u++) {
                            int ai = half*2 + u;
                            float rp = acc[0][i][j][ai] + (u ? bh_r.y : bh_r.x) + (u ? gx_r.y : gx_r.x);
                            float zp = acc[1][i][j][ai] + (u ? bh_z.y : bh_z.x) + (u ? gx_z.y : gx_z.x);
                            float np = acc[2][i][j][ai] + (u ? bh_n.y : bh_n.x);
                            float r = 1.f/(1.f + expf(-rp));
                            float z = 1.f/(1.f + expf(-zp));
                            float n = tanhf((u ? gx_n.y : gx_n.x) + r*np);
                            float hold = __bfloat162float(u ? ho_hi.y : ho_hi.x)
                                       + __bfloat162float(u ? ho_lo.y : ho_lo.x);
                            hn2[u] = (1.f - z)*n + z*hold;
                        }
                        __nv_bfloat162 hi2, lo2;
                        hi2.x = __float2bfloat16(hn2[0]); hi2.y = __float2bfloat16(hn2[1]);
                        lo2.x = __float2bfloat16(hn2[0] - __bfloat162float(hi2.x));
                        lo2.y = __float2bfloat16(hn2[1] - __bfloat162float(hi2.y));
                        *(__nv_bfloat162*)&Hhi_n[(size_t)grow*H_ + cc2] = hi2;
                        *(__nv_bfloat162*)&Hlo_n[(size_t)grow*H_ + cc2] = lo2;
                        if (gru == 0) {
                            float2 aw = *(const float2*)&alpha_w[cc2];
                            row_part += 0.5f*hn2[0]*aw.x + 0.5f*hn2[1]*aw.y;
                        } else {
                            float f0 = 0.5f*hn2[0], f1 = 0.5f*hn2[1];
                            __nv_bfloat162 fh, fl;
                            fh.x = __float2bfloat16(f0); fh.y = __float2bfloat16(f1);
                            fl.x = __float2bfloat16(f0 - __bfloat162float(fh.x));
                            fl.y = __float2bfloat16(f1 - __bfloat162float(fh.y));
                            *(__nv_bfloat162*)&g_fbhi[prow*H_ + cc2] = fh;
                            *(__nv_bfloat162*)&g_fblo[prow*H_ + cc2] = fl;
                        }
                    }
                    if (gru == 0) {
                        row_part += __shfl_xor_sync(0xffffffffu, row_part, 1);
                        row_part += __shfl_xor_sync(0xffffffffu, row_part, 2);
                        if ((lane & 3) == 0)
                            g_prep[prow*16 + cb*4 + wn] = row_part;
                    }
                }
            }
        }
        __syncthreads();
        if (tid == 0) {
            __threadfence();
            atomicAdd(mybar, 1u);
            const unsigned target = 4u*(unsigned)(step+1);
            unsigned v;
            do {
                asm volatile("ld.acquire.gpu.u32 %0, [%1];" : "=r"(v) : "l"(mybar));
            } while (v < target);
        }
        __syncthreads();
    }
}

// ------------------------- dense GEMM body (K=32 chunks, 1 sync/chunk) ------
__device__ __forceinline__ void dense_body(
        const __nv_bfloat16* __restrict__ Ahi, const __nv_bfloat16* __restrict__ Alo,
        const __nv_bfloat16* __restrict__ Bthi, const __nv_bfloat16* __restrict__ Btlo,
        const float* __restrict__ bias, int act, int ldc, float* __restrict__ outf,
        __nv_bfloat16* __restrict__ Phi, __nv_bfloat16* __restrict__ Plo,
        int rowbase, int colbase, uint32_t sbase) {
    const int tid = threadIdx.x, lane = tid & 31, wid = tid >> 5;
    const int wm = wid & 3, wn = wid >> 2;

    float acc[2][4][4] = {};

    const int a_r = lane & 15, a_c16 = ((lane >> 4) & 1) * 16;
    const int b_r = (lane & 7) + ((lane >> 4) & 1) * 8, b_c16 = (lane & 8) * 2;
    uint32_t aob[2][2], bob[2][2];
#pragma unroll
    for (int p = 0; p < 2; p++) {
#pragma unroll
        for (int i = 0; i < 2; i++)
            aob[p][i] = (uint32_t)(p*6144 + (wm*32 + i*16 + a_r)*48 + a_c16);
#pragma unroll
        for (int h2 = 0; h2 < 2; h2++)
            bob[p][h2] = (uint32_t)(p*6144 + (wn*32 + h2*16 + b_r)*48 + b_c16);
    }

    const int st_q = tid & 1, st_r = (tid >> 1) & 127, st_p = tid >> 8;
    const uint32_t stoff = (uint32_t)(st_p*6144 + st_r*48 + st_q*16);
    const __nv_bfloat16* srcA = (st_p ? Alo : Ahi) + (size_t)(rowbase + st_r)*256 + st_q*8;
    const __nv_bfloat16* srcB = (st_p ? Btlo : Bthi) + (size_t)(colbase + st_r)*256 + st_q*8;

#pragma unroll
    for (int sub = 0; sub < 2; sub++) {
        CP_ASYNC16(sbase + sub*12288u + stoff, srcA + sub*16);
        CP_ASYNC16(sbase + 24576u + sub*12288u + stoff, srcB + sub*16);
    }
    CP_COMMIT();

#pragma unroll 1
    for (int c = 0; c < 8; c++) {
        CP_WAIT0();
        __syncthreads();
        if (c < 7) {
            uint32_t bb = sbase + (uint32_t)(((c+1)&1)*DCH2);
            int ko = (c+1)*32;
#pragma unroll
            for (int sub = 0; sub < 2; sub++) {
                CP_ASYNC16(bb + sub*12288u + stoff, srcA + ko + sub*16);
                CP_ASYNC16(bb + 24576u + sub*12288u + stoff, srcB + ko + sub*16);
            }
            CP_COMMIT();
        }
        const uint32_t bufb = sbase + (uint32_t)((c&1)*DCH2);
#pragma unroll
        for (int sub = 0; sub < 2; sub++) {
            const uint32_t ab = bufb + sub*12288u;
            const uint32_t bbB = bufb + 24576u + sub*12288u;
            uint32_t Ah[2][4], Al[2][4], Bh[8], Bl[8];
            ldsm4(Ah[0], ab + aob[0][0]); ldsm4(Ah[1], ab + aob[0][1]);
            ldsm4(Al[0], ab + aob[1][0]); ldsm4(Al[1], ab + aob[1][1]);
            ldsm4(Bh,   bbB + bob[0][0]); ldsm4(Bh+4, bbB + bob[0][1]);
            ldsm4(Bl,   bbB + bob[1][0]); ldsm4(Bl+4, bbB + bob[1][1]);
#pragma unroll
            for (int i = 0; i < 2; i++)
#pragma unroll
            for (int j = 0; j < 4; j++) {
                mma16816(acc[i][j], Ah[i], &Bh[j*2]);
                mma16816(acc[i][j], Ah[i], &Bl[j*2]);
                mma16816(acc[i][j], Al[i], &Bh[j*2]);
            }
        }
    }

    const int g8 = lane >> 2, t2 = (lane & 3)*2;
#pragma unroll
    for (int i = 0; i < 2; i++)
#pragma unroll
    for (int half = 0; half < 2; half++) {
        int grow = rowbase + wm*32 + i*16 + g8 + half*8;
#pragma unroll
        for (int j = 0; j < 4; j++) {
            int cc = colbase + wn*32 + j*8 + t2;
            float v0 = acc[i][j][half*2 + 0];
            float v1 = acc[i][j][half*2 + 1];
            if (bias) { v0 += bias[cc]; v1 += bias[cc+1]; }
            if (act == 1) { v0 = tanhf(v0); v1 = tanhf(v1); }
            if (outf) {
                float2 f2; f2.x = v0; f2.y = v1;
                *(float2*)&outf[(size_t)grow*ldc + cc] = f2;
            }
            if (Phi) {
                __nv_bfloat162 hi2, lo2;
                hi2.x = __float2bfloat16(v0); hi2.y = __float2bfloat16(v1);
                lo2.x = __float2bfloat16(v0 - __bfloat162float(hi2.x));
                lo2.y = __float2bfloat16(v1 - __bfloat162float(hi2.y));
                *(__nv_bfloat162*)&Phi[(size_t)grow*ldc + cc] = hi2;
                *(__nv_bfloat162*)&Plo[(size_t)grow*ldc + cc] = lo2;
            }
        }
    }
}

__global__ void __launch_bounds__(512, 1)
dense_mma(const __nv_bfloat16* __restrict__ Ahi, const __nv_bfloat16* __restrict__ Alo,
          const __nv_bfloat16* __restrict__ Bthi, const __nv_bfloat16* __restrict__ Btlo,
          const float* __restrict__ bias, int act, int ldc, float* __restrict__ outf,
          __nv_bfloat16* __restrict__ Phi, __nv_bfloat16* __restrict__ Plo) {
    extern __shared__ __align__(16) unsigned char smem[];
    dense_body(Ahi, Alo, Bthi, Btlo, bias, act, ldc, outf, Phi, Plo,
               blockIdx.x*128, blockIdx.y*128, smem_u32(smem));
}

// merged gx: y<6 -> GRU a, else GRU b
__global__ void __launch_bounds__(512, 1)
gx_mma(const __nv_bfloat16* __restrict__ Ahi, const __nv_bfloat16* __restrict__ Alo,
       const __nv_bfloat16* __restrict__ wihhi, const __nv_bfloat16* __restrict__ wihlo,
       const float* __restrict__ biasA, const float* __restrict__ biasB,
       float* __restrict__ gxa, float* __restrict__ gxb) {
    extern __shared__ __align__(16) unsigned char smem[];
    int y = blockIdx.y;
    int gru = y >= 6;
    int yy = gru ? y - 6 : y;
    dense_body(Ahi, Alo,
               wihhi + (size_t)gru*3*H_*E_, wihlo + (size_t)gru*3*H_*E_,
               gru ? biasB : biasA, 0, 3*H_, gru ? gxb : gxa,
               (__nv_bfloat16*)0, (__nv_bfloat16*)0,
               blockIdx.x*128, yy*128, smem_u32(smem));
}

// ------------------------- reduce (alpha fused, beta from planes) -----------
__global__ void reduce_kernel(const float* __restrict__ x,
                              const float* __restrict__ out_w,
                              const float* __restrict__ out_b,
                              const float* __restrict__ alpha_b,
                              float* __restrict__ out) {
    int pb = blockIdx.x;
    int p = 62 - (pb >> 5);
    int b = pb & 31;
    int e = threadIdx.x;
    __shared__ float s_alpha[T_];
    if (e < 32) {
        int lane = e;
        float ab = alpha_b[0];
        float v0 = -1e30f, v1 = -1e30f;
        {
            int t = lane;
            if (t <= p) {
                int kk = p - t;
                int offk = 32*(63*kk - (kk*(kk-1))/2);
                size_t prow = (size_t)offk + t*32 + b;
                const float4* qq = (const float4*)&g_prep[prow*16];
                float4 s0 = qq[0], s1 = qq[1], s2 = qq[2], s3 = qq[3];
                v0 = (s0.x+s0.y+s0.z+s0.w) + (s1.x+s1.y+s1.z+s1.w)
                   + (s2.x+s2.y+s2.z+s2.w) + (s3.x+s3.y+s3.z+s3.w) + ab;
            }
        }
        {
            int t = lane + 32;
            if (t <= p) {
                int kk = p - t;
                int offk = 32*(63*kk - (kk*(kk-1))/2);
                size_t prow = (size_t)offk + t*32 + b;
                const float4* qq = (const float4*)&g_prep[prow*16];
                float4 s0 = qq[0], s1 = qq[1], s2 = qq[2], s3 = qq[3];
                v1 = (s0.x+s0.y+s0.z+s0.w) + (s1.x+s1.y+s1.z+s1.w)
                   + (s2.x+s2.y+s2.z+s2.w) + (s3.x+s3.y+s3.z+s3.w) + ab;
            }
        }
        float m = fmaxf(v0, v1);
#pragma unroll
        for (int o=16;o;o>>=1) m = fmaxf(m, __shfl_xor_sync(0xffffffffu, m, o));
        float e0 = (lane      <= p) ? expf(v0-m) : 0.f;
        float e1 = (lane + 32 <= p) ? expf(v1-m) : 0.f;
        float s = e0 + e1;
#pragma unroll
        for (int o=16;o;o>>=1) s += __shfl_xor_sync(0xffffffffu, s, o);
        float inv = 1.f/s;
        s_alpha[lane]      = e0*inv;
        s_alpha[lane + 32] = e1*inv;
    }
    __syncthreads();
    float cc = 0.f, gg = 0.f;
#pragma unroll 2
    for (int t = 0; t <= p; t++) {
        float a = s_alpha[t];
        int kk = p - t;
        int offk = 32*(63*kk - (kk*(kk-1))/2);
        size_t prow = (size_t)offk + t*32 + b;
        float beta = __bfloat162float(g_betahi[prow*E_ + e])
                   + __bfloat162float(g_betalo[prow*E_ + e]);
        cc += a * beta * g_emb[((size_t)(t*B_+b))*E_ + e];
        gg += a * g_ebeta[prow*E_ + e] * x[((size_t)b*T_ + t)*E_ + e];
    }
    out[B_*P_ + ((size_t)(b*P_+p))*E_ + e] = gg / (float)(p+1);
    __shared__ float red[256];
    red[e] = cc * out_w[e];
    __syncthreads();
    for (int s2=128; s2; s2>>=1) { if (e < s2) red[e] += red[e+s2]; __syncthreads(); }
    if (e == 0) out[b*P_ + p] = red[0] + out_b[0];
}

// ------------------------- launch -------------------------------------------
extern "C" void kernel_launch(void* const* d_in, const int* in_sizes, int n_in,
                              void* d_out, int out_size) {
    (void)in_sizes; (void)n_in; (void)out_size;
    const float* x       = (const float*)d_in[0];
    const float* emb_w   = (const float*)d_in[1];
    const float* emb_b   = (const float*)d_in[2];
    const float* a_wih   = (const float*)d_in[3];
    const float* a_whh   = (const float*)d_in[4];
    const float* a_bih   = (const float*)d_in[5];
    const float* a_bhh   = (const float*)d_in[6];
    const float* b_wih   = (const float*)d_in[7];
    const float* b_whh   = (const float*)d_in[8];
    const float* b_bih   = (const float*)d_in[9];
    const float* b_bhh   = (const float*)d_in[10];
    const float* alpha_w = (const float*)d_in[11];
    const float* alpha_b = (const float*)d_in[12];
    const float* beta_w  = (const float*)d_in[13];
    const float* beta_b  = (const float*)d_in[14];
    const float* out_w   = (const float*)d_in[15];
    const float* out_b   = (const float*)d_in[16];
    float* out = (float*)d_out;

    cudaFuncSetAttribute(gru_persistent, cudaFuncAttributeMaxDynamicSharedMemorySize, SMEM_TOTAL_PERS);
    cudaFuncSetAttribute(dense_mma,      cudaFuncAttributeMaxDynamicSharedMemorySize, SMEM_TOTAL_DENSE);
    cudaFuncSetAttribute(gx_mma,         cudaFuncAttributeMaxDynamicSharedMemorySize, SMEM_TOTAL_DENSE);

    float *p_emb=0, *p_gxa=0, *p_gxb=0, *p_ebeta=0;
    __nv_bfloat16 *p_embhi=0, *p_emblo=0, *p_fbhi=0, *p_fblo=0;
    __nv_bfloat16 *p_bwhi=0, *p_bwlo=0, *p_mthi=0, *p_mtlo=0, *p_bhi=0, *p_blo=0;
    __nv_bfloat16 *p_wihhi=0, *p_wihlo=0;
    cudaGetSymbolAddress((void**)&p_emb,   g_emb);
    cudaGetSymbolAddress((void**)&p_embhi, g_embhi);
    cudaGetSymbolAddress((void**)&p_emblo, g_emblo);
    cudaGetSymbolAddress((void**)&p_gxa,   g_gxa);
    cudaGetSymbolAddress((void**)&p_gxb,   g_gxb);
    cudaGetSymbolAddress((void**)&p_ebeta, g_ebeta);
    cudaGetSymbolAddress((void**)&p_fbhi,  g_fbhi);
    cudaGetSymbolAddress((void**)&p_fblo,  g_fblo);
    cudaGetSymbolAddress((void**)&p_bwhi,  g_bwhi);
    cudaGetSymbolAddress((void**)&p_bwlo,  g_bwlo);
    cudaGetSymbolAddress((void**)&p_mthi,  g_mthi);
    cudaGetSymbolAddress((void**)&p_mtlo,  g_mtlo);
    cudaGetSymbolAddress((void**)&p_bhi,   g_betahi);
    cudaGetSymbolAddress((void**)&p_blo,   g_betalo);
    cudaGetSymbolAddress((void**)&p_wihhi, g_wihhi);
    cudaGetSymbolAddress((void**)&p_wihlo, g_wihlo);

    prep_all<<<(int)((PREP_TOTAL + 255)/256), 256>>>(a_whh, b_whh, a_wih, b_wih,
                                                     beta_w, emb_w, out_w);

    sgemm128<<<dim3((T_*B_)/128, E_/128), 256>>>(x, emb_w, emb_b, p_emb, E_,
                                                 p_embhi, p_emblo);

    gx_mma<<<dim3((T_*B_)/128, 12), 512, SMEM_TOTAL_DENSE>>>(
        p_embhi, p_emblo, p_wihhi, p_wihlo, a_bih, b_bih, p_gxa, p_gxb);

    gru_persistent<<<NCTA_PERS, 512, SMEM_TOTAL_PERS>>>(a_bhh, b_bhh, alpha_w);

    dense_mma<<<dim3(NPACK_/128, 2), 512, SMEM_TOTAL_DENSE>>>(
        p_fbhi, p_fblo, p_bwhi, p_bwlo, beta_b, 1, E_, (float*)0, p_bhi, p_blo);
    dense_mma<<<dim3(NPACK_/128, 2), 512, SMEM_TOTAL_DENSE>>>(
        p_bhi, p_blo, p_mthi, p_mtlo, (const float*)0, 0, E_, p_ebeta,
        (__nv_bfloat16*)0, (__nv_bfloat16*)0);

    reduce_kernel<<<PB_, 256>>>(x, out_w, out_b, alpha_b, out);
}